// round 1
// baseline (speedup 1.0000x reference)
#include <cuda_runtime.h>
#include <math.h>

// Problem constants
#define B_  2
#define T_  2048
#define DM  2048
#define H_  32
#define DH  64
#define M_  (B_*T_)   // 4096

// Scratch (device globals: allocation-free per harness rules)
__device__ float g_q[(size_t)B_*H_*T_*DH];    // [B,H,T,Dh] rope'd Q
__device__ float g_o[(size_t)M_*DM];          // [B*T, Dm] attention output
__device__ float g_cos[T_*(DH/2)];
__device__ float g_sin[T_*(DH/2)];

// ---------------------------------------------------------------------------
// RoPE table: double-precision angles to avoid fp32 pow/large-angle drift.
// ---------------------------------------------------------------------------
__global__ void rope_table_kernel() {
    int idx = blockIdx.x * blockDim.x + threadIdx.x;
    if (idx >= T_ * (DH/2)) return;
    int t = idx >> 5;       // / 32
    int i = idx & 31;
    double inv = pow(10000.0, -((double)(2 * i)) / 64.0);
    double ang = (double)t * inv;
    g_cos[idx] = (float)cos(ang);
    g_sin[idx] = (float)sin(ang);
}

// ---------------------------------------------------------------------------
// Tiled fp32 GEMM: C[m,n] = sum_k A[m,k] * W[n,k]   (i.e. A @ W^T)
// M=4096, N=2048, K=2048. Block tile 128x128, K-tile 8, 256 threads, 8x8/thread.
// DO_ROPE=true : A = Ain (hidden), epilogue applies interleaved RoPE and
//                stores to g_q in [B,H,T,Dh] layout.
// DO_ROPE=false: A = g_o, plain store to C.
// ---------------------------------------------------------------------------
template<bool DO_ROPE>
__global__ __launch_bounds__(256)
void gemm128_kernel(const float* __restrict__ Ain,
                    const float* __restrict__ Bw,
                    float* __restrict__ C) {
    __shared__ float As[8][132];
    __shared__ float Bs[8][132];

    const float* A = DO_ROPE ? Ain : (const float*)g_o;

    const int tid = threadIdx.x;
    const int tx  = tid & 15;        // 0..15 -> col sub
    const int ty  = tid >> 4;        // 0..15 -> row sub
    const int rowBase = blockIdx.y * 128;
    const int colBase = blockIdx.x * 128;

    const int lr = tid >> 1;         // 0..127
    const int lc = (tid & 1) * 4;    // 0 or 4

    float acc[8][8];
    #pragma unroll
    for (int i = 0; i < 8; i++)
        #pragma unroll
        for (int j = 0; j < 8; j++) acc[i][j] = 0.f;

    const float* aptr = A  + (size_t)(rowBase + lr) * DM + lc;
    const float* bptr = Bw + (size_t)(colBase + lr) * DM + lc;

    for (int kt = 0; kt < DM; kt += 8) {
        float4 av = *(const float4*)(aptr + kt);
        float4 bv = *(const float4*)(bptr + kt);
        As[lc + 0][lr] = av.x; As[lc + 1][lr] = av.y;
        As[lc + 2][lr] = av.z; As[lc + 3][lr] = av.w;
        Bs[lc + 0][lr] = bv.x; Bs[lc + 1][lr] = bv.y;
        Bs[lc + 2][lr] = bv.z; Bs[lc + 3][lr] = bv.w;
        __syncthreads();

        #pragma unroll
        for (int k = 0; k < 8; k++) {
            float4 a0 = *(const float4*)&As[k][ty * 8];
            float4 a1 = *(const float4*)&As[k][ty * 8 + 4];
            float4 b0 = *(const float4*)&Bs[k][tx * 8];
            float4 b1 = *(const float4*)&Bs[k][tx * 8 + 4];
            float a[8] = {a0.x, a0.y, a0.z, a0.w, a1.x, a1.y, a1.z, a1.w};
            float b[8] = {b0.x, b0.y, b0.z, b0.w, b1.x, b1.y, b1.z, b1.w};
            #pragma unroll
            for (int i = 0; i < 8; i++)
                #pragma unroll
                for (int j = 0; j < 8; j++)
                    acc[i][j] = fmaf(a[i], b[j], acc[i][j]);
        }
        __syncthreads();
    }

    if (DO_ROPE) {
        #pragma unroll
        for (int i = 0; i < 8; i++) {
            int m = rowBase + ty * 8 + i;
            int b = m >> 11;            // / T_
            int t = m & (T_ - 1);
            #pragma unroll
            for (int j = 0; j < 8; j += 2) {
                int n  = colBase + tx * 8 + j;
                int h  = n >> 6;
                int d  = n & 63;        // even
                int pi = d >> 1;
                float c = g_cos[t * 32 + pi];
                float s = g_sin[t * 32 + pi];
                float x1 = acc[i][j], x2 = acc[i][j + 1];
                size_t base = (((size_t)(b * H_ + h)) * T_ + t) * DH + d;
                g_q[base]     = x1 * c - x2 * s;
                g_q[base + 1] = x1 * s + x2 * c;
            }
        }
    } else {
        #pragma unroll
        for (int i = 0; i < 8; i++) {
            size_t m = rowBase + ty * 8 + i;
            float* cp = C + m * DM + colBase + tx * 8;
            float4 v0 = make_float4(acc[i][0], acc[i][1], acc[i][2], acc[i][3]);
            float4 v1 = make_float4(acc[i][4], acc[i][5], acc[i][6], acc[i][7]);
            *(float4*)cp       = v0;
            *(float4*)(cp + 4) = v1;
        }
    }
}

// ---------------------------------------------------------------------------
// Causal flash attention, fp32. One block = (b, h, 64-row Q tile).
// 64 threads; thread t owns Q row (q & o accumulator in registers).
// K/V tiles staged in smem with coalesced loads. Online softmax with lazy
// rescale (rescale o only when a new row max appears: ~ln(T) times total).
// ---------------------------------------------------------------------------
__global__ __launch_bounds__(64)
void attn_kernel(const float* __restrict__ Kg, const float* __restrict__ Vg) {
    __shared__ float Ks[64][64];
    __shared__ float Vs[64][64];

    const int tid = threadIdx.x;
    const int bx  = blockIdx.x;  // q tile (0..31)
    const int h   = blockIdx.y;
    const int b   = blockIdx.z;
    const int qg  = bx * 64 + tid;

    // Load my Q row into registers
    float q[64];
    const float* qp = g_q + (((size_t)(b * H_ + h)) * T_ + qg) * DH;
    #pragma unroll
    for (int d4 = 0; d4 < 16; d4++) {
        float4 v = *(const float4*)(qp + d4 * 4);
        q[d4*4+0] = v.x; q[d4*4+1] = v.y; q[d4*4+2] = v.z; q[d4*4+3] = v.w;
    }

    const float scale = 0.125f;   // 1/sqrt(64)
    float mrow = -1e30f, l = 0.f;
    float o[64];
    #pragma unroll
    for (int d = 0; d < 64; d++) o[d] = 0.f;

    // K/V layout [B,T,H,Dh]: row stride (in floats) between tokens = H*Dh = DM
    const float* kbase = Kg + (size_t)b * T_ * DM + h * DH;
    const float* vbase = Vg + (size_t)b * T_ * DM + h * DH;

    for (int kt = 0; kt <= bx; kt++) {
        __syncthreads();   // protect smem from previous iteration's readers
        #pragma unroll 4
        for (int j = 0; j < 64; j++) {
            Ks[j][tid] = kbase[(size_t)(kt * 64 + j) * DM + tid];
            Vs[j][tid] = vbase[(size_t)(kt * 64 + j) * DM + tid];
        }
        __syncthreads();

        const int jmax = (kt == bx) ? tid : 63;   // causal: kg <= qg
        for (int j = 0; j <= jmax; j++) {
            // score = q . K[j]
            const float4* kr = (const float4*)&Ks[j][0];
            float a0 = 0.f, a1 = 0.f, a2 = 0.f, a3 = 0.f;
            #pragma unroll
            for (int d4 = 0; d4 < 16; d4++) {
                float4 kv = kr[d4];
                a0 = fmaf(q[d4*4+0], kv.x, a0);
                a1 = fmaf(q[d4*4+1], kv.y, a1);
                a2 = fmaf(q[d4*4+2], kv.z, a2);
                a3 = fmaf(q[d4*4+3], kv.w, a3);
            }
            float s = ((a0 + a1) + (a2 + a3)) * scale;

            if (s > mrow) {                     // rare: lazy rescale
                float corr = __expf(mrow - s);
                l *= corr;
                #pragma unroll
                for (int d = 0; d < 64; d++) o[d] *= corr;
                mrow = s;
            }
            float p = __expf(s - mrow);
            l += p;

            const float4* vr = (const float4*)&Vs[j][0];
            #pragma unroll
            for (int d4 = 0; d4 < 16; d4++) {
                float4 vv = vr[d4];
                o[d4*4+0] = fmaf(p, vv.x, o[d4*4+0]);
                o[d4*4+1] = fmaf(p, vv.y, o[d4*4+1]);
                o[d4*4+2] = fmaf(p, vv.z, o[d4*4+2]);
                o[d4*4+3] = fmaf(p, vv.w, o[d4*4+3]);
            }
        }
    }

    const float inv_l = 1.0f / l;
    float* op = g_o + ((size_t)(b * T_ + qg)) * DM + h * DH;
    #pragma unroll
    for (int d4 = 0; d4 < 16; d4++) {
        float4 v = make_float4(o[d4*4+0] * inv_l, o[d4*4+1] * inv_l,
                               o[d4*4+2] * inv_l, o[d4*4+3] * inv_l);
        *(float4*)(op + d4 * 4) = v;
    }
}

// ---------------------------------------------------------------------------
// Launch
// inputs (metadata order): hidden_states, shared_k, shared_v, Wq, Wo
// output: float32 [B,T,Dm]
// ---------------------------------------------------------------------------
extern "C" void kernel_launch(void* const* d_in, const int* in_sizes, int n_in,
                              void* d_out, int out_size) {
    const float* hidden = (const float*)d_in[0];
    const float* Kin    = (const float*)d_in[1];
    const float* Vin    = (const float*)d_in[2];
    const float* Wq     = (const float*)d_in[3];
    const float* Wo     = (const float*)d_in[4];
    float* out          = (float*)d_out;

    // 1) RoPE tables (65536 entries)
    rope_table_kernel<<<(T_ * (DH/2) + 255) / 256, 256>>>();

    // 2) Q projection + fused RoPE  (writes g_q in [B,H,T,Dh])
    dim3 gGemm(DM / 128, M_ / 128);   // (16, 32)
    gemm128_kernel<true><<<gGemm, 256>>>(hidden, Wq, nullptr);

    // 3) Causal attention (writes g_o in [B*T, Dm])
    dim3 gAttn(T_ / 64, H_, B_);      // (32, 32, 2)
    attn_kernel<<<gAttn, 64>>>(Kin, Vin);

    // 4) Output projection
    gemm128_kernel<false><<<gGemm, 256>>>(nullptr, Wo, out);
}

// round 3
// speedup vs baseline: 1.2121x; 1.2121x over previous
#include <cuda_runtime.h>
#include <math.h>
#include <stdint.h>

// Problem constants
#define B_  2
#define T_  2048
#define DM  2048
#define H_  32
#define DH  64
#define M_  (B_*T_)   // 4096

// Scratch (device globals: allocation-free per harness rules)
__device__ float g_q[(size_t)B_*H_*T_*DH];    // [B,H,T,Dh] rope'd Q
__device__ float g_o[(size_t)M_*DM];          // [B*T, Dm] attention output
__device__ float g_cos[T_*(DH/2)];
__device__ float g_sin[T_*(DH/2)];

__device__ __forceinline__ uint32_t f2tf(float x) {   // round-to-nearest tf32 bits
    uint32_t r;
    asm("cvt.rna.tf32.f32 %0, %1;" : "=r"(r) : "f"(x));
    return r;
}

// d += a * b  (tf32 m16n8k8, fp32 accumulate)
__device__ __forceinline__ void mma1688(float* d, const uint32_t* a, const uint32_t* b) {
    asm volatile(
        "mma.sync.aligned.m16n8k8.row.col.f32.tf32.tf32.f32 "
        "{%0,%1,%2,%3}, {%4,%5,%6,%7}, {%8,%9}, {%0,%1,%2,%3};"
        : "+f"(d[0]), "+f"(d[1]), "+f"(d[2]), "+f"(d[3])
        : "r"(a[0]), "r"(a[1]), "r"(a[2]), "r"(a[3]), "r"(b[0]), "r"(b[1]));
}

// ---------------------------------------------------------------------------
// RoPE table: double-precision angles to avoid fp32 pow/large-angle drift.
// ---------------------------------------------------------------------------
__global__ void rope_table_kernel() {
    int idx = blockIdx.x * blockDim.x + threadIdx.x;
    if (idx >= T_ * (DH/2)) return;
    int t = idx >> 5;
    int i = idx & 31;
    double inv = pow(10000.0, -((double)(2 * i)) / 64.0);
    double ang = (double)t * inv;
    g_cos[idx] = (float)cos(ang);
    g_sin[idx] = (float)sin(ang);
}

// ---------------------------------------------------------------------------
// Split-TF32 mma.sync GEMM: C[m,n] = sum_k A[m,k] * W[n,k]  (A @ W^T)
// CTA 128x128, BK=32, 256 threads (8 warps as 2x4, each 64x32).
// Smem holds pre-split hi/lo tiles, stride 36 floats (conflict-free frags).
// ---------------------------------------------------------------------------
#define STRD 36
#define TILE_F (128*STRD)                 // floats per tile
#define SMEM_G_BYTES (4*TILE_F*4)         // Ah, Al, Bh, Bl = 73728 B

template<bool DO_ROPE>
__global__ __launch_bounds__(256)
void gemm_mma_kernel(const float* __restrict__ Ain,
                     const float* __restrict__ Bw,
                     float* __restrict__ C) {
    extern __shared__ float sm[];
    float* Ah = sm;
    float* Al = sm + TILE_F;
    float* Bh = sm + 2*TILE_F;
    float* Bl = sm + 3*TILE_F;

    const float* A = DO_ROPE ? Ain : (const float*)g_o;

    const int tid   = threadIdx.x;
    const int wid   = tid >> 5;
    const int lane  = tid & 31;
    const int gid   = lane >> 2;     // 0..7
    const int tig   = lane & 3;      // 0..3
    const int warpR = wid >> 2;      // 0..1  -> 64-row band
    const int warpC = wid & 3;       // 0..3  -> 32-col band
    const int rowBase = blockIdx.y * 128;
    const int colBase = blockIdx.x * 128;

    float acc[4][4][4];
    #pragma unroll
    for (int mt = 0; mt < 4; mt++)
        #pragma unroll
        for (int nt = 0; nt < 4; nt++)
            #pragma unroll
            for (int i = 0; i < 4; i++) acc[mt][nt][i] = 0.f;

    // gmem load map: chunk = i*256 + tid; r = chunk>>3 (row), c4 = chunk&7 (k/4)
    const int lr = tid >> 3;         // base row advanced by 32 per i
    const int lc4 = tid & 7;

    for (int kt = 0; kt < 64; kt++) {
        // ---- global loads (issued before sync: overlap prior compute) ----
        float4 ra[4], rb[4];
        #pragma unroll
        for (int i = 0; i < 4; i++) {
            int r = lr + i * 32;
            const float* ap = A  + (size_t)(rowBase + r) * DM + kt * 32 + lc4 * 4;
            const float* bp = Bw + (size_t)(colBase + r) * DM + kt * 32 + lc4 * 4;
            ra[i] = *(const float4*)ap;
            rb[i] = *(const float4*)bp;
        }

        __syncthreads();   // previous iteration's frag reads done

        #pragma unroll
        for (int i = 0; i < 4; i++) {
            int r = lr + i * 32;
            int o = r * STRD + lc4 * 4;
            float f;
            uint4 h, l;
            h.x = f2tf(ra[i].x); f = ra[i].x - __uint_as_float(h.x); l.x = f2tf(f);
            h.y = f2tf(ra[i].y); f = ra[i].y - __uint_as_float(h.y); l.y = f2tf(f);
            h.z = f2tf(ra[i].z); f = ra[i].z - __uint_as_float(h.z); l.z = f2tf(f);
            h.w = f2tf(ra[i].w); f = ra[i].w - __uint_as_float(h.w); l.w = f2tf(f);
            *(uint4*)(Ah + o) = h;
            *(uint4*)(Al + o) = l;
            h.x = f2tf(rb[i].x); f = rb[i].x - __uint_as_float(h.x); l.x = f2tf(f);
            h.y = f2tf(rb[i].y); f = rb[i].y - __uint_as_float(h.y); l.y = f2tf(f);
            h.z = f2tf(rb[i].z); f = rb[i].z - __uint_as_float(h.z); l.z = f2tf(f);
            h.w = f2tf(rb[i].w); f = rb[i].w - __uint_as_float(h.w); l.w = f2tf(f);
            *(uint4*)(Bh + o) = h;
            *(uint4*)(Bl + o) = l;
        }
        __syncthreads();

        // ---- MMA over 4 k-steps ----
        #pragma unroll
        for (int kk = 0; kk < 4; kk++) {
            uint32_t ah[4][4], al4[4][4], bh[4][2], bl4[4][2];
            #pragma unroll
            for (int mt = 0; mt < 4; mt++) {
                int row = warpR * 64 + mt * 16 + gid;
                int o0 = row * STRD + kk * 8 + tig;
                int o1 = (row + 8) * STRD + kk * 8 + tig;
                ah[mt][0] = __float_as_uint(Ah[o0]);
                ah[mt][1] = __float_as_uint(Ah[o1]);
                ah[mt][2] = __float_as_uint(Ah[o0 + 4]);
                ah[mt][3] = __float_as_uint(Ah[o1 + 4]);
                al4[mt][0] = __float_as_uint(Al[o0]);
                al4[mt][1] = __float_as_uint(Al[o1]);
                al4[mt][2] = __float_as_uint(Al[o0 + 4]);
                al4[mt][3] = __float_as_uint(Al[o1 + 4]);
            }
            #pragma unroll
            for (int nt = 0; nt < 4; nt++) {
                int n = warpC * 32 + nt * 8 + gid;
                int o = n * STRD + kk * 8 + tig;
                bh[nt][0] = __float_as_uint(Bh[o]);
                bh[nt][1] = __float_as_uint(Bh[o + 4]);
                bl4[nt][0] = __float_as_uint(Bl[o]);
                bl4[nt][1] = __float_as_uint(Bl[o + 4]);
            }
            #pragma unroll
            for (int mt = 0; mt < 4; mt++)
                #pragma unroll
                for (int nt = 0; nt < 4; nt++) {
                    mma1688(acc[mt][nt], ah[mt], bh[nt]);
                    mma1688(acc[mt][nt], ah[mt], bl4[nt]);
                    mma1688(acc[mt][nt], al4[mt], bh[nt]);
                }
        }
    }

    // ---- epilogue ----
    #pragma unroll
    for (int mt = 0; mt < 4; mt++) {
        #pragma unroll
        for (int nt = 0; nt < 4; nt++) {
            int m0 = rowBase + warpR * 64 + mt * 16 + gid;
            int n  = colBase + warpC * 32 + nt * 8 + 2 * tig;   // even col
            if (DO_ROPE) {
                #pragma unroll
                for (int half = 0; half < 2; half++) {
                    int m = m0 + half * 8;
                    float x1 = acc[mt][nt][half * 2];
                    float x2 = acc[mt][nt][half * 2 + 1];
                    int bb = m >> 11;
                    int t  = m & (T_ - 1);
                    int hh = n >> 6;
                    int d  = n & 63;
                    float c = g_cos[t * 32 + (d >> 1)];
                    float s = g_sin[t * 32 + (d >> 1)];
                    size_t base = (((size_t)(bb * H_ + hh)) * T_ + t) * DH + d;
                    float2 v = make_float2(x1 * c - x2 * s, x1 * s + x2 * c);
                    *(float2*)(g_q + base) = v;
                }
            } else {
                float2 v0 = make_float2(acc[mt][nt][0], acc[mt][nt][1]);
                float2 v1 = make_float2(acc[mt][nt][2], acc[mt][nt][3]);
                *(float2*)(C + (size_t)m0 * DM + n)       = v0;
                *(float2*)(C + (size_t)(m0 + 8) * DM + n) = v1;
            }
        }
    }
}

// ---------------------------------------------------------------------------
// Causal flash attention, fp32 (unchanged; next round's target).
// ---------------------------------------------------------------------------
__global__ __launch_bounds__(64)
void attn_kernel(const float* __restrict__ Kg, const float* __restrict__ Vg) {
    __shared__ float Ks[64][64];
    __shared__ float Vs[64][64];

    const int tid = threadIdx.x;
    const int bx  = blockIdx.x;
    const int h   = blockIdx.y;
    const int b   = blockIdx.z;
    const int qg  = bx * 64 + tid;

    float q[64];
    const float* qp = g_q + (((size_t)(b * H_ + h)) * T_ + qg) * DH;
    #pragma unroll
    for (int d4 = 0; d4 < 16; d4++) {
        float4 v = *(const float4*)(qp + d4 * 4);
        q[d4*4+0] = v.x; q[d4*4+1] = v.y; q[d4*4+2] = v.z; q[d4*4+3] = v.w;
    }

    const float scale = 0.125f;
    float mrow = -1e30f, l = 0.f;
    float o[64];
    #pragma unroll
    for (int d = 0; d < 64; d++) o[d] = 0.f;

    const float* kbase = Kg + (size_t)b * T_ * DM + h * DH;
    const float* vbase = Vg + (size_t)b * T_ * DM + h * DH;

    for (int kt = 0; kt <= bx; kt++) {
        __syncthreads();
        #pragma unroll 4
        for (int j = 0; j < 64; j++) {
            Ks[j][tid] = kbase[(size_t)(kt * 64 + j) * DM + tid];
            Vs[j][tid] = vbase[(size_t)(kt * 64 + j) * DM + tid];
        }
        __syncthreads();

        const int jmax = (kt == bx) ? tid : 63;
        for (int j = 0; j <= jmax; j++) {
            const float4* kr = (const float4*)&Ks[j][0];
            float a0 = 0.f, a1 = 0.f, a2 = 0.f, a3 = 0.f;
            #pragma unroll
            for (int d4 = 0; d4 < 16; d4++) {
                float4 kv = kr[d4];
                a0 = fmaf(q[d4*4+0], kv.x, a0);
                a1 = fmaf(q[d4*4+1], kv.y, a1);
                a2 = fmaf(q[d4*4+2], kv.z, a2);
                a3 = fmaf(q[d4*4+3], kv.w, a3);
            }
            float s = ((a0 + a1) + (a2 + a3)) * scale;

            if (s > mrow) {
                float corr = __expf(mrow - s);
                l *= corr;
                #pragma unroll
                for (int d = 0; d < 64; d++) o[d] *= corr;
                mrow = s;
            }
            float p = __expf(s - mrow);
            l += p;

            const float4* vr = (const float4*)&Vs[j][0];
            #pragma unroll
            for (int d4 = 0; d4 < 16; d4++) {
                float4 vv = vr[d4];
                o[d4*4+0] = fmaf(p, vv.x, o[d4*4+0]);
                o[d4*4+1] = fmaf(p, vv.y, o[d4*4+1]);
                o[d4*4+2] = fmaf(p, vv.z, o[d4*4+2]);
                o[d4*4+3] = fmaf(p, vv.w, o[d4*4+3]);
            }
        }
    }

    const float inv_l = 1.0f / l;
    float* op = g_o + ((size_t)(b * T_ + qg)) * DM + h * DH;
    #pragma unroll
    for (int d4 = 0; d4 < 16; d4++) {
        float4 v = make_float4(o[d4*4+0] * inv_l, o[d4*4+1] * inv_l,
                               o[d4*4+2] * inv_l, o[d4*4+3] * inv_l);
        *(float4*)(op + d4 * 4) = v;
    }
}

// ---------------------------------------------------------------------------
// Launch: hidden_states, shared_k, shared_v, Wq, Wo -> out (float32 [B,T,Dm])
// ---------------------------------------------------------------------------
extern "C" void kernel_launch(void* const* d_in, const int* in_sizes, int n_in,
                              void* d_out, int out_size) {
    const float* hidden = (const float*)d_in[0];
    const float* Kin    = (const float*)d_in[1];
    const float* Vin    = (const float*)d_in[2];
    const float* Wq     = (const float*)d_in[3];
    const float* Wo     = (const float*)d_in[4];
    float* out          = (float*)d_out;

    cudaFuncSetAttribute(gemm_mma_kernel<true>,
                         cudaFuncAttributeMaxDynamicSharedMemorySize, SMEM_G_BYTES);
    cudaFuncSetAttribute(gemm_mma_kernel<false>,
                         cudaFuncAttributeMaxDynamicSharedMemorySize, SMEM_G_BYTES);

    rope_table_kernel<<<(T_ * (DH/2) + 255) / 256, 256>>>();

    dim3 gGemm(DM / 128, M_ / 128);   // (16, 32)
    gemm_mma_kernel<true><<<gGemm, 256, SMEM_G_BYTES>>>(hidden, Wq, nullptr);

    dim3 gAttn(T_ / 64, H_, B_);      // (32, 32, 2)
    attn_kernel<<<gAttn, 64>>>(Kin, Vin);

    gemm_mma_kernel<false><<<gGemm, 256, SMEM_G_BYTES>>>(nullptr, Wo, out);
}

// round 5
// speedup vs baseline: 1.8354x; 1.5143x over previous
#include <cuda_runtime.h>
#include <math.h>
#include <stdint.h>

// Problem constants
#define B_  2
#define T_  2048
#define DM  2048
#define H_  32
#define DH  64
#define M_  (B_*T_)   // 4096

// Scratch (device globals: allocation-free per harness rules)
__device__ float g_q[(size_t)B_*H_*T_*DH];    // [B,H,T,Dh] rope'd Q
__device__ float g_o[(size_t)M_*DM];          // [B*T, Dm] attention output
__device__ float g_cos[T_*(DH/2)];
__device__ float g_sin[T_*(DH/2)];

__device__ __forceinline__ uint32_t f2tf(float x) {   // round-to-nearest tf32 bits
    uint32_t r;
    asm("cvt.rna.tf32.f32 %0, %1;" : "=r"(r) : "f"(x));
    return r;
}

// d += a * b  (tf32 m16n8k8, fp32 accumulate)
__device__ __forceinline__ void mma1688(float* d, const uint32_t* a, const uint32_t* b) {
    asm volatile(
        "mma.sync.aligned.m16n8k8.row.col.f32.tf32.tf32.f32 "
        "{%0,%1,%2,%3}, {%4,%5,%6,%7}, {%8,%9}, {%0,%1,%2,%3};"
        : "+f"(d[0]), "+f"(d[1]), "+f"(d[2]), "+f"(d[3])
        : "r"(a[0]), "r"(a[1]), "r"(a[2]), "r"(a[3]), "r"(b[0]), "r"(b[1]));
}

// ---------------------------------------------------------------------------
// RoPE table
// ---------------------------------------------------------------------------
__global__ void rope_table_kernel() {
    int idx = blockIdx.x * blockDim.x + threadIdx.x;
    if (idx >= T_ * (DH/2)) return;
    int t = idx >> 5;
    int i = idx & 31;
    double inv = pow(10000.0, -((double)(2 * i)) / 64.0);
    double ang = (double)t * inv;
    g_cos[idx] = (float)cos(ang);
    g_sin[idx] = (float)sin(ang);
}

// ---------------------------------------------------------------------------
// Split-TF32 mma.sync GEMM (unchanged): C = A @ W^T
// ---------------------------------------------------------------------------
#define STRD 36
#define TILE_F (128*STRD)
#define SMEM_G_BYTES (4*TILE_F*4)

template<bool DO_ROPE>
__global__ __launch_bounds__(256)
void gemm_mma_kernel(const float* __restrict__ Ain,
                     const float* __restrict__ Bw,
                     float* __restrict__ C) {
    extern __shared__ float sm[];
    float* Ah = sm;
    float* Al = sm + TILE_F;
    float* Bh = sm + 2*TILE_F;
    float* Bl = sm + 3*TILE_F;

    const float* A = DO_ROPE ? Ain : (const float*)g_o;

    const int tid   = threadIdx.x;
    const int wid   = tid >> 5;
    const int lane  = tid & 31;
    const int gid   = lane >> 2;
    const int tig   = lane & 3;
    const int warpR = wid >> 2;
    const int warpC = wid & 3;
    const int rowBase = blockIdx.y * 128;
    const int colBase = blockIdx.x * 128;

    float acc[4][4][4];
    #pragma unroll
    for (int mt = 0; mt < 4; mt++)
        #pragma unroll
        for (int nt = 0; nt < 4; nt++)
            #pragma unroll
            for (int i = 0; i < 4; i++) acc[mt][nt][i] = 0.f;

    const int lr = tid >> 3;
    const int lc4 = tid & 7;

    for (int kt = 0; kt < 64; kt++) {
        float4 ra[4], rb[4];
        #pragma unroll
        for (int i = 0; i < 4; i++) {
            int r = lr + i * 32;
            ra[i] = *(const float4*)(A  + (size_t)(rowBase + r) * DM + kt * 32 + lc4 * 4);
            rb[i] = *(const float4*)(Bw + (size_t)(colBase + r) * DM + kt * 32 + lc4 * 4);
        }

        __syncthreads();

        #pragma unroll
        for (int i = 0; i < 4; i++) {
            int r = lr + i * 32;
            int o = r * STRD + lc4 * 4;
            float f;
            uint4 h, l;
            h.x = f2tf(ra[i].x); f = ra[i].x - __uint_as_float(h.x); l.x = f2tf(f);
            h.y = f2tf(ra[i].y); f = ra[i].y - __uint_as_float(h.y); l.y = f2tf(f);
            h.z = f2tf(ra[i].z); f = ra[i].z - __uint_as_float(h.z); l.z = f2tf(f);
            h.w = f2tf(ra[i].w); f = ra[i].w - __uint_as_float(h.w); l.w = f2tf(f);
            *(uint4*)(Ah + o) = h;
            *(uint4*)(Al + o) = l;
            h.x = f2tf(rb[i].x); f = rb[i].x - __uint_as_float(h.x); l.x = f2tf(f);
            h.y = f2tf(rb[i].y); f = rb[i].y - __uint_as_float(h.y); l.y = f2tf(f);
            h.z = f2tf(rb[i].z); f = rb[i].z - __uint_as_float(h.z); l.z = f2tf(f);
            h.w = f2tf(rb[i].w); f = rb[i].w - __uint_as_float(h.w); l.w = f2tf(f);
            *(uint4*)(Bh + o) = h;
            *(uint4*)(Bl + o) = l;
        }
        __syncthreads();

        #pragma unroll
        for (int kk = 0; kk < 4; kk++) {
            uint32_t ah[4][4], al4[4][4], bh[4][2], bl4[4][2];
            #pragma unroll
            for (int mt = 0; mt < 4; mt++) {
                int row = warpR * 64 + mt * 16 + gid;
                int o0 = row * STRD + kk * 8 + tig;
                int o1 = (row + 8) * STRD + kk * 8 + tig;
                ah[mt][0] = __float_as_uint(Ah[o0]);
                ah[mt][1] = __float_as_uint(Ah[o1]);
                ah[mt][2] = __float_as_uint(Ah[o0 + 4]);
                ah[mt][3] = __float_as_uint(Ah[o1 + 4]);
                al4[mt][0] = __float_as_uint(Al[o0]);
                al4[mt][1] = __float_as_uint(Al[o1]);
                al4[mt][2] = __float_as_uint(Al[o0 + 4]);
                al4[mt][3] = __float_as_uint(Al[o1 + 4]);
            }
            #pragma unroll
            for (int nt = 0; nt < 4; nt++) {
                int n = warpC * 32 + nt * 8 + gid;
                int o = n * STRD + kk * 8 + tig;
                bh[nt][0] = __float_as_uint(Bh[o]);
                bh[nt][1] = __float_as_uint(Bh[o + 4]);
                bl4[nt][0] = __float_as_uint(Bl[o]);
                bl4[nt][1] = __float_as_uint(Bl[o + 4]);
            }
            #pragma unroll
            for (int mt = 0; mt < 4; mt++)
                #pragma unroll
                for (int nt = 0; nt < 4; nt++) {
                    mma1688(acc[mt][nt], ah[mt], bh[nt]);
                    mma1688(acc[mt][nt], ah[mt], bl4[nt]);
                    mma1688(acc[mt][nt], al4[mt], bh[nt]);
                }
        }
    }

    #pragma unroll
    for (int mt = 0; mt < 4; mt++) {
        #pragma unroll
        for (int nt = 0; nt < 4; nt++) {
            int m0 = rowBase + warpR * 64 + mt * 16 + gid;
            int n  = colBase + warpC * 32 + nt * 8 + 2 * tig;
            if (DO_ROPE) {
                #pragma unroll
                for (int half = 0; half < 2; half++) {
                    int m = m0 + half * 8;
                    float x1 = acc[mt][nt][half * 2];
                    float x2 = acc[mt][nt][half * 2 + 1];
                    int bb = m >> 11;
                    int t  = m & (T_ - 1);
                    int hh = n >> 6;
                    int d  = n & 63;
                    float c = g_cos[t * 32 + (d >> 1)];
                    float s = g_sin[t * 32 + (d >> 1)];
                    size_t base = (((size_t)(bb * H_ + hh)) * T_ + t) * DH + d;
                    float2 v = make_float2(x1 * c - x2 * s, x1 * s + x2 * c);
                    *(float2*)(g_q + base) = v;
                }
            } else {
                float2 v0 = make_float2(acc[mt][nt][0], acc[mt][nt][1]);
                float2 v1 = make_float2(acc[mt][nt][2], acc[mt][nt][3]);
                *(float2*)(C + (size_t)m0 * DM + n)       = v0;
                *(float2*)(C + (size_t)(m0 + 8) * DM + n) = v1;
            }
        }
    }
}

// ---------------------------------------------------------------------------
// Tensor-core causal flash attention (split-TF32 mma.sync).
// Block = (b, h, 128-row Q tile). 256 threads, 8 warps x 16 rows.
// ---------------------------------------------------------------------------
#define AT_STRD 68
#define KV_TILE_F (64*AT_STRD)                 // 4352 floats
#define STG_F     (64*65)                      // 4160 floats
#define SMEM_A_BYTES ((4*KV_TILE_F + STG_F)*4) // 86272 B

__global__ __launch_bounds__(256)
void attn_mma_kernel(const float* __restrict__ Kg, const float* __restrict__ Vg) {
    extern __shared__ float sm[];
    float* Kh  = sm;
    float* Kl  = sm +     KV_TILE_F;
    float* Vh  = sm + 2 * KV_TILE_F;
    float* Vl  = sm + 3 * KV_TILE_F;
    float* stg = sm + 4 * KV_TILE_F;

    const int tid  = threadIdx.x;
    const int wid  = tid >> 5;
    const int lane = tid & 31;
    const int g    = lane >> 2;
    const int t    = lane & 3;
    const int bx   = (int)gridDim.x - 1 - (int)blockIdx.x;   // heavy blocks first
    const int h    = blockIdx.y;
    const int b    = blockIdx.z;
    const int q0   = bx * 128;
    const int wbase = wid * 16;

    // ---- stage Q tile (fp32): 128 rows x 16 float4 = 2048 chunks ----
    const float* qbase = g_q + (((size_t)(b * H_ + h)) * T_ + q0) * DH;
    #pragma unroll
    for (int i = 0; i < 8; i++) {
        int chunk = i * 256 + tid;
        int r = chunk >> 4, c4 = chunk & 15;
        float4 v = *(const float4*)(qbase + (size_t)r * DH + c4 * 4);
        float* dst = sm + r * AT_STRD + c4 * 4;
        dst[0] = v.x; dst[1] = v.y; dst[2] = v.z; dst[3] = v.w;
    }
    __syncthreads();

    uint32_t qh[8][4], ql[8][4];
    #pragma unroll
    for (int kk = 0; kk < 8; kk++) {
        int o0 = (wbase + g) * AT_STRD + kk * 8 + t;
        int o1 = o0 + 8 * AT_STRD;
        float v0 = 0.125f * sm[o0];
        float v1 = 0.125f * sm[o1];
        float v2 = 0.125f * sm[o0 + 4];
        float v3 = 0.125f * sm[o1 + 4];
        qh[kk][0] = f2tf(v0); ql[kk][0] = f2tf(v0 - __uint_as_float(qh[kk][0]));
        qh[kk][1] = f2tf(v1); ql[kk][1] = f2tf(v1 - __uint_as_float(qh[kk][1]));
        qh[kk][2] = f2tf(v2); ql[kk][2] = f2tf(v2 - __uint_as_float(qh[kk][2]));
        qh[kk][3] = f2tf(v3); ql[kk][3] = f2tf(v3 - __uint_as_float(qh[kk][3]));
    }

    float m0 = -1e30f, m1 = -1e30f, l0 = 0.f, l1 = 0.f;
    float oacc[8][4];
    #pragma unroll
    for (int nt = 0; nt < 8; nt++)
        #pragma unroll
        for (int i = 0; i < 4; i++) oacc[nt][i] = 0.f;

    const int nkt = 2 * bx + 2;
    const float* kbase = Kg + (size_t)b * T_ * DM + h * DH;
    const float* vbase = Vg + (size_t)b * T_ * DM + h * DH;

    const int ldr  = tid >> 4;      // 0..15
    const int ldc4 = tid & 15;      // dh float4 index

    float4 rk[4], rv[4];
    #pragma unroll
    for (int i = 0; i < 4; i++) {
        int r = ldr + i * 16;
        rk[i] = *(const float4*)(kbase + (size_t)r * DM + ldc4 * 4);
        rv[i] = *(const float4*)(vbase + (size_t)r * DM + ldc4 * 4);
    }

    const int qw_min = q0 + wbase;
    const int qw_max = q0 + wbase + 15;

    for (int kt = 0; kt < nkt; kt++) {
        const int ktb = kt * 64;

        __syncthreads();

        #pragma unroll
        for (int i = 0; i < 4; i++) {
            int r = ldr + i * 16;
            int o = r * AT_STRD + ldc4 * 4;
            float f;
            uint4 hh, ll;
            hh.x = f2tf(rk[i].x); f = rk[i].x - __uint_as_float(hh.x); ll.x = f2tf(f);
            hh.y = f2tf(rk[i].y); f = rk[i].y - __uint_as_float(hh.y); ll.y = f2tf(f);
            hh.z = f2tf(rk[i].z); f = rk[i].z - __uint_as_float(hh.z); ll.z = f2tf(f);
            hh.w = f2tf(rk[i].w); f = rk[i].w - __uint_as_float(hh.w); ll.w = f2tf(f);
            *(uint4*)(Kh + o) = hh;
            *(uint4*)(Kl + o) = ll;
            float* sp = stg + r * 65 + ldc4 * 4;
            sp[0] = rv[i].x; sp[1] = rv[i].y; sp[2] = rv[i].z; sp[3] = rv[i].w;
        }
        __syncthreads();

        // V convert: transpose stage -> Vh/Vl [dh][key]
        {
            int key = tid & 63, dhg = tid >> 6;
            #pragma unroll
            for (int i = 0; i < 16; i++) {
                int dh = dhg * 16 + i;
                float v = stg[key * 65 + dh];
                uint32_t hv = f2tf(v);
                ((uint32_t*)Vh)[dh * AT_STRD + key] = hv;
                ((uint32_t*)Vl)[dh * AT_STRD + key] = f2tf(v - __uint_as_float(hv));
            }
        }
        __syncthreads();

        if (kt + 1 < nkt) {
            const float* kb = kbase + (size_t)(ktb + 64) * DM;
            const float* vb = vbase + (size_t)(ktb + 64) * DM;
            #pragma unroll
            for (int i = 0; i < 4; i++) {
                int r = ldr + i * 16;
                rk[i] = *(const float4*)(kb + (size_t)r * DM + ldc4 * 4);
                rv[i] = *(const float4*)(vb + (size_t)r * DM + ldc4 * 4);
            }
        }

        if (ktb > qw_max) continue;   // fully masked for this warp

        // ---- S = Q K^T (3-pass split) ----
        float sacc[8][4];
        #pragma unroll
        for (int nt = 0; nt < 8; nt++)
            #pragma unroll
            for (int i = 0; i < 4; i++) sacc[nt][i] = 0.f;

        #pragma unroll
        for (int kk = 0; kk < 8; kk++) {
            #pragma unroll
            for (int nt = 0; nt < 8; nt++) {
                int o = (nt * 8 + g) * AT_STRD + kk * 8 + t;
                uint32_t bh[2] = { __float_as_uint(Kh[o]), __float_as_uint(Kh[o + 4]) };
                uint32_t bl[2] = { __float_as_uint(Kl[o]), __float_as_uint(Kl[o + 4]) };
                mma1688(sacc[nt], qh[kk], bh);
                mma1688(sacc[nt], qh[kk], bl);
                mma1688(sacc[nt], ql[kk], bh);
            }
        }

        // ---- causal mask (diagonal tiles only) ----
        if (ktb + 63 > qw_min) {
            int qr0 = qw_min + g, qr1 = qr0 + 8;
            #pragma unroll
            for (int nt = 0; nt < 8; nt++) {
                int kc0 = ktb + nt * 8 + 2 * t;
                if (kc0     > qr0) sacc[nt][0] = -1e30f;
                if (kc0 + 1 > qr0) sacc[nt][1] = -1e30f;
                if (kc0     > qr1) sacc[nt][2] = -1e30f;
                if (kc0 + 1 > qr1) sacc[nt][3] = -1e30f;
            }
        }

        // ---- online softmax ----
        float mx0 = -1e30f, mx1 = -1e30f;
        #pragma unroll
        for (int nt = 0; nt < 8; nt++) {
            mx0 = fmaxf(mx0, fmaxf(sacc[nt][0], sacc[nt][1]));
            mx1 = fmaxf(mx1, fmaxf(sacc[nt][2], sacc[nt][3]));
        }
        mx0 = fmaxf(mx0, __shfl_xor_sync(0xffffffffu, mx0, 1));
        mx0 = fmaxf(mx0, __shfl_xor_sync(0xffffffffu, mx0, 2));
        mx1 = fmaxf(mx1, __shfl_xor_sync(0xffffffffu, mx1, 1));
        mx1 = fmaxf(mx1, __shfl_xor_sync(0xffffffffu, mx1, 2));

        float mn0 = fmaxf(m0, mx0), mn1 = fmaxf(m1, mx1);
        float c0 = __expf(m0 - mn0), c1 = __expf(m1 - mn1);
        m0 = mn0; m1 = mn1;

        float s0 = 0.f, s1 = 0.f;
        #pragma unroll
        for (int nt = 0; nt < 8; nt++) {
            sacc[nt][0] = __expf(sacc[nt][0] - mn0);
            sacc[nt][1] = __expf(sacc[nt][1] - mn0);
            sacc[nt][2] = __expf(sacc[nt][2] - mn1);
            sacc[nt][3] = __expf(sacc[nt][3] - mn1);
            s0 += sacc[nt][0] + sacc[nt][1];
            s1 += sacc[nt][2] + sacc[nt][3];
        }
        s0 += __shfl_xor_sync(0xffffffffu, s0, 1);
        s0 += __shfl_xor_sync(0xffffffffu, s0, 2);
        s1 += __shfl_xor_sync(0xffffffffu, s1, 1);
        s1 += __shfl_xor_sync(0xffffffffu, s1, 2);
        l0 = l0 * c0 + s0;
        l1 = l1 * c1 + s1;

        #pragma unroll
        for (int nt = 0; nt < 8; nt++) {
            oacc[nt][0] *= c0; oacc[nt][1] *= c0;
            oacc[nt][2] *= c1; oacc[nt][3] *= c1;
        }

        // ---- O += P V (3-pass split); C-frag -> A-frag via quad shuffles ----
        const int src0 = (lane & ~3) | (t >> 1);
        const int src1 = src0 | 2;
        #pragma unroll
        for (int kk = 0; kk < 8; kk++) {
            float x0 = __shfl_sync(0xffffffffu, sacc[kk][0], src0);
            float x1 = __shfl_sync(0xffffffffu, sacc[kk][1], src0);
            float x2 = __shfl_sync(0xffffffffu, sacc[kk][2], src0);
            float x3 = __shfl_sync(0xffffffffu, sacc[kk][3], src0);
            float y0 = __shfl_sync(0xffffffffu, sacc[kk][0], src1);
            float y1 = __shfl_sync(0xffffffffu, sacc[kk][1], src1);
            float y2 = __shfl_sync(0xffffffffu, sacc[kk][2], src1);
            float y3 = __shfl_sync(0xffffffffu, sacc[kk][3], src1);
            bool odd = (t & 1);
            float pa0 = odd ? x1 : x0;
            float pa1 = odd ? x3 : x2;
            float pa2 = odd ? y1 : y0;
            float pa3 = odd ? y3 : y2;
            uint32_t pah[4], pal[4];
            pah[0] = f2tf(pa0); pal[0] = f2tf(pa0 - __uint_as_float(pah[0]));
            pah[1] = f2tf(pa1); pal[1] = f2tf(pa1 - __uint_as_float(pah[1]));
            pah[2] = f2tf(pa2); pal[2] = f2tf(pa2 - __uint_as_float(pah[2]));
            pah[3] = f2tf(pa3); pal[3] = f2tf(pa3 - __uint_as_float(pah[3]));
            #pragma unroll
            for (int nt2 = 0; nt2 < 8; nt2++) {
                int o = (nt2 * 8 + g) * AT_STRD + kk * 8 + t;
                uint32_t vh[2] = { ((uint32_t*)Vh)[o], ((uint32_t*)Vh)[o + 4] };
                uint32_t vl[2] = { ((uint32_t*)Vl)[o], ((uint32_t*)Vl)[o + 4] };
                mma1688(oacc[nt2], pah, vh);
                mma1688(oacc[nt2], pah, vl);
                mma1688(oacc[nt2], pal, vh);
            }
        }
    }

    // ---- finalize ----
    float il0 = 1.0f / l0, il1 = 1.0f / l1;
    int r0 = q0 + wbase + g;
    float* op0 = g_o + ((size_t)(b * T_ + r0)) * DM + h * DH;
    float* op1 = op0 + (size_t)8 * DM;
    #pragma unroll
    for (int nt2 = 0; nt2 < 8; nt2++) {
        int col = nt2 * 8 + 2 * t;
        *(float2*)(op0 + col) = make_float2(oacc[nt2][0] * il0, oacc[nt2][1] * il0);
        *(float2*)(op1 + col) = make_float2(oacc[nt2][2] * il1, oacc[nt2][3] * il1);
    }
}

// ---------------------------------------------------------------------------
// Launch: hidden_states, shared_k, shared_v, Wq, Wo -> out (float32 [B,T,Dm])
// ---------------------------------------------------------------------------
extern "C" void kernel_launch(void* const* d_in, const int* in_sizes, int n_in,
                              void* d_out, int out_size) {
    const float* hidden = (const float*)d_in[0];
    const float* Kin    = (const float*)d_in[1];
    const float* Vin    = (const float*)d_in[2];
    const float* Wq     = (const float*)d_in[3];
    const float* Wo     = (const float*)d_in[4];
    float* out          = (float*)d_out;

    cudaFuncSetAttribute(gemm_mma_kernel<true>,
                         cudaFuncAttributeMaxDynamicSharedMemorySize, SMEM_G_BYTES);
    cudaFuncSetAttribute(gemm_mma_kernel<false>,
                         cudaFuncAttributeMaxDynamicSharedMemorySize, SMEM_G_BYTES);
    cudaFuncSetAttribute(attn_mma_kernel,
                         cudaFuncAttributeMaxDynamicSharedMemorySize, SMEM_A_BYTES);

    rope_table_kernel<<<(T_ * (DH/2) + 255) / 256, 256>>>();

    dim3 gGemm(DM / 128, M_ / 128);   // (16, 32)
    gemm_mma_kernel<true><<<gGemm, 256, SMEM_G_BYTES>>>(hidden, Wq, nullptr);

    dim3 gAttn(T_ / 128, H_, B_);     // (16, 32, 2)
    attn_mma_kernel<<<gAttn, 256, SMEM_A_BYTES>>>(Kin, Vin);

    gemm_mma_kernel<false><<<gGemm, 256, SMEM_G_BYTES>>>(nullptr, Wo, out);
}

// round 7
// speedup vs baseline: 2.8689x; 1.5631x over previous
#include <cuda_runtime.h>
#include <cuda_fp16.h>
#include <math.h>
#include <stdint.h>

// Problem constants
#define B_  2
#define T_  2048
#define DM  2048
#define H_  32
#define DH  64
#define M_  (B_*T_)   // 4096

// Scratch (device globals: allocation-free per harness rules)
__device__ float g_q[(size_t)B_*H_*T_*DH];    // [B,H,T,Dh] rope'd Q
__device__ float g_o[(size_t)M_*DM];          // [B*T, Dm] attention output
__device__ float g_cos[T_*(DH/2)];
__device__ float g_sin[T_*(DH/2)];

// ---------------------------------------------------------------------------
// helpers
// ---------------------------------------------------------------------------
__device__ __forceinline__ uint32_t pack_h2(float a, float b) {
    __half2 h = __floats2half2_rn(a, b);
    return *(uint32_t*)&h;
}

// hi = fp16(x), lo = fp16(x - hi), packed as half2 pairs
__device__ __forceinline__ void split_h2(float x, float y, uint32_t& h, uint32_t& l) {
    __half2 hh = __floats2half2_rn(x, y);
    float2 f = __half22float2(hh);
    __half2 ll = __floats2half2_rn(x - f.x, y - f.y);
    h = *(uint32_t*)&hh;
    l = *(uint32_t*)&ll;
}

// d += a * b  (fp16 m16n8k16, fp32 accumulate)
__device__ __forceinline__ void mma16816(float* d, const uint32_t* a, const uint32_t* b) {
    asm volatile(
        "mma.sync.aligned.m16n8k16.row.col.f32.f16.f16.f32 "
        "{%0,%1,%2,%3}, {%4,%5,%6,%7}, {%8,%9}, {%0,%1,%2,%3};"
        : "+f"(d[0]), "+f"(d[1]), "+f"(d[2]), "+f"(d[3])
        : "r"(a[0]), "r"(a[1]), "r"(a[2]), "r"(a[3]), "r"(b[0]), "r"(b[1]));
}

// ---------------------------------------------------------------------------
// RoPE table
// ---------------------------------------------------------------------------
__global__ void rope_table_kernel() {
    int idx = blockIdx.x * blockDim.x + threadIdx.x;
    if (idx >= T_ * (DH/2)) return;
    int t = idx >> 5;
    int i = idx & 31;
    double inv = pow(10000.0, -((double)(2 * i)) / 64.0);
    double ang = (double)t * inv;
    g_cos[idx] = (float)cos(ang);
    g_sin[idx] = (float)sin(ang);
}

// ---------------------------------------------------------------------------
// Split-FP16 mma.sync GEMM: C[m,n] = sum_k A[m,k] * W[n,k]  (A @ W^T)
// CTA 128x128, BK=32, 256 threads (8 warps 2x4, each 64x32).
// Rows: 16 data words + 4 pad = stride 20 (BK=32 k-values).
// 3-pass: Ahi*Bhi + Ahi*Blo + Alo*Bhi.
// ---------------------------------------------------------------------------
#define GSTW 20
#define GT_W (128*GSTW)
#define SMEM_G_BYTES (4*GT_W*4)         // 40960 B

template<bool DO_ROPE>
__global__ __launch_bounds__(256)
void gemm_mma_kernel(const float* __restrict__ Ain,
                     const float* __restrict__ Bw,
                     float* __restrict__ C) {
    extern __shared__ uint32_t smw[];
    uint32_t* Ah = smw;
    uint32_t* Al = smw + GT_W;
    uint32_t* Bh = smw + 2*GT_W;
    uint32_t* Bl = smw + 3*GT_W;

    const float* A = DO_ROPE ? Ain : (const float*)g_o;

    const int tid   = threadIdx.x;
    const int wid   = tid >> 5;
    const int lane  = tid & 31;
    const int g     = lane >> 2;
    const int t     = lane & 3;
    const int warpR = wid >> 2;
    const int warpC = wid & 3;
    const int rowBase = blockIdx.y * 128;
    const int colBase = blockIdx.x * 128;

    float acc[4][4][4];
    #pragma unroll
    for (int mt = 0; mt < 4; mt++)
        #pragma unroll
        for (int nt = 0; nt < 4; nt++)
            #pragma unroll
            for (int i = 0; i < 4; i++) acc[mt][nt][i] = 0.f;

    const int lr  = tid >> 3;
    const int lc4 = tid & 7;

    for (int kt = 0; kt < 64; kt++) {
        float4 ra[4], rb[4];
        #pragma unroll
        for (int i = 0; i < 4; i++) {
            int r = lr + i * 32;
            ra[i] = *(const float4*)(A  + (size_t)(rowBase + r) * DM + kt * 32 + lc4 * 4);
            rb[i] = *(const float4*)(Bw + (size_t)(colBase + r) * DM + kt * 32 + lc4 * 4);
        }

        __syncthreads();

        #pragma unroll
        for (int i = 0; i < 4; i++) {
            int r = lr + i * 32;
            int wo = r * GSTW + lc4 * 2;
            uint32_t h0, l0, h1, l1;
            split_h2(ra[i].x, ra[i].y, h0, l0);
            split_h2(ra[i].z, ra[i].w, h1, l1);
            *(uint2*)(Ah + wo) = make_uint2(h0, h1);
            *(uint2*)(Al + wo) = make_uint2(l0, l1);
            split_h2(rb[i].x, rb[i].y, h0, l0);
            split_h2(rb[i].z, rb[i].w, h1, l1);
            *(uint2*)(Bh + wo) = make_uint2(h0, h1);
            *(uint2*)(Bl + wo) = make_uint2(l0, l1);
        }
        __syncthreads();

        #pragma unroll
        for (int ks = 0; ks < 2; ks++) {
            uint32_t ah[4][4], al4[4][4], bh[4][2], bl4[4][2];
            #pragma unroll
            for (int mt = 0; mt < 4; mt++) {
                int r0 = (warpR * 64 + mt * 16 + g) * GSTW + ks * 8 + t;
                int r1 = r0 + 8 * GSTW;
                ah[mt][0] = Ah[r0];     ah[mt][1] = Ah[r1];
                ah[mt][2] = Ah[r0 + 4]; ah[mt][3] = Ah[r1 + 4];
                al4[mt][0] = Al[r0];     al4[mt][1] = Al[r1];
                al4[mt][2] = Al[r0 + 4]; al4[mt][3] = Al[r1 + 4];
            }
            #pragma unroll
            for (int nt = 0; nt < 4; nt++) {
                int o = (warpC * 32 + nt * 8 + g) * GSTW + ks * 8 + t;
                bh[nt][0] = Bh[o]; bh[nt][1] = Bh[o + 4];
                bl4[nt][0] = Bl[o]; bl4[nt][1] = Bl[o + 4];
            }
            #pragma unroll
            for (int mt = 0; mt < 4; mt++)
                #pragma unroll
                for (int nt = 0; nt < 4; nt++) {
                    mma16816(acc[mt][nt], ah[mt], bh[nt]);
                    mma16816(acc[mt][nt], ah[mt], bl4[nt]);
                    mma16816(acc[mt][nt], al4[mt], bh[nt]);
                }
        }
    }

    #pragma unroll
    for (int mt = 0; mt < 4; mt++) {
        #pragma unroll
        for (int nt = 0; nt < 4; nt++) {
            int m0 = rowBase + warpR * 64 + mt * 16 + g;
            int n  = colBase + warpC * 32 + nt * 8 + 2 * t;
            if (DO_ROPE) {
                #pragma unroll
                for (int half = 0; half < 2; half++) {
                    int m = m0 + half * 8;
                    float x1 = acc[mt][nt][half * 2];
                    float x2 = acc[mt][nt][half * 2 + 1];
                    int bb = m >> 11;
                    int tt = m & (T_ - 1);
                    int hh = n >> 6;
                    int d  = n & 63;
                    float c = g_cos[tt * 32 + (d >> 1)];
                    float s = g_sin[tt * 32 + (d >> 1)];
                    size_t base = (((size_t)(bb * H_ + hh)) * T_ + tt) * DH + d;
                    float2 v = make_float2(x1 * c - x2 * s, x1 * s + x2 * c);
                    *(float2*)(g_q + base) = v;
                }
            } else {
                float2 v0 = make_float2(acc[mt][nt][0], acc[mt][nt][1]);
                float2 v1 = make_float2(acc[mt][nt][2], acc[mt][nt][3]);
                *(float2*)(C + (size_t)m0 * DM + n)       = v0;
                *(float2*)(C + (size_t)(m0 + 8) * DM + n) = v1;
            }
        }
    }
}

// ---------------------------------------------------------------------------
// FP16 tensor-core causal flash attention.
// Block = (b, h, 128-row Q tile). 256 threads, 8 warps x 16 rows.
// K rows hold DH=64 values = 32 words -> stride 36 (NOT 20!).
// ---------------------------------------------------------------------------
#define KSTW 36
#define VSTW 36
#define KW_  (64*KSTW)                  // 2304 words
#define VW_  (64*VSTW)                  // 2304 words
#define STGW (64*65)                    // 4160 words (fp32 V stage)
#define SMEM_A_WORDS (2*KW_ + 2*VW_ + STGW)   // 13376
#define SMEM_A_BYTES (SMEM_A_WORDS*4)         // 53504 B

__global__ __launch_bounds__(256)
void attn_mma_kernel(const float* __restrict__ Kg, const float* __restrict__ Vg) {
    extern __shared__ uint32_t smw[];
    uint32_t* Khw = smw;
    uint32_t* Klw = smw + KW_;
    uint32_t* Vhw = smw + 2*KW_;
    uint32_t* Vlw = smw + 2*KW_ + VW_;
    float*    stg = (float*)(smw + 2*KW_ + 2*VW_);
    float*    smf = (float*)smw;        // Q staging overlay (one-time, 8320 words)

    const int tid  = threadIdx.x;
    const int wid  = tid >> 5;
    const int lane = tid & 31;
    const int g    = lane >> 2;
    const int t    = lane & 3;
    const int bx   = (int)gridDim.x - 1 - (int)blockIdx.x;   // heavy blocks first
    const int h    = blockIdx.y;
    const int b    = blockIdx.z;
    const int q0   = bx * 128;
    const int wbase = wid * 16;

    // ---- stage Q tile fp32 (rows 128, stride 65) ----
    const float* qbase = g_q + (((size_t)(b * H_ + h)) * T_ + q0) * DH;
    #pragma unroll
    for (int i = 0; i < 8; i++) {
        int chunk = i * 256 + tid;
        int r = chunk >> 4, c4 = chunk & 15;
        float4 v = *(const float4*)(qbase + (size_t)r * DH + c4 * 4);
        float* dst = smf + r * 65 + c4 * 4;
        dst[0] = v.x; dst[1] = v.y; dst[2] = v.z; dst[3] = v.w;
    }
    __syncthreads();

    // Q A-frags (scaled, split hi/lo)
    uint32_t qh[4][4], ql[4][4];
    #pragma unroll
    for (int s = 0; s < 4; s++) {
        int r0 = (wbase + g) * 65 + s * 16 + 2 * t;
        int r1 = r0 + 8 * 65;
        split_h2(0.125f * smf[r0],     0.125f * smf[r0 + 1], qh[s][0], ql[s][0]);
        split_h2(0.125f * smf[r1],     0.125f * smf[r1 + 1], qh[s][1], ql[s][1]);
        split_h2(0.125f * smf[r0 + 8], 0.125f * smf[r0 + 9], qh[s][2], ql[s][2]);
        split_h2(0.125f * smf[r1 + 8], 0.125f * smf[r1 + 9], qh[s][3], ql[s][3]);
    }
    __syncthreads();   // done with smf before K/V stores overlay it

    float m0 = -1e30f, m1 = -1e30f, l0 = 0.f, l1 = 0.f;
    float oacc[8][4];
    #pragma unroll
    for (int nt = 0; nt < 8; nt++)
        #pragma unroll
        for (int i = 0; i < 4; i++) oacc[nt][i] = 0.f;

    const int nkt = 2 * bx + 2;
    const float* kbase = Kg + (size_t)b * T_ * DM + h * DH;
    const float* vbase = Vg + (size_t)b * T_ * DM + h * DH;

    const int ldr  = tid >> 4;
    const int ldc4 = tid & 15;

    float4 rk[4], rv[4];
    #pragma unroll
    for (int i = 0; i < 4; i++) {
        int r = ldr + i * 16;
        rk[i] = *(const float4*)(kbase + (size_t)r * DM + ldc4 * 4);
        rv[i] = *(const float4*)(vbase + (size_t)r * DM + ldc4 * 4);
    }

    const int qw_min = q0 + wbase;
    const int qw_max = q0 + wbase + 15;
    const int kh_ = tid & 31;     // key-pair index for V convert
    const int dhg = tid >> 5;     // 0..7

    for (int kt = 0; kt < nkt; kt++) {
        const int ktb = kt * 64;

        __syncthreads();

        // K hi/lo store + V fp32 stage
        #pragma unroll
        for (int i = 0; i < 4; i++) {
            int r = ldr + i * 16;
            int wo = r * KSTW + ldc4 * 2;
            uint32_t h0, lo0, h1, lo1;
            split_h2(rk[i].x, rk[i].y, h0, lo0);
            split_h2(rk[i].z, rk[i].w, h1, lo1);
            *(uint2*)(Khw + wo) = make_uint2(h0, h1);
            *(uint2*)(Klw + wo) = make_uint2(lo0, lo1);
            float* sp = stg + r * 65 + ldc4 * 4;
            sp[0] = rv[i].x; sp[1] = rv[i].y; sp[2] = rv[i].z; sp[3] = rv[i].w;
        }
        __syncthreads();

        // V convert: [key][dh] fp32 -> V^T [dh][keypair] half2 hi/lo
        #pragma unroll
        for (int i = 0; i < 8; i++) {
            int dh = dhg * 8 + i;
            float v0 = stg[(2 * kh_)     * 65 + dh];
            float v1 = stg[(2 * kh_ + 1) * 65 + dh];
            uint32_t hw, lw;
            split_h2(v0, v1, hw, lw);
            Vhw[dh * VSTW + kh_] = hw;
            Vlw[dh * VSTW + kh_] = lw;
        }
        __syncthreads();

        // prefetch next tile
        if (kt + 1 < nkt) {
            const float* kb = kbase + (size_t)(ktb + 64) * DM;
            const float* vb = vbase + (size_t)(ktb + 64) * DM;
            #pragma unroll
            for (int i = 0; i < 4; i++) {
                int r = ldr + i * 16;
                rk[i] = *(const float4*)(kb + (size_t)r * DM + ldc4 * 4);
                rv[i] = *(const float4*)(vb + (size_t)r * DM + ldc4 * 4);
            }
        }

        if (ktb > qw_max) continue;   // fully masked for this warp

        // ---- S = Q K^T (3-pass fp16 split) ----
        float sacc[8][4];
        #pragma unroll
        for (int nt = 0; nt < 8; nt++)
            #pragma unroll
            for (int i = 0; i < 4; i++) sacc[nt][i] = 0.f;

        #pragma unroll
        for (int s = 0; s < 4; s++) {
            #pragma unroll
            for (int nt = 0; nt < 8; nt++) {
                int o = (nt * 8 + g) * KSTW + s * 8 + t;
                uint32_t bh2[2] = { Khw[o], Khw[o + 4] };
                uint32_t bl2[2] = { Klw[o], Klw[o + 4] };
                mma16816(sacc[nt], qh[s], bh2);
                mma16816(sacc[nt], qh[s], bl2);
                mma16816(sacc[nt], ql[s], bh2);
            }
        }

        // ---- causal mask (diagonal tiles only) ----
        if (ktb + 63 > qw_min) {
            int qr0 = qw_min + g, qr1 = qr0 + 8;
            #pragma unroll
            for (int nt = 0; nt < 8; nt++) {
                int kc0 = ktb + nt * 8 + 2 * t;
                if (kc0     > qr0) sacc[nt][0] = -1e30f;
                if (kc0 + 1 > qr0) sacc[nt][1] = -1e30f;
                if (kc0     > qr1) sacc[nt][2] = -1e30f;
                if (kc0 + 1 > qr1) sacc[nt][3] = -1e30f;
            }
        }

        // ---- online softmax ----
        float mx0 = -1e30f, mx1 = -1e30f;
        #pragma unroll
        for (int nt = 0; nt < 8; nt++) {
            mx0 = fmaxf(mx0, fmaxf(sacc[nt][0], sacc[nt][1]));
            mx1 = fmaxf(mx1, fmaxf(sacc[nt][2], sacc[nt][3]));
        }
        mx0 = fmaxf(mx0, __shfl_xor_sync(0xffffffffu, mx0, 1));
        mx0 = fmaxf(mx0, __shfl_xor_sync(0xffffffffu, mx0, 2));
        mx1 = fmaxf(mx1, __shfl_xor_sync(0xffffffffu, mx1, 1));
        mx1 = fmaxf(mx1, __shfl_xor_sync(0xffffffffu, mx1, 2));

        float mn0 = fmaxf(m0, mx0), mn1 = fmaxf(m1, mx1);
        float c0 = __expf(m0 - mn0), c1 = __expf(m1 - mn1);
        m0 = mn0; m1 = mn1;

        float s0 = 0.f, s1 = 0.f;
        #pragma unroll
        for (int nt = 0; nt < 8; nt++) {
            sacc[nt][0] = __expf(sacc[nt][0] - mn0);
            sacc[nt][1] = __expf(sacc[nt][1] - mn0);
            sacc[nt][2] = __expf(sacc[nt][2] - mn1);
            sacc[nt][3] = __expf(sacc[nt][3] - mn1);
            s0 += sacc[nt][0] + sacc[nt][1];
            s1 += sacc[nt][2] + sacc[nt][3];
        }
        s0 += __shfl_xor_sync(0xffffffffu, s0, 1);
        s0 += __shfl_xor_sync(0xffffffffu, s0, 2);
        s1 += __shfl_xor_sync(0xffffffffu, s1, 1);
        s1 += __shfl_xor_sync(0xffffffffu, s1, 2);
        l0 = l0 * c0 + s0;
        l1 = l1 * c1 + s1;

        #pragma unroll
        for (int nt = 0; nt < 8; nt++) {
            oacc[nt][0] *= c0; oacc[nt][1] *= c0;
            oacc[nt][2] *= c1; oacc[nt][3] *= c1;
        }

        // ---- O += P V (P fp16 single-pass; V hi/lo 2-pass) ----
        #pragma unroll
        for (int s = 0; s < 4; s++) {
            uint32_t pa[4];
            pa[0] = pack_h2(sacc[2*s][0],     sacc[2*s][1]);
            pa[1] = pack_h2(sacc[2*s][2],     sacc[2*s][3]);
            pa[2] = pack_h2(sacc[2*s + 1][0], sacc[2*s + 1][1]);
            pa[3] = pack_h2(sacc[2*s + 1][2], sacc[2*s + 1][3]);
            #pragma unroll
            for (int nt2 = 0; nt2 < 8; nt2++) {
                int o = (nt2 * 8 + g) * VSTW + s * 8 + t;
                uint32_t vh2[2] = { Vhw[o], Vhw[o + 4] };
                uint32_t vl2[2] = { Vlw[o], Vlw[o + 4] };
                mma16816(oacc[nt2], pa, vh2);
                mma16816(oacc[nt2], pa, vl2);
            }
        }
    }

    // ---- finalize ----
    float il0 = 1.0f / l0, il1 = 1.0f / l1;
    int r0 = q0 + wbase + g;
    float* op0 = g_o + ((size_t)(b * T_ + r0)) * DM + h * DH;
    float* op1 = op0 + (size_t)8 * DM;
    #pragma unroll
    for (int nt2 = 0; nt2 < 8; nt2++) {
        int col = nt2 * 8 + 2 * t;
        *(float2*)(op0 + col) = make_float2(oacc[nt2][0] * il0, oacc[nt2][1] * il0);
        *(float2*)(op1 + col) = make_float2(oacc[nt2][2] * il1, oacc[nt2][3] * il1);
    }
}

// ---------------------------------------------------------------------------
// Launch: hidden_states, shared_k, shared_v, Wq, Wo -> out (float32 [B,T,Dm])
// ---------------------------------------------------------------------------
extern "C" void kernel_launch(void* const* d_in, const int* in_sizes, int n_in,
                              void* d_out, int out_size) {
    const float* hidden = (const float*)d_in[0];
    const float* Kin    = (const float*)d_in[1];
    const float* Vin    = (const float*)d_in[2];
    const float* Wq     = (const float*)d_in[3];
    const float* Wo     = (const float*)d_in[4];
    float* out          = (float*)d_out;

    cudaFuncSetAttribute(gemm_mma_kernel<true>,
                         cudaFuncAttributeMaxDynamicSharedMemorySize, SMEM_G_BYTES);
    cudaFuncSetAttribute(gemm_mma_kernel<false>,
                         cudaFuncAttributeMaxDynamicSharedMemorySize, SMEM_G_BYTES);
    cudaFuncSetAttribute(attn_mma_kernel,
                         cudaFuncAttributeMaxDynamicSharedMemorySize, SMEM_A_BYTES);

    rope_table_kernel<<<(T_ * (DH/2) + 255) / 256, 256>>>();

    dim3 gGemm(DM / 128, M_ / 128);   // (16, 32)
    gemm_mma_kernel<true><<<gGemm, 256, SMEM_G_BYTES>>>(hidden, Wq, nullptr);

    dim3 gAttn(T_ / 128, H_, B_);     // (16, 32, 2)
    attn_mma_kernel<<<gAttn, 256, SMEM_A_BYTES>>>(Kin, Vin);

    gemm_mma_kernel<false><<<gGemm, 256, SMEM_G_BYTES>>>(nullptr, Wo, out);
}

// round 8
// speedup vs baseline: 3.0910x; 1.0774x over previous
#include <cuda_runtime.h>
#include <cuda_fp16.h>
#include <math.h>
#include <stdint.h>

// Problem constants
#define B_  2
#define T_  2048
#define DM  2048
#define H_  32
#define DH  64
#define M_  (B_*T_)   // 4096

// ---------------------------------------------------------------------------
// Half hi/lo scratch (device globals: allocation-free per harness rules)
// ---------------------------------------------------------------------------
__device__ __half g_ah[(size_t)M_*DM],  g_al[(size_t)M_*DM];     // split hidden
__device__ __half g_wqh[(size_t)DM*DM], g_wql[(size_t)DM*DM];    // split Wq
__device__ __half g_woh[(size_t)DM*DM], g_wol[(size_t)DM*DM];    // split Wo
__device__ __half g_qh[(size_t)B_*H_*T_*DH], g_ql[(size_t)B_*H_*T_*DH];   // rope'd+scaled Q
__device__ __half g_kh[(size_t)B_*H_*T_*DH], g_kl[(size_t)B_*H_*T_*DH];   // K [B,H,T,Dh]
__device__ __half g_vth[(size_t)B_*H_*T_*DH], g_vtl[(size_t)B_*H_*T_*DH]; // V^T [B,H,Dh,T]
__device__ __half g_oh[(size_t)M_*DM],  g_ol[(size_t)M_*DM];     // attention out
__device__ float g_cos[T_*(DH/2)];
__device__ float g_sin[T_*(DH/2)];

// ---------------------------------------------------------------------------
// helpers
// ---------------------------------------------------------------------------
__device__ __forceinline__ uint32_t pack_h2(float a, float b) {
    __half2 h = __floats2half2_rn(a, b);
    return *(uint32_t*)&h;
}
__device__ __forceinline__ void split_h2(float x, float y, uint32_t& h, uint32_t& l) {
    __half2 hh = __floats2half2_rn(x, y);
    float2 f = __half22float2(hh);
    __half2 ll = __floats2half2_rn(x - f.x, y - f.y);
    h = *(uint32_t*)&hh;
    l = *(uint32_t*)&ll;
}
__device__ __forceinline__ void mma16816(float* d, const uint32_t* a, const uint32_t* b) {
    asm volatile(
        "mma.sync.aligned.m16n8k16.row.col.f32.f16.f16.f32 "
        "{%0,%1,%2,%3}, {%4,%5,%6,%7}, {%8,%9}, {%0,%1,%2,%3};"
        : "+f"(d[0]), "+f"(d[1]), "+f"(d[2]), "+f"(d[3])
        : "r"(a[0]), "r"(a[1]), "r"(a[2]), "r"(a[3]), "r"(b[0]), "r"(b[1]));
}

// ---------------------------------------------------------------------------
// RoPE table
// ---------------------------------------------------------------------------
__global__ void rope_table_kernel() {
    int idx = blockIdx.x * blockDim.x + threadIdx.x;
    if (idx >= T_ * (DH/2)) return;
    int t = idx >> 5;
    int i = idx & 31;
    double inv = pow(10000.0, -((double)(2 * i)) / 64.0);
    double ang = (double)t * inv;
    g_cos[idx] = (float)cos(ang);
    g_sin[idx] = (float)sin(ang);
}

// ---------------------------------------------------------------------------
// Elementwise fp32 -> half hi/lo split.  WHICH: 0=hidden, 1=Wq, 2=Wo
// ---------------------------------------------------------------------------
template<int WHICH>
__global__ void split_f32_kernel(const float* __restrict__ in) {
    size_t i = (size_t)blockIdx.x * 256 + threadIdx.x;
    float2 v = ((const float2*)in)[i];
    uint32_t h, l;
    split_h2(v.x, v.y, h, l);
    uint32_t* hw = (uint32_t*)(WHICH == 0 ? g_ah : WHICH == 1 ? g_wqh : g_woh);
    uint32_t* lw = (uint32_t*)(WHICH == 0 ? g_al : WHICH == 1 ? g_wql : g_wol);
    hw[i] = h;
    lw[i] = l;
}

// ---------------------------------------------------------------------------
// K prep: [B,T,H,Dh] fp32 -> [B,H,T,Dh] half hi/lo.  One half2 word / thread.
// ---------------------------------------------------------------------------
__global__ void prep_k_kernel(const float* __restrict__ Kg) {
    uint32_t w = blockIdx.x * 256 + threadIdx.x;     // < B*H*T*32
    int dh2 = w & 31;
    int tok = (w >> 5) & (T_ - 1);
    int h   = (w >> 16) & (H_ - 1);
    int b   = (int)(w >> 21);
    float2 v = ((const float2*)Kg)[(((size_t)(b * T_ + tok)) * H_ + h) * 32 + dh2];
    uint32_t hh, ll;
    split_h2(v.x, v.y, hh, ll);
    ((uint32_t*)g_kh)[w] = hh;
    ((uint32_t*)g_kl)[w] = ll;
}

// ---------------------------------------------------------------------------
// V prep: [B,T,H,Dh] fp32 -> transposed [B,H,Dh,T] half hi/lo (key-pair words).
// Block = (keytile64, h, b), 256 threads, smem transpose.
// ---------------------------------------------------------------------------
__global__ void prep_v_kernel(const float* __restrict__ Vg) {
    __shared__ float stg[64 * 65];
    const int tid = threadIdx.x;
    const int kt  = blockIdx.x, h = blockIdx.y, b = blockIdx.z;
    const float* src = Vg + ((size_t)(b * T_ + kt * 64) * H_ + h) * DH;

    #pragma unroll
    for (int i = 0; i < 4; i++) {
        int chunk = i * 256 + tid;            // 64 rows x 16 float4
        int r = chunk >> 4, c4 = chunk & 15;
        float4 v = *(const float4*)(src + (size_t)r * (H_ * DH) + c4 * 4);
        float* d = stg + r * 65 + c4 * 4;
        d[0] = v.x; d[1] = v.y; d[2] = v.z; d[3] = v.w;
    }
    __syncthreads();

    const int kp = tid & 31, dhg = tid >> 5;
    #pragma unroll
    for (int i = 0; i < 8; i++) {
        int dh = dhg * 8 + i;
        float v0 = stg[(2 * kp)     * 65 + dh];
        float v1 = stg[(2 * kp + 1) * 65 + dh];
        uint32_t hw, lw;
        split_h2(v0, v1, hw, lw);
        size_t idx = ((size_t)(b * H_ + h) * DH + dh) * (T_ / 2) + kt * 32 + kp;
        ((uint32_t*)g_vth)[idx] = hw;
        ((uint32_t*)g_vtl)[idx] = lw;
    }
}

// ---------------------------------------------------------------------------
// Split-FP16 GEMM on preconverted operands: C = A @ W^T.
// CTA 128x128, BK=32, 256 threads. Smem stride 28 words (uint4-aligned,
// conflict-free frags). MODE 0: Q-proj (+RoPE, scale, half out). MODE 1: fp32 out.
// ---------------------------------------------------------------------------
#define GSTW 28
#define GT_W (128*GSTW)
#define SMEM_G_BYTES (4*GT_W*4)         // 57344 B

template<int MODE>
__global__ __launch_bounds__(256)
void gemm_h_kernel(float* __restrict__ C) {
    extern __shared__ uint32_t smw[];
    uint32_t* Ah = smw;
    uint32_t* Al = smw + GT_W;
    uint32_t* Bh = smw + 2*GT_W;
    uint32_t* Bl = smw + 3*GT_W;

    const uint4* Agh = (const uint4*)(MODE == 0 ? g_ah  : g_oh);
    const uint4* Agl = (const uint4*)(MODE == 0 ? g_al  : g_ol);
    const uint4* Bgh = (const uint4*)(MODE == 0 ? g_wqh : g_woh);
    const uint4* Bgl = (const uint4*)(MODE == 0 ? g_wql : g_wol);

    const int tid   = threadIdx.x;
    const int wid   = tid >> 5;
    const int lane  = tid & 31;
    const int g     = lane >> 2;
    const int t     = lane & 3;
    const int warpR = wid >> 2;
    const int warpC = wid & 3;
    const int rowBase = blockIdx.y * 128;
    const int colBase = blockIdx.x * 128;

    float acc[4][4][4];
    #pragma unroll
    for (int mt = 0; mt < 4; mt++)
        #pragma unroll
        for (int nt = 0; nt < 4; nt++)
            #pragma unroll
            for (int i = 0; i < 4; i++) acc[mt][nt][i] = 0.f;

    const int lr2 = tid >> 2;   // 0..63
    const int lc2 = tid & 3;    // 0..3 (uint4 = 8 halves; 4 per row)

    for (int kt = 0; kt < 64; kt++) {
        uint4 rah[2], ral[2], rbh[2], rbl[2];
        #pragma unroll
        for (int i = 0; i < 2; i++) {
            int r = lr2 + i * 64;
            size_t ai = ((size_t)(rowBase + r)) * 256 + kt * 4 + lc2;  // 256 uint4/row
            size_t bi = ((size_t)(colBase + r)) * 256 + kt * 4 + lc2;
            rah[i] = Agh[ai]; ral[i] = Agl[ai];
            rbh[i] = Bgh[bi]; rbl[i] = Bgl[bi];
        }

        __syncthreads();
        #pragma unroll
        for (int i = 0; i < 2; i++) {
            int wo = (lr2 + i * 64) * GSTW + lc2 * 4;
            *(uint4*)(Ah + wo) = rah[i];
            *(uint4*)(Al + wo) = ral[i];
            *(uint4*)(Bh + wo) = rbh[i];
            *(uint4*)(Bl + wo) = rbl[i];
        }
        __syncthreads();

        #pragma unroll
        for (int ks = 0; ks < 2; ks++) {
            uint32_t ah[4][4], al4[4][4], bh[4][2], bl4[4][2];
            #pragma unroll
            for (int mt = 0; mt < 4; mt++) {
                int r0 = (warpR * 64 + mt * 16 + g) * GSTW + ks * 8 + t;
                int r1 = r0 + 8 * GSTW;
                ah[mt][0] = Ah[r0];     ah[mt][1] = Ah[r1];
                ah[mt][2] = Ah[r0 + 4]; ah[mt][3] = Ah[r1 + 4];
                al4[mt][0] = Al[r0];     al4[mt][1] = Al[r1];
                al4[mt][2] = Al[r0 + 4]; al4[mt][3] = Al[r1 + 4];
            }
            #pragma unroll
            for (int nt = 0; nt < 4; nt++) {
                int o = (warpC * 32 + nt * 8 + g) * GSTW + ks * 8 + t;
                bh[nt][0] = Bh[o]; bh[nt][1] = Bh[o + 4];
                bl4[nt][0] = Bl[o]; bl4[nt][1] = Bl[o + 4];
            }
            #pragma unroll
            for (int mt = 0; mt < 4; mt++)
                #pragma unroll
                for (int nt = 0; nt < 4; nt++) {
                    mma16816(acc[mt][nt], ah[mt], bh[nt]);
                    mma16816(acc[mt][nt], ah[mt], bl4[nt]);
                    mma16816(acc[mt][nt], al4[mt], bh[nt]);
                }
        }
    }

    #pragma unroll
    for (int mt = 0; mt < 4; mt++) {
        #pragma unroll
        for (int nt = 0; nt < 4; nt++) {
            int m0 = rowBase + warpR * 64 + mt * 16 + g;
            int n  = colBase + warpC * 32 + nt * 8 + 2 * t;
            if (MODE == 0) {
                int hh = n >> 6;
                int d  = n & 63;   // even
                #pragma unroll
                for (int half = 0; half < 2; half++) {
                    int m = m0 + half * 8;
                    float x1 = acc[mt][nt][half * 2];
                    float x2 = acc[mt][nt][half * 2 + 1];
                    int bb = m >> 11;
                    int tt = m & (T_ - 1);
                    float c = g_cos[tt * 32 + (d >> 1)];
                    float s = g_sin[tt * 32 + (d >> 1)];
                    float xr1 = (x1 * c - x2 * s) * 0.125f;
                    float xr2 = (x1 * s + x2 * c) * 0.125f;
                    uint32_t hw, lw;
                    split_h2(xr1, xr2, hw, lw);
                    size_t idx = ((size_t)(bb * H_ + hh) * T_ + tt) * 32 + (d >> 1);
                    ((uint32_t*)g_qh)[idx] = hw;
                    ((uint32_t*)g_ql)[idx] = lw;
                }
            } else {
                float2 v0 = make_float2(acc[mt][nt][0], acc[mt][nt][1]);
                float2 v1 = make_float2(acc[mt][nt][2], acc[mt][nt][3]);
                *(float2*)(C + (size_t)m0 * DM + n)       = v0;
                *(float2*)(C + (size_t)(m0 + 8) * DM + n) = v1;
            }
        }
    }
}

// ---------------------------------------------------------------------------
// FP16 flash attention on preconverted operands.
// Block = (b, h, 128-row Q tile). 256 threads, 8 warps x 16 rows.
// Smem stride 44 words (uint4-aligned, conflict-free: bank 12g+8s+t distinct).
// ---------------------------------------------------------------------------
#define ASTW 44
#define AT_W (64*ASTW)                  // 2816 words / buffer
#define SMEM_A_BYTES (4*AT_W*4)         // 45056 B

__global__ __launch_bounds__(256)
void attn_mma_kernel() {
    extern __shared__ uint32_t smw[];
    uint32_t* Khw = smw;
    uint32_t* Klw = smw + AT_W;
    uint32_t* Vhw = smw + 2*AT_W;
    uint32_t* Vlw = smw + 3*AT_W;

    const int tid  = threadIdx.x;
    const int wid  = tid >> 5;
    const int lane = tid & 31;
    const int g    = lane >> 2;
    const int t    = lane & 3;
    const int bx   = (int)gridDim.x - 1 - (int)blockIdx.x;   // heavy blocks first
    const int h    = blockIdx.y;
    const int b    = blockIdx.z;
    const int q0   = bx * 128;
    const int wbase = wid * 16;

    // ---- Q A-frags direct from gmem (pre-rope'd, pre-scaled, pre-split) ----
    uint32_t qh[4][4], ql[4][4];
    {
        const uint32_t* qhw = (const uint32_t*)g_qh
            + (((size_t)(b * H_ + h)) * T_ + q0 + wbase + g) * 32;
        const uint32_t* qlw = (const uint32_t*)g_ql
            + (((size_t)(b * H_ + h)) * T_ + q0 + wbase + g) * 32;
        #pragma unroll
        for (int s = 0; s < 4; s++) {
            int o = s * 8 + t;
            qh[s][0] = qhw[o];           qh[s][1] = qhw[8 * 32 + o];
            qh[s][2] = qhw[o + 4];       qh[s][3] = qhw[8 * 32 + o + 4];
            ql[s][0] = qlw[o];           ql[s][1] = qlw[8 * 32 + o];
            ql[s][2] = qlw[o + 4];       ql[s][3] = qlw[8 * 32 + o + 4];
        }
    }

    float m0 = -1e30f, m1 = -1e30f, l0 = 0.f, l1 = 0.f;
    float oacc[8][4];
    #pragma unroll
    for (int nt = 0; nt < 8; nt++)
        #pragma unroll
        for (int i = 0; i < 4; i++) oacc[nt][i] = 0.f;

    const int nkt = 2 * bx + 2;

    // gmem tile bases (uint4 units)
    const uint4* kh4 = (const uint4*)g_kh  + ((size_t)(b * H_ + h) * T_) * 8;   // 8 uint4/key-row
    const uint4* kl4 = (const uint4*)g_kl  + ((size_t)(b * H_ + h) * T_) * 8;
    const uint4* vh4 = (const uint4*)g_vth + ((size_t)(b * H_ + h) * DH) * (T_ / 8); // 256 uint4/dh-row
    const uint4* vl4 = (const uint4*)g_vtl + ((size_t)(b * H_ + h) * DH) * (T_ / 8);

    const int ldr = tid >> 3;   // 0..31 (row, +32)
    const int ldc = tid & 7;    // uint4 chunk within 32-word row

    uint4 pkh[2], pkl[2], pvh[2], pvl[2];
    #pragma unroll
    for (int i = 0; i < 2; i++) {
        int r = ldr + i * 32;
        pkh[i] = kh4[(size_t)r * 8 + ldc];
        pkl[i] = kl4[(size_t)r * 8 + ldc];
        pvh[i] = vh4[(size_t)r * 256 + ldc];
        pvl[i] = vl4[(size_t)r * 256 + ldc];
    }

    const int qw_min = q0 + wbase;
    const int qw_max = q0 + wbase + 15;

    for (int kt = 0; kt < nkt; kt++) {
        const int ktb = kt * 64;

        __syncthreads();
        #pragma unroll
        for (int i = 0; i < 2; i++) {
            int wo = (ldr + i * 32) * ASTW + ldc * 4;
            *(uint4*)(Khw + wo) = pkh[i];
            *(uint4*)(Klw + wo) = pkl[i];
            *(uint4*)(Vhw + wo) = pvh[i];
            *(uint4*)(Vlw + wo) = pvl[i];
        }
        __syncthreads();

        // prefetch next tile
        if (kt + 1 < nkt) {
            int kb = ktb + 64;
            #pragma unroll
            for (int i = 0; i < 2; i++) {
                int r = ldr + i * 32;
                pkh[i] = kh4[(size_t)(kb + r) * 8 + ldc];
                pkl[i] = kl4[(size_t)(kb + r) * 8 + ldc];
                pvh[i] = vh4[(size_t)r * 256 + (kb >> 3) + ldc];
                pvl[i] = vl4[(size_t)r * 256 + (kb >> 3) + ldc];
            }
        }

        if (ktb > qw_max) continue;   // fully masked for this warp

        // ---- S = Q K^T (3-pass fp16 split) ----
        float sacc[8][4];
        #pragma unroll
        for (int nt = 0; nt < 8; nt++)
            #pragma unroll
            for (int i = 0; i < 4; i++) sacc[nt][i] = 0.f;

        #pragma unroll
        for (int s = 0; s < 4; s++) {
            #pragma unroll
            for (int nt = 0; nt < 8; nt++) {
                int o = (nt * 8 + g) * ASTW + s * 8 + t;
                uint32_t bh2[2] = { Khw[o], Khw[o + 4] };
                uint32_t bl2[2] = { Klw[o], Klw[o + 4] };
                mma16816(sacc[nt], qh[s], bh2);
                mma16816(sacc[nt], qh[s], bl2);
                mma16816(sacc[nt], ql[s], bh2);
            }
        }

        // ---- causal mask (diagonal tiles only) ----
        if (ktb + 63 > qw_min) {
            int qr0 = qw_min + g, qr1 = qr0 + 8;
            #pragma unroll
            for (int nt = 0; nt < 8; nt++) {
                int kc0 = ktb + nt * 8 + 2 * t;
                if (kc0     > qr0) sacc[nt][0] = -1e30f;
                if (kc0 + 1 > qr0) sacc[nt][1] = -1e30f;
                if (kc0     > qr1) sacc[nt][2] = -1e30f;
                if (kc0 + 1 > qr1) sacc[nt][3] = -1e30f;
            }
        }

        // ---- online softmax ----
        float mx0 = -1e30f, mx1 = -1e30f;
        #pragma unroll
        for (int nt = 0; nt < 8; nt++) {
            mx0 = fmaxf(mx0, fmaxf(sacc[nt][0], sacc[nt][1]));
            mx1 = fmaxf(mx1, fmaxf(sacc[nt][2], sacc[nt][3]));
        }
        mx0 = fmaxf(mx0, __shfl_xor_sync(0xffffffffu, mx0, 1));
        mx0 = fmaxf(mx0, __shfl_xor_sync(0xffffffffu, mx0, 2));
        mx1 = fmaxf(mx1, __shfl_xor_sync(0xffffffffu, mx1, 1));
        mx1 = fmaxf(mx1, __shfl_xor_sync(0xffffffffu, mx1, 2));

        float mn0 = fmaxf(m0, mx0), mn1 = fmaxf(m1, mx1);
        float c0 = __expf(m0 - mn0), c1 = __expf(m1 - mn1);
        m0 = mn0; m1 = mn1;

        float s0 = 0.f, s1 = 0.f;
        #pragma unroll
        for (int nt = 0; nt < 8; nt++) {
            sacc[nt][0] = __expf(sacc[nt][0] - mn0);
            sacc[nt][1] = __expf(sacc[nt][1] - mn0);
            sacc[nt][2] = __expf(sacc[nt][2] - mn1);
            sacc[nt][3] = __expf(sacc[nt][3] - mn1);
            s0 += sacc[nt][0] + sacc[nt][1];
            s1 += sacc[nt][2] + sacc[nt][3];
        }
        s0 += __shfl_xor_sync(0xffffffffu, s0, 1);
        s0 += __shfl_xor_sync(0xffffffffu, s0, 2);
        s1 += __shfl_xor_sync(0xffffffffu, s1, 1);
        s1 += __shfl_xor_sync(0xffffffffu, s1, 2);
        l0 = l0 * c0 + s0;
        l1 = l1 * c1 + s1;

        #pragma unroll
        for (int nt = 0; nt < 8; nt++) {
            oacc[nt][0] *= c0; oacc[nt][1] *= c0;
            oacc[nt][2] *= c1; oacc[nt][3] *= c1;
        }

        // ---- O += P V (P fp16 single-pass; V hi/lo 2-pass) ----
        #pragma unroll
        for (int s = 0; s < 4; s++) {
            uint32_t pa[4];
            pa[0] = pack_h2(sacc[2*s][0],     sacc[2*s][1]);
            pa[1] = pack_h2(sacc[2*s][2],     sacc[2*s][3]);
            pa[2] = pack_h2(sacc[2*s + 1][0], sacc[2*s + 1][1]);
            pa[3] = pack_h2(sacc[2*s + 1][2], sacc[2*s + 1][3]);
            #pragma unroll
            for (int nt2 = 0; nt2 < 8; nt2++) {
                int o = (nt2 * 8 + g) * ASTW + s * 8 + t;
                uint32_t vh2[2] = { Vhw[o], Vhw[o + 4] };
                uint32_t vl2[2] = { Vlw[o], Vlw[o + 4] };
                mma16816(oacc[nt2], pa, vh2);
                mma16816(oacc[nt2], pa, vl2);
            }
        }
    }

    // ---- finalize: write O as half hi/lo (feeds O-proj GEMM) ----
    float il0 = 1.0f / l0, il1 = 1.0f / l1;
    size_t row0 = (size_t)(b * T_ + q0 + wbase + g);
    uint32_t* ohw = (uint32_t*)g_oh;
    uint32_t* olw = (uint32_t*)g_ol;
    const int colw0 = (h * DH) >> 1;     // head column offset in words
    #pragma unroll
    for (int nt2 = 0; nt2 < 8; nt2++) {
        int w = colw0 + nt2 * 4 + t;
        uint32_t hw, lw;
        split_h2(oacc[nt2][0] * il0, oacc[nt2][1] * il0, hw, lw);
        ohw[row0 * 1024 + w] = hw;
        olw[row0 * 1024 + w] = lw;
        split_h2(oacc[nt2][2] * il1, oacc[nt2][3] * il1, hw, lw);
        ohw[(row0 + 8) * 1024 + w] = hw;
        olw[(row0 + 8) * 1024 + w] = lw;
    }
}

// ---------------------------------------------------------------------------
// Launch: hidden_states, shared_k, shared_v, Wq, Wo -> out (float32 [B,T,Dm])
// ---------------------------------------------------------------------------
extern "C" void kernel_launch(void* const* d_in, const int* in_sizes, int n_in,
                              void* d_out, int out_size) {
    const float* hidden = (const float*)d_in[0];
    const float* Kin    = (const float*)d_in[1];
    const float* Vin    = (const float*)d_in[2];
    const float* Wq     = (const float*)d_in[3];
    const float* Wo     = (const float*)d_in[4];
    float* out          = (float*)d_out;

    cudaFuncSetAttribute(gemm_h_kernel<0>,
                         cudaFuncAttributeMaxDynamicSharedMemorySize, SMEM_G_BYTES);
    cudaFuncSetAttribute(gemm_h_kernel<1>,
                         cudaFuncAttributeMaxDynamicSharedMemorySize, SMEM_G_BYTES);
    cudaFuncSetAttribute(attn_mma_kernel,
                         cudaFuncAttributeMaxDynamicSharedMemorySize, SMEM_A_BYTES);

    rope_table_kernel<<<(T_ * (DH/2) + 255) / 256, 256>>>();
    split_f32_kernel<0><<<M_ * DM / 512, 256>>>(hidden);   // 16384 blocks
    split_f32_kernel<1><<<DM * DM / 512, 256>>>(Wq);       // 8192
    split_f32_kernel<2><<<DM * DM / 512, 256>>>(Wo);
    prep_k_kernel<<<B_ * H_ * T_ * 32 / 256, 256>>>(Kin);  // 16384
    prep_v_kernel<<<dim3(T_ / 64, H_, B_), 256>>>(Vin);

    dim3 gGemm(DM / 128, M_ / 128);   // (16, 32)
    gemm_h_kernel<0><<<gGemm, 256, SMEM_G_BYTES>>>(nullptr);

    dim3 gAttn(T_ / 128, H_, B_);     // (16, 32, 2)
    attn_mma_kernel<<<gAttn, 256, SMEM_A_BYTES>>>();

    gemm_h_kernel<1><<<gGemm, 256, SMEM_G_BYTES>>>(out);
}

// round 9
// speedup vs baseline: 3.4135x; 1.1043x over previous
#include <cuda_runtime.h>
#include <cuda_fp16.h>
#include <math.h>
#include <stdint.h>

// Problem constants
#define B_  2
#define T_  2048
#define DM  2048
#define H_  32
#define DH  64
#define M_  (B_*T_)   // 4096

// ---------------------------------------------------------------------------
// Half hi/lo scratch (device globals: allocation-free per harness rules)
// ---------------------------------------------------------------------------
__device__ __half g_ah[(size_t)M_*DM],  g_al[(size_t)M_*DM];     // split hidden
__device__ __half g_wqh[(size_t)DM*DM], g_wql[(size_t)DM*DM];    // split Wq
__device__ __half g_woh[(size_t)DM*DM], g_wol[(size_t)DM*DM];    // split Wo
__device__ __half g_qh[(size_t)B_*H_*T_*DH], g_ql[(size_t)B_*H_*T_*DH];   // rope'd+scaled Q
__device__ __half g_kh[(size_t)B_*H_*T_*DH];                     // K hi [B,H,T,Dh]
__device__ __half g_vth[(size_t)B_*H_*T_*DH];                    // V^T hi [B,H,Dh,T]
__device__ __half g_oh[(size_t)M_*DM],  g_ol[(size_t)M_*DM];     // attention out
__device__ float g_cos[T_*(DH/2)];
__device__ float g_sin[T_*(DH/2)];

// ---------------------------------------------------------------------------
// helpers
// ---------------------------------------------------------------------------
__device__ __forceinline__ uint32_t pack_h2(float a, float b) {
    __half2 h = __floats2half2_rn(a, b);
    return *(uint32_t*)&h;
}
__device__ __forceinline__ void split_h2(float x, float y, uint32_t& h, uint32_t& l) {
    __half2 hh = __floats2half2_rn(x, y);
    float2 f = __half22float2(hh);
    __half2 ll = __floats2half2_rn(x - f.x, y - f.y);
    h = *(uint32_t*)&hh;
    l = *(uint32_t*)&ll;
}
__device__ __forceinline__ void mma16816(float* d, const uint32_t* a, const uint32_t* b) {
    asm volatile(
        "mma.sync.aligned.m16n8k16.row.col.f32.f16.f16.f32 "
        "{%0,%1,%2,%3}, {%4,%5,%6,%7}, {%8,%9}, {%0,%1,%2,%3};"
        : "+f"(d[0]), "+f"(d[1]), "+f"(d[2]), "+f"(d[3])
        : "r"(a[0]), "r"(a[1]), "r"(a[2]), "r"(a[3]), "r"(b[0]), "r"(b[1]));
}

// ---------------------------------------------------------------------------
// RoPE table
// ---------------------------------------------------------------------------
__global__ void rope_table_kernel() {
    int idx = blockIdx.x * blockDim.x + threadIdx.x;
    if (idx >= T_ * (DH/2)) return;
    int t = idx >> 5;
    int i = idx & 31;
    double inv = pow(10000.0, -((double)(2 * i)) / 64.0);
    double ang = (double)t * inv;
    g_cos[idx] = (float)cos(ang);
    g_sin[idx] = (float)sin(ang);
}

// ---------------------------------------------------------------------------
// Elementwise fp32 -> half hi/lo split.  WHICH: 0=hidden, 1=Wq, 2=Wo
// ---------------------------------------------------------------------------
template<int WHICH>
__global__ void split_f32_kernel(const float* __restrict__ in) {
    size_t i = (size_t)blockIdx.x * 256 + threadIdx.x;
    float2 v = ((const float2*)in)[i];
    uint32_t h, l;
    split_h2(v.x, v.y, h, l);
    uint32_t* hw = (uint32_t*)(WHICH == 0 ? g_ah : WHICH == 1 ? g_wqh : g_woh);
    uint32_t* lw = (uint32_t*)(WHICH == 0 ? g_al : WHICH == 1 ? g_wql : g_wol);
    hw[i] = h;
    lw[i] = l;
}

// ---------------------------------------------------------------------------
// K prep: [B,T,H,Dh] fp32 -> [B,H,T,Dh] half (hi only).
// ---------------------------------------------------------------------------
__global__ void prep_k_kernel(const float* __restrict__ Kg) {
    uint32_t w = blockIdx.x * 256 + threadIdx.x;     // < B*H*T*32
    int dh2 = w & 31;
    int tok = (w >> 5) & (T_ - 1);
    int h   = (w >> 16) & (H_ - 1);
    int b   = (int)(w >> 21);
    float2 v = ((const float2*)Kg)[(((size_t)(b * T_ + tok)) * H_ + h) * 32 + dh2];
    ((uint32_t*)g_kh)[w] = pack_h2(v.x, v.y);
}

// ---------------------------------------------------------------------------
// V prep: [B,T,H,Dh] fp32 -> transposed [B,H,Dh,T] half (hi only).
// ---------------------------------------------------------------------------
__global__ void prep_v_kernel(const float* __restrict__ Vg) {
    __shared__ float stg[64 * 65];
    const int tid = threadIdx.x;
    const int kt  = blockIdx.x, h = blockIdx.y, b = blockIdx.z;
    const float* src = Vg + ((size_t)(b * T_ + kt * 64) * H_ + h) * DH;

    #pragma unroll
    for (int i = 0; i < 4; i++) {
        int chunk = i * 256 + tid;            // 64 rows x 16 float4
        int r = chunk >> 4, c4 = chunk & 15;
        float4 v = *(const float4*)(src + (size_t)r * (H_ * DH) + c4 * 4);
        float* d = stg + r * 65 + c4 * 4;
        d[0] = v.x; d[1] = v.y; d[2] = v.z; d[3] = v.w;
    }
    __syncthreads();

    const int kp = tid & 31, dhg = tid >> 5;
    #pragma unroll
    for (int i = 0; i < 8; i++) {
        int dh = dhg * 8 + i;
        float v0 = stg[(2 * kp)     * 65 + dh];
        float v1 = stg[(2 * kp + 1) * 65 + dh];
        size_t idx = ((size_t)(b * H_ + h) * DH + dh) * (T_ / 2) + kt * 32 + kp;
        ((uint32_t*)g_vth)[idx] = pack_h2(v0, v1);
    }
}

// ---------------------------------------------------------------------------
// Split-FP16 GEMM on preconverted operands (3-pass, unchanged): C = A @ W^T.
// ---------------------------------------------------------------------------
#define GSTW 28
#define GT_W (128*GSTW)
#define SMEM_G_BYTES (4*GT_W*4)         // 57344 B

template<int MODE>
__global__ __launch_bounds__(256)
void gemm_h_kernel(float* __restrict__ C) {
    extern __shared__ uint32_t smw[];
    uint32_t* Ah = smw;
    uint32_t* Al = smw + GT_W;
    uint32_t* Bh = smw + 2*GT_W;
    uint32_t* Bl = smw + 3*GT_W;

    const uint4* Agh = (const uint4*)(MODE == 0 ? g_ah  : g_oh);
    const uint4* Agl = (const uint4*)(MODE == 0 ? g_al  : g_ol);
    const uint4* Bgh = (const uint4*)(MODE == 0 ? g_wqh : g_woh);
    const uint4* Bgl = (const uint4*)(MODE == 0 ? g_wql : g_wol);

    const int tid   = threadIdx.x;
    const int wid   = tid >> 5;
    const int lane  = tid & 31;
    const int g     = lane >> 2;
    const int t     = lane & 3;
    const int warpR = wid >> 2;
    const int warpC = wid & 3;
    const int rowBase = blockIdx.y * 128;
    const int colBase = blockIdx.x * 128;

    float acc[4][4][4];
    #pragma unroll
    for (int mt = 0; mt < 4; mt++)
        #pragma unroll
        for (int nt = 0; nt < 4; nt++)
            #pragma unroll
            for (int i = 0; i < 4; i++) acc[mt][nt][i] = 0.f;

    const int lr2 = tid >> 2;   // 0..63
    const int lc2 = tid & 3;    // 0..3

    for (int kt = 0; kt < 64; kt++) {
        uint4 rah[2], ral[2], rbh[2], rbl[2];
        #pragma unroll
        for (int i = 0; i < 2; i++) {
            int r = lr2 + i * 64;
            size_t ai = ((size_t)(rowBase + r)) * 256 + kt * 4 + lc2;
            size_t bi = ((size_t)(colBase + r)) * 256 + kt * 4 + lc2;
            rah[i] = Agh[ai]; ral[i] = Agl[ai];
            rbh[i] = Bgh[bi]; rbl[i] = Bgl[bi];
        }

        __syncthreads();
        #pragma unroll
        for (int i = 0; i < 2; i++) {
            int wo = (lr2 + i * 64) * GSTW + lc2 * 4;
            *(uint4*)(Ah + wo) = rah[i];
            *(uint4*)(Al + wo) = ral[i];
            *(uint4*)(Bh + wo) = rbh[i];
            *(uint4*)(Bl + wo) = rbl[i];
        }
        __syncthreads();

        #pragma unroll
        for (int ks = 0; ks < 2; ks++) {
            uint32_t ah[4][4], al4[4][4], bh[4][2], bl4[4][2];
            #pragma unroll
            for (int mt = 0; mt < 4; mt++) {
                int r0 = (warpR * 64 + mt * 16 + g) * GSTW + ks * 8 + t;
                int r1 = r0 + 8 * GSTW;
                ah[mt][0] = Ah[r0];     ah[mt][1] = Ah[r1];
                ah[mt][2] = Ah[r0 + 4]; ah[mt][3] = Ah[r1 + 4];
                al4[mt][0] = Al[r0];     al4[mt][1] = Al[r1];
                al4[mt][2] = Al[r0 + 4]; al4[mt][3] = Al[r1 + 4];
            }
            #pragma unroll
            for (int nt = 0; nt < 4; nt++) {
                int o = (warpC * 32 + nt * 8 + g) * GSTW + ks * 8 + t;
                bh[nt][0] = Bh[o]; bh[nt][1] = Bh[o + 4];
                bl4[nt][0] = Bl[o]; bl4[nt][1] = Bl[o + 4];
            }
            #pragma unroll
            for (int mt = 0; mt < 4; mt++)
                #pragma unroll
                for (int nt = 0; nt < 4; nt++) {
                    mma16816(acc[mt][nt], ah[mt], bh[nt]);
                    mma16816(acc[mt][nt], ah[mt], bl4[nt]);
                    mma16816(acc[mt][nt], al4[mt], bh[nt]);
                }
        }
    }

    #pragma unroll
    for (int mt = 0; mt < 4; mt++) {
        #pragma unroll
        for (int nt = 0; nt < 4; nt++) {
            int m0 = rowBase + warpR * 64 + mt * 16 + g;
            int n  = colBase + warpC * 32 + nt * 8 + 2 * t;
            if (MODE == 0) {
                int hh = n >> 6;
                int d  = n & 63;   // even
                #pragma unroll
                for (int half = 0; half < 2; half++) {
                    int m = m0 + half * 8;
                    float x1 = acc[mt][nt][half * 2];
                    float x2 = acc[mt][nt][half * 2 + 1];
                    int bb = m >> 11;
                    int tt = m & (T_ - 1);
                    float c = g_cos[tt * 32 + (d >> 1)];
                    float s = g_sin[tt * 32 + (d >> 1)];
                    float xr1 = (x1 * c - x2 * s) * 0.125f;
                    float xr2 = (x1 * s + x2 * c) * 0.125f;
                    uint32_t hw, lw;
                    split_h2(xr1, xr2, hw, lw);
                    size_t idx = ((size_t)(bb * H_ + hh) * T_ + tt) * 32 + (d >> 1);
                    ((uint32_t*)g_qh)[idx] = hw;
                    ((uint32_t*)g_ql)[idx] = lw;
                }
            } else {
                float2 v0 = make_float2(acc[mt][nt][0], acc[mt][nt][1]);
                float2 v1 = make_float2(acc[mt][nt][2], acc[mt][nt][3]);
                *(float2*)(C + (size_t)m0 * DM + n)       = v0;
                *(float2*)(C + (size_t)(m0 + 8) * DM + n) = v1;
            }
        }
    }
}

// ---------------------------------------------------------------------------
// FP16 flash attention: 2-pass S (qh+ql vs K hi), 1-pass PV (V hi).
// Block = (b, h, 128-row Q tile). 256 threads, 8 warps x 16 rows.
// Smem: Khw + Vhw only, stride 44 words. 22528 B.
// ---------------------------------------------------------------------------
#define ASTW 44
#define AT_W (64*ASTW)                  // 2816 words / buffer
#define SMEM_A_BYTES (2*AT_W*4)         // 22528 B

__global__ __launch_bounds__(256)
void attn_mma_kernel() {
    extern __shared__ uint32_t smw[];
    uint32_t* Khw = smw;
    uint32_t* Vhw = smw + AT_W;

    const int tid  = threadIdx.x;
    const int wid  = tid >> 5;
    const int lane = tid & 31;
    const int g    = lane >> 2;
    const int t    = lane & 3;
    const int bx   = (int)gridDim.x - 1 - (int)blockIdx.x;   // heavy blocks first
    const int h    = blockIdx.y;
    const int b    = blockIdx.z;
    const int q0   = bx * 128;
    const int wbase = wid * 16;

    // ---- Q A-frags direct from gmem (pre-rope'd, pre-scaled, pre-split) ----
    uint32_t qh[4][4], ql[4][4];
    {
        const uint32_t* qhw = (const uint32_t*)g_qh
            + (((size_t)(b * H_ + h)) * T_ + q0 + wbase + g) * 32;
        const uint32_t* qlw = (const uint32_t*)g_ql
            + (((size_t)(b * H_ + h)) * T_ + q0 + wbase + g) * 32;
        #pragma unroll
        for (int s = 0; s < 4; s++) {
            int o = s * 8 + t;
            qh[s][0] = qhw[o];           qh[s][1] = qhw[8 * 32 + o];
            qh[s][2] = qhw[o + 4];       qh[s][3] = qhw[8 * 32 + o + 4];
            ql[s][0] = qlw[o];           ql[s][1] = qlw[8 * 32 + o];
            ql[s][2] = qlw[o + 4];       ql[s][3] = qlw[8 * 32 + o + 4];
        }
    }

    float m0 = -1e30f, m1 = -1e30f, l0 = 0.f, l1 = 0.f;
    float oacc[8][4];
    #pragma unroll
    for (int nt = 0; nt < 8; nt++)
        #pragma unroll
        for (int i = 0; i < 4; i++) oacc[nt][i] = 0.f;

    const int nkt = 2 * bx + 2;

    const uint4* kh4 = (const uint4*)g_kh  + ((size_t)(b * H_ + h) * T_) * 8;
    const uint4* vh4 = (const uint4*)g_vth + ((size_t)(b * H_ + h) * DH) * (T_ / 8);

    const int ldr = tid >> 3;   // 0..31 (row, +32)
    const int ldc = tid & 7;    // uint4 chunk within 32-word row

    uint4 pkh[2], pvh[2];
    #pragma unroll
    for (int i = 0; i < 2; i++) {
        int r = ldr + i * 32;
        pkh[i] = kh4[(size_t)r * 8 + ldc];
        pvh[i] = vh4[(size_t)r * 256 + ldc];
    }

    const int qw_min = q0 + wbase;
    const int qw_max = q0 + wbase + 15;

    for (int kt = 0; kt < nkt; kt++) {
        const int ktb = kt * 64;

        __syncthreads();
        #pragma unroll
        for (int i = 0; i < 2; i++) {
            int wo = (ldr + i * 32) * ASTW + ldc * 4;
            *(uint4*)(Khw + wo) = pkh[i];
            *(uint4*)(Vhw + wo) = pvh[i];
        }
        __syncthreads();

        // prefetch next tile
        if (kt + 1 < nkt) {
            int kb = ktb + 64;
            #pragma unroll
            for (int i = 0; i < 2; i++) {
                int r = ldr + i * 32;
                pkh[i] = kh4[(size_t)(kb + r) * 8 + ldc];
                pvh[i] = vh4[(size_t)r * 256 + (kb >> 3) + ldc];
            }
        }

        if (ktb > qw_max) continue;   // fully masked for this warp

        // ---- S = Q K^T (2-pass: qh*kh + ql*kh) ----
        float sacc[8][4];
        #pragma unroll
        for (int nt = 0; nt < 8; nt++)
            #pragma unroll
            for (int i = 0; i < 4; i++) sacc[nt][i] = 0.f;

        #pragma unroll
        for (int s = 0; s < 4; s++) {
            #pragma unroll
            for (int nt = 0; nt < 8; nt++) {
                int o = (nt * 8 + g) * ASTW + s * 8 + t;
                uint32_t bh2[2] = { Khw[o], Khw[o + 4] };
                mma16816(sacc[nt], qh[s], bh2);
                mma16816(sacc[nt], ql[s], bh2);
            }
        }

        // ---- causal mask (diagonal tiles only) ----
        if (ktb + 63 > qw_min) {
            int qr0 = qw_min + g, qr1 = qr0 + 8;
            #pragma unroll
            for (int nt = 0; nt < 8; nt++) {
                int kc0 = ktb + nt * 8 + 2 * t;
                if (kc0     > qr0) sacc[nt][0] = -1e30f;
                if (kc0 + 1 > qr0) sacc[nt][1] = -1e30f;
                if (kc0     > qr1) sacc[nt][2] = -1e30f;
                if (kc0 + 1 > qr1) sacc[nt][3] = -1e30f;
            }
        }

        // ---- online softmax ----
        float mx0 = -1e30f, mx1 = -1e30f;
        #pragma unroll
        for (int nt = 0; nt < 8; nt++) {
            mx0 = fmaxf(mx0, fmaxf(sacc[nt][0], sacc[nt][1]));
            mx1 = fmaxf(mx1, fmaxf(sacc[nt][2], sacc[nt][3]));
        }
        mx0 = fmaxf(mx0, __shfl_xor_sync(0xffffffffu, mx0, 1));
        mx0 = fmaxf(mx0, __shfl_xor_sync(0xffffffffu, mx0, 2));
        mx1 = fmaxf(mx1, __shfl_xor_sync(0xffffffffu, mx1, 1));
        mx1 = fmaxf(mx1, __shfl_xor_sync(0xffffffffu, mx1, 2));

        float mn0 = fmaxf(m0, mx0), mn1 = fmaxf(m1, mx1);
        float c0 = __expf(m0 - mn0), c1 = __expf(m1 - mn1);
        m0 = mn0; m1 = mn1;

        float s0 = 0.f, s1 = 0.f;
        #pragma unroll
        for (int nt = 0; nt < 8; nt++) {
            sacc[nt][0] = __expf(sacc[nt][0] - mn0);
            sacc[nt][1] = __expf(sacc[nt][1] - mn0);
            sacc[nt][2] = __expf(sacc[nt][2] - mn1);
            sacc[nt][3] = __expf(sacc[nt][3] - mn1);
            s0 += sacc[nt][0] + sacc[nt][1];
            s1 += sacc[nt][2] + sacc[nt][3];
        }
        s0 += __shfl_xor_sync(0xffffffffu, s0, 1);
        s0 += __shfl_xor_sync(0xffffffffu, s0, 2);
        s1 += __shfl_xor_sync(0xffffffffu, s1, 1);
        s1 += __shfl_xor_sync(0xffffffffu, s1, 2);
        l0 = l0 * c0 + s0;
        l1 = l1 * c1 + s1;

        #pragma unroll
        for (int nt = 0; nt < 8; nt++) {
            oacc[nt][0] *= c0; oacc[nt][1] *= c0;
            oacc[nt][2] *= c1; oacc[nt][3] *= c1;
        }

        // ---- O += P V (P fp16, V hi single-pass) ----
        #pragma unroll
        for (int s = 0; s < 4; s++) {
            uint32_t pa[4];
            pa[0] = pack_h2(sacc[2*s][0],     sacc[2*s][1]);
            pa[1] = pack_h2(sacc[2*s][2],     sacc[2*s][3]);
            pa[2] = pack_h2(sacc[2*s + 1][0], sacc[2*s + 1][1]);
            pa[3] = pack_h2(sacc[2*s + 1][2], sacc[2*s + 1][3]);
            #pragma unroll
            for (int nt2 = 0; nt2 < 8; nt2++) {
                int o = (nt2 * 8 + g) * ASTW + s * 8 + t;
                uint32_t vh2[2] = { Vhw[o], Vhw[o + 4] };
                mma16816(oacc[nt2], pa, vh2);
            }
        }
    }

    // ---- finalize: write O as half hi/lo (feeds O-proj GEMM) ----
    float il0 = 1.0f / l0, il1 = 1.0f / l1;
    size_t row0 = (size_t)(b * T_ + q0 + wbase + g);
    uint32_t* ohw = (uint32_t*)g_oh;
    uint32_t* olw = (uint32_t*)g_ol;
    const int colw0 = (h * DH) >> 1;
    #pragma unroll
    for (int nt2 = 0; nt2 < 8; nt2++) {
        int w = colw0 + nt2 * 4 + t;
        uint32_t hw, lw;
        split_h2(oacc[nt2][0] * il0, oacc[nt2][1] * il0, hw, lw);
        ohw[row0 * 1024 + w] = hw;
        olw[row0 * 1024 + w] = lw;
        split_h2(oacc[nt2][2] * il1, oacc[nt2][3] * il1, hw, lw);
        ohw[(row0 + 8) * 1024 + w] = hw;
        olw[(row0 + 8) * 1024 + w] = lw;
    }
}

// ---------------------------------------------------------------------------
// Launch: hidden_states, shared_k, shared_v, Wq, Wo -> out (float32 [B,T,Dm])
// ---------------------------------------------------------------------------
extern "C" void kernel_launch(void* const* d_in, const int* in_sizes, int n_in,
                              void* d_out, int out_size) {
    const float* hidden = (const float*)d_in[0];
    const float* Kin    = (const float*)d_in[1];
    const float* Vin    = (const float*)d_in[2];
    const float* Wq     = (const float*)d_in[3];
    const float* Wo     = (const float*)d_in[4];
    float* out          = (float*)d_out;

    cudaFuncSetAttribute(gemm_h_kernel<0>,
                         cudaFuncAttributeMaxDynamicSharedMemorySize, SMEM_G_BYTES);
    cudaFuncSetAttribute(gemm_h_kernel<1>,
                         cudaFuncAttributeMaxDynamicSharedMemorySize, SMEM_G_BYTES);
    cudaFuncSetAttribute(attn_mma_kernel,
                         cudaFuncAttributeMaxDynamicSharedMemorySize, SMEM_A_BYTES);

    rope_table_kernel<<<(T_ * (DH/2) + 255) / 256, 256>>>();
    split_f32_kernel<0><<<M_ * DM / 512, 256>>>(hidden);
    split_f32_kernel<1><<<DM * DM / 512, 256>>>(Wq);
    split_f32_kernel<2><<<DM * DM / 512, 256>>>(Wo);
    prep_k_kernel<<<B_ * H_ * T_ * 32 / 256, 256>>>(Kin);
    prep_v_kernel<<<dim3(T_ / 64, H_, B_), 256>>>(Vin);

    dim3 gGemm(DM / 128, M_ / 128);   // (16, 32)
    gemm_h_kernel<0><<<gGemm, 256, SMEM_G_BYTES>>>(nullptr);

    dim3 gAttn(T_ / 128, H_, B_);     // (16, 32, 2)
    attn_mma_kernel<<<gAttn, 256, SMEM_A_BYTES>>>();

    gemm_h_kernel<1><<<gGemm, 256, SMEM_G_BYTES>>>(out);
}

// round 10
// speedup vs baseline: 3.5837x; 1.0498x over previous
#include <cuda_runtime.h>
#include <cuda_fp16.h>
#include <math.h>
#include <stdint.h>

// Problem constants
#define B_  2
#define T_  2048
#define DM  2048
#define H_  32
#define DH  64
#define M_  (B_*T_)   // 4096

// ---------------------------------------------------------------------------
// Half hi/lo scratch (device globals: allocation-free per harness rules)
// ---------------------------------------------------------------------------
__device__ __half g_ah[(size_t)M_*DM],  g_al[(size_t)M_*DM];     // split hidden
__device__ __half g_wqh[(size_t)DM*DM], g_wql[(size_t)DM*DM];    // split Wq
__device__ __half g_woh[(size_t)DM*DM], g_wol[(size_t)DM*DM];    // split Wo
__device__ __half g_qh[(size_t)B_*H_*T_*DH], g_ql[(size_t)B_*H_*T_*DH];   // rope'd+scaled Q
__device__ __half g_kh[(size_t)B_*H_*T_*DH];                     // K hi [B,H,T,Dh]
__device__ __half g_vth[(size_t)B_*H_*T_*DH];                    // V^T hi [B,H,Dh,T]
__device__ __half g_oh[(size_t)M_*DM],  g_ol[(size_t)M_*DM];     // attention out
__device__ float g_cos[T_*(DH/2)];
__device__ float g_sin[T_*(DH/2)];

// ---------------------------------------------------------------------------
// helpers
// ---------------------------------------------------------------------------
__device__ __forceinline__ uint32_t pack_h2(float a, float b) {
    __half2 h = __floats2half2_rn(a, b);
    return *(uint32_t*)&h;
}
__device__ __forceinline__ void split_h2(float x, float y, uint32_t& h, uint32_t& l) {
    __half2 hh = __floats2half2_rn(x, y);
    float2 f = __half22float2(hh);
    __half2 ll = __floats2half2_rn(x - f.x, y - f.y);
    h = *(uint32_t*)&hh;
    l = *(uint32_t*)&ll;
}
__device__ __forceinline__ void mma16816(float* d, const uint32_t* a, const uint32_t* b) {
    asm volatile(
        "mma.sync.aligned.m16n8k16.row.col.f32.f16.f16.f32 "
        "{%0,%1,%2,%3}, {%4,%5,%6,%7}, {%8,%9}, {%0,%1,%2,%3};"
        : "+f"(d[0]), "+f"(d[1]), "+f"(d[2]), "+f"(d[3])
        : "r"(a[0]), "r"(a[1]), "r"(a[2]), "r"(a[3]), "r"(b[0]), "r"(b[1]));
}
__device__ __forceinline__ void ldsm_x4(uint32_t* r, uint32_t addr) {
    asm volatile(
        "ldmatrix.sync.aligned.m8n8.x4.shared.b16 {%0,%1,%2,%3}, [%4];"
        : "=r"(r[0]), "=r"(r[1]), "=r"(r[2]), "=r"(r[3]) : "r"(addr));
}

// ---------------------------------------------------------------------------
// RoPE table
// ---------------------------------------------------------------------------
__global__ void rope_table_kernel() {
    int idx = blockIdx.x * blockDim.x + threadIdx.x;
    if (idx >= T_ * (DH/2)) return;
    int t = idx >> 5;
    int i = idx & 31;
    double inv = pow(10000.0, -((double)(2 * i)) / 64.0);
    double ang = (double)t * inv;
    g_cos[idx] = (float)cos(ang);
    g_sin[idx] = (float)sin(ang);
}

// ---------------------------------------------------------------------------
// Elementwise fp32 -> half hi/lo split.  WHICH: 0=hidden, 1=Wq, 2=Wo
// ---------------------------------------------------------------------------
template<int WHICH>
__global__ void split_f32_kernel(const float* __restrict__ in) {
    size_t i = (size_t)blockIdx.x * 256 + threadIdx.x;
    float2 v = ((const float2*)in)[i];
    uint32_t h, l;
    split_h2(v.x, v.y, h, l);
    uint32_t* hw = (uint32_t*)(WHICH == 0 ? g_ah : WHICH == 1 ? g_wqh : g_woh);
    uint32_t* lw = (uint32_t*)(WHICH == 0 ? g_al : WHICH == 1 ? g_wql : g_wol);
    hw[i] = h;
    lw[i] = l;
}

// ---------------------------------------------------------------------------
// K prep: [B,T,H,Dh] fp32 -> [B,H,T,Dh] half (hi only).
// ---------------------------------------------------------------------------
__global__ void prep_k_kernel(const float* __restrict__ Kg) {
    uint32_t w = blockIdx.x * 256 + threadIdx.x;     // < B*H*T*32
    int dh2 = w & 31;
    int tok = (w >> 5) & (T_ - 1);
    int h   = (w >> 16) & (H_ - 1);
    int b   = (int)(w >> 21);
    float2 v = ((const float2*)Kg)[(((size_t)(b * T_ + tok)) * H_ + h) * 32 + dh2];
    ((uint32_t*)g_kh)[w] = pack_h2(v.x, v.y);
}

// ---------------------------------------------------------------------------
// V prep: [B,T,H,Dh] fp32 -> transposed [B,H,Dh,T] half (hi only).
// ---------------------------------------------------------------------------
__global__ void prep_v_kernel(const float* __restrict__ Vg) {
    __shared__ float stg[64 * 65];
    const int tid = threadIdx.x;
    const int kt  = blockIdx.x, h = blockIdx.y, b = blockIdx.z;
    const float* src = Vg + ((size_t)(b * T_ + kt * 64) * H_ + h) * DH;

    #pragma unroll
    for (int i = 0; i < 4; i++) {
        int chunk = i * 256 + tid;            // 64 rows x 16 float4
        int r = chunk >> 4, c4 = chunk & 15;
        float4 v = *(const float4*)(src + (size_t)r * (H_ * DH) + c4 * 4);
        float* d = stg + r * 65 + c4 * 4;
        d[0] = v.x; d[1] = v.y; d[2] = v.z; d[3] = v.w;
    }
    __syncthreads();

    const int kp = tid & 31, dhg = tid >> 5;
    #pragma unroll
    for (int i = 0; i < 8; i++) {
        int dh = dhg * 8 + i;
        float v0 = stg[(2 * kp)     * 65 + dh];
        float v1 = stg[(2 * kp + 1) * 65 + dh];
        size_t idx = ((size_t)(b * H_ + h) * DH + dh) * (T_ / 2) + kt * 32 + kp;
        ((uint32_t*)g_vth)[idx] = pack_h2(v0, v1);
    }
}

// ---------------------------------------------------------------------------
// Split-FP16 GEMM (3-pass) with ldmatrix fragment loads: C = A @ W^T.
// ---------------------------------------------------------------------------
#define GSTW 28
#define GT_W (128*GSTW)
#define SMEM_G_BYTES (4*GT_W*4)         // 57344 B

template<int MODE>
__global__ __launch_bounds__(256)
void gemm_h_kernel(float* __restrict__ C) {
    extern __shared__ uint32_t smw[];
    uint32_t* Ah = smw;
    uint32_t* Al = smw + GT_W;
    uint32_t* Bh = smw + 2*GT_W;
    uint32_t* Bl = smw + 3*GT_W;

    const uint4* Agh = (const uint4*)(MODE == 0 ? g_ah  : g_oh);
    const uint4* Agl = (const uint4*)(MODE == 0 ? g_al  : g_ol);
    const uint4* Bgh = (const uint4*)(MODE == 0 ? g_wqh : g_woh);
    const uint4* Bgl = (const uint4*)(MODE == 0 ? g_wql : g_wol);

    const int tid   = threadIdx.x;
    const int wid   = tid >> 5;
    const int lane  = tid & 31;
    const int g     = lane >> 2;
    const int t     = lane & 3;
    const int warpR = wid >> 2;
    const int warpC = wid & 3;
    const int rowBase = blockIdx.y * 128;
    const int colBase = blockIdx.x * 128;

    // ldmatrix per-lane source row/col selectors
    const int q4 = lane >> 3;          // quad 0..3
    const int rr = lane & 7;
    const int arow = (q4 & 1) * 8 + rr;        // A: quad0/2 rows 0-7, quad1/3 rows 8-15
    const int aoff = (q4 >> 1) * 4;            //    quad0/1 k0-7, quad2/3 k8-15
    const int brow = (q4 >> 1) * 8 + rr;       // B: quad0/1 nt even, quad2/3 nt odd
    const int boff = (q4 & 1) * 4;

    const uint32_t AhS = (uint32_t)__cvta_generic_to_shared(Ah);
    const uint32_t AlS = (uint32_t)__cvta_generic_to_shared(Al);
    const uint32_t BhS = (uint32_t)__cvta_generic_to_shared(Bh);
    const uint32_t BlS = (uint32_t)__cvta_generic_to_shared(Bl);

    float acc[4][4][4];
    #pragma unroll
    for (int mt = 0; mt < 4; mt++)
        #pragma unroll
        for (int nt = 0; nt < 4; nt++)
            #pragma unroll
            for (int i = 0; i < 4; i++) acc[mt][nt][i] = 0.f;

    const int lr2 = tid >> 2;   // 0..63
    const int lc2 = tid & 3;    // 0..3

    for (int kt = 0; kt < 64; kt++) {
        uint4 rah[2], ral[2], rbh[2], rbl[2];
        #pragma unroll
        for (int i = 0; i < 2; i++) {
            int r = lr2 + i * 64;
            size_t ai = ((size_t)(rowBase + r)) * 256 + kt * 4 + lc2;
            size_t bi = ((size_t)(colBase + r)) * 256 + kt * 4 + lc2;
            rah[i] = Agh[ai]; ral[i] = Agl[ai];
            rbh[i] = Bgh[bi]; rbl[i] = Bgl[bi];
        }

        __syncthreads();
        #pragma unroll
        for (int i = 0; i < 2; i++) {
            int wo = (lr2 + i * 64) * GSTW + lc2 * 4;
            *(uint4*)(Ah + wo) = rah[i];
            *(uint4*)(Al + wo) = ral[i];
            *(uint4*)(Bh + wo) = rbh[i];
            *(uint4*)(Bl + wo) = rbl[i];
        }
        __syncthreads();

        #pragma unroll
        for (int ks = 0; ks < 2; ks++) {
            uint32_t ah[4][4], al4[4][4], bh[2][4], bl4[2][4];
            #pragma unroll
            for (int mt = 0; mt < 4; mt++) {
                uint32_t ao = ((warpR * 64 + mt * 16 + arow) * GSTW + ks * 8 + aoff) * 4;
                ldsm_x4(ah[mt],  AhS + ao);
                ldsm_x4(al4[mt], AlS + ao);
            }
            #pragma unroll
            for (int p = 0; p < 2; p++) {
                uint32_t bo = ((warpC * 32 + p * 16 + brow) * GSTW + ks * 8 + boff) * 4;
                ldsm_x4(bh[p],  BhS + bo);
                ldsm_x4(bl4[p], BlS + bo);
            }
            #pragma unroll
            for (int mt = 0; mt < 4; mt++)
                #pragma unroll
                for (int nt = 0; nt < 4; nt++) {
                    const uint32_t* bhp = &bh[nt >> 1][(nt & 1) * 2];
                    const uint32_t* blp = &bl4[nt >> 1][(nt & 1) * 2];
                    mma16816(acc[mt][nt], ah[mt],  bhp);
                    mma16816(acc[mt][nt], ah[mt],  blp);
                    mma16816(acc[mt][nt], al4[mt], bhp);
                }
        }
    }

    #pragma unroll
    for (int mt = 0; mt < 4; mt++) {
        #pragma unroll
        for (int nt = 0; nt < 4; nt++) {
            int m0 = rowBase + warpR * 64 + mt * 16 + g;
            int n  = colBase + warpC * 32 + nt * 8 + 2 * t;
            if (MODE == 0) {
                int hh = n >> 6;
                int d  = n & 63;   // even
                #pragma unroll
                for (int half = 0; half < 2; half++) {
                    int m = m0 + half * 8;
                    float x1 = acc[mt][nt][half * 2];
                    float x2 = acc[mt][nt][half * 2 + 1];
                    int bb = m >> 11;
                    int tt = m & (T_ - 1);
                    float c = g_cos[tt * 32 + (d >> 1)];
                    float s = g_sin[tt * 32 + (d >> 1)];
                    float xr1 = (x1 * c - x2 * s) * 0.125f;
                    float xr2 = (x1 * s + x2 * c) * 0.125f;
                    uint32_t hw, lw;
                    split_h2(xr1, xr2, hw, lw);
                    size_t idx = ((size_t)(bb * H_ + hh) * T_ + tt) * 32 + (d >> 1);
                    ((uint32_t*)g_qh)[idx] = hw;
                    ((uint32_t*)g_ql)[idx] = lw;
                }
            } else {
                float2 v0 = make_float2(acc[mt][nt][0], acc[mt][nt][1]);
                float2 v1 = make_float2(acc[mt][nt][2], acc[mt][nt][3]);
                *(float2*)(C + (size_t)m0 * DM + n)       = v0;
                *(float2*)(C + (size_t)(m0 + 8) * DM + n) = v1;
            }
        }
    }
}

// ---------------------------------------------------------------------------
// FP16 flash attention with ldmatrix: 2-pass S, 1-pass PV.
// ---------------------------------------------------------------------------
#define ASTW 44
#define AT_W (64*ASTW)                  // 2816 words / buffer
#define SMEM_A_BYTES (2*AT_W*4)         // 22528 B

__global__ __launch_bounds__(256)
void attn_mma_kernel() {
    extern __shared__ uint32_t smw[];
    uint32_t* Khw = smw;
    uint32_t* Vhw = smw + AT_W;

    const int tid  = threadIdx.x;
    const int wid  = tid >> 5;
    const int lane = tid & 31;
    const int g    = lane >> 2;
    const int t    = lane & 3;
    const int bx   = (int)gridDim.x - 1 - (int)blockIdx.x;   // heavy blocks first
    const int h    = blockIdx.y;
    const int b    = blockIdx.z;
    const int q0   = bx * 128;
    const int wbase = wid * 16;

    const int q4 = lane >> 3;
    const int rr = lane & 7;

    const uint32_t KhS = (uint32_t)__cvta_generic_to_shared(Khw);
    const uint32_t VhS = (uint32_t)__cvta_generic_to_shared(Vhw);

    // ---- Q A-frags direct from gmem (pre-rope'd, pre-scaled, pre-split) ----
    uint32_t qh[4][4], ql[4][4];
    {
        const uint32_t* qhw = (const uint32_t*)g_qh
            + (((size_t)(b * H_ + h)) * T_ + q0 + wbase + g) * 32;
        const uint32_t* qlw = (const uint32_t*)g_ql
            + (((size_t)(b * H_ + h)) * T_ + q0 + wbase + g) * 32;
        #pragma unroll
        for (int s = 0; s < 4; s++) {
            int o = s * 8 + t;
            qh[s][0] = qhw[o];           qh[s][1] = qhw[8 * 32 + o];
            qh[s][2] = qhw[o + 4];       qh[s][3] = qhw[8 * 32 + o + 4];
            ql[s][0] = qlw[o];           ql[s][1] = qlw[8 * 32 + o];
            ql[s][2] = qlw[o + 4];       ql[s][3] = qlw[8 * 32 + o + 4];
        }
    }

    float m0 = -1e30f, m1 = -1e30f, l0 = 0.f, l1 = 0.f;
    float oacc[8][4];
    #pragma unroll
    for (int nt = 0; nt < 8; nt++)
        #pragma unroll
        for (int i = 0; i < 4; i++) oacc[nt][i] = 0.f;

    const int nkt = 2 * bx + 2;

    const uint4* kh4 = (const uint4*)g_kh  + ((size_t)(b * H_ + h) * T_) * 8;
    const uint4* vh4 = (const uint4*)g_vth + ((size_t)(b * H_ + h) * DH) * (T_ / 8);

    const int ldr = tid >> 3;   // 0..31 (row, +32)
    const int ldc = tid & 7;    // uint4 chunk within 32-word row

    uint4 pkh[2], pvh[2];
    #pragma unroll
    for (int i = 0; i < 2; i++) {
        int r = ldr + i * 32;
        pkh[i] = kh4[(size_t)r * 8 + ldc];
        pvh[i] = vh4[(size_t)r * 256 + ldc];
    }

    const int qw_min = q0 + wbase;
    const int qw_max = q0 + wbase + 15;

    for (int kt = 0; kt < nkt; kt++) {
        const int ktb = kt * 64;

        __syncthreads();
        #pragma unroll
        for (int i = 0; i < 2; i++) {
            int wo = (ldr + i * 32) * ASTW + ldc * 4;
            *(uint4*)(Khw + wo) = pkh[i];
            *(uint4*)(Vhw + wo) = pvh[i];
        }
        __syncthreads();

        // prefetch next tile
        if (kt + 1 < nkt) {
            int kb = ktb + 64;
            #pragma unroll
            for (int i = 0; i < 2; i++) {
                int r = ldr + i * 32;
                pkh[i] = kh4[(size_t)(kb + r) * 8 + ldc];
                pvh[i] = vh4[(size_t)r * 256 + (kb >> 3) + ldc];
            }
        }

        if (ktb > qw_max) continue;   // fully masked for this warp

        // ---- S = Q K^T (2-pass: qh*kh + ql*kh), ldmatrix x4 per (nt, s-pair) ----
        float sacc[8][4];
        #pragma unroll
        for (int nt = 0; nt < 8; nt++)
            #pragma unroll
            for (int i = 0; i < 4; i++) sacc[nt][i] = 0.f;

        #pragma unroll
        for (int nt = 0; nt < 8; nt++) {
            #pragma unroll
            for (int sp = 0; sp < 2; sp++) {
                uint32_t kb2[4];
                ldsm_x4(kb2, KhS + (((nt * 8 + rr) * ASTW) + sp * 16 + q4 * 4) * 4);
                mma16816(sacc[nt], qh[2 * sp],     &kb2[0]);
                mma16816(sacc[nt], ql[2 * sp],     &kb2[0]);
                mma16816(sacc[nt], qh[2 * sp + 1], &kb2[2]);
                mma16816(sacc[nt], ql[2 * sp + 1], &kb2[2]);
            }
        }

        // ---- causal mask (diagonal tiles only) ----
        if (ktb + 63 > qw_min) {
            int qr0 = qw_min + g, qr1 = qr0 + 8;
            #pragma unroll
            for (int nt = 0; nt < 8; nt++) {
                int kc0 = ktb + nt * 8 + 2 * t;
                if (kc0     > qr0) sacc[nt][0] = -1e30f;
                if (kc0 + 1 > qr0) sacc[nt][1] = -1e30f;
                if (kc0     > qr1) sacc[nt][2] = -1e30f;
                if (kc0 + 1 > qr1) sacc[nt][3] = -1e30f;
            }
        }

        // ---- online softmax ----
        float mx0 = -1e30f, mx1 = -1e30f;
        #pragma unroll
        for (int nt = 0; nt < 8; nt++) {
            mx0 = fmaxf(mx0, fmaxf(sacc[nt][0], sacc[nt][1]));
            mx1 = fmaxf(mx1, fmaxf(sacc[nt][2], sacc[nt][3]));
        }
        mx0 = fmaxf(mx0, __shfl_xor_sync(0xffffffffu, mx0, 1));
        mx0 = fmaxf(mx0, __shfl_xor_sync(0xffffffffu, mx0, 2));
        mx1 = fmaxf(mx1, __shfl_xor_sync(0xffffffffu, mx1, 1));
        mx1 = fmaxf(mx1, __shfl_xor_sync(0xffffffffu, mx1, 2));

        float mn0 = fmaxf(m0, mx0), mn1 = fmaxf(m1, mx1);
        float c0 = __expf(m0 - mn0), c1 = __expf(m1 - mn1);
        m0 = mn0; m1 = mn1;

        float s0 = 0.f, s1 = 0.f;
        #pragma unroll
        for (int nt = 0; nt < 8; nt++) {
            sacc[nt][0] = __expf(sacc[nt][0] - mn0);
            sacc[nt][1] = __expf(sacc[nt][1] - mn0);
            sacc[nt][2] = __expf(sacc[nt][2] - mn1);
            sacc[nt][3] = __expf(sacc[nt][3] - mn1);
            s0 += sacc[nt][0] + sacc[nt][1];
            s1 += sacc[nt][2] + sacc[nt][3];
        }
        s0 += __shfl_xor_sync(0xffffffffu, s0, 1);
        s0 += __shfl_xor_sync(0xffffffffu, s0, 2);
        s1 += __shfl_xor_sync(0xffffffffu, s1, 1);
        s1 += __shfl_xor_sync(0xffffffffu, s1, 2);
        l0 = l0 * c0 + s0;
        l1 = l1 * c1 + s1;

        #pragma unroll
        for (int nt = 0; nt < 8; nt++) {
            oacc[nt][0] *= c0; oacc[nt][1] *= c0;
            oacc[nt][2] *= c1; oacc[nt][3] *= c1;
        }

        // ---- O += P V (P fp16, V hi single-pass), ldmatrix for V ----
        uint32_t pa[4][4];
        #pragma unroll
        for (int s = 0; s < 4; s++) {
            pa[s][0] = pack_h2(sacc[2*s][0],     sacc[2*s][1]);
            pa[s][1] = pack_h2(sacc[2*s][2],     sacc[2*s][3]);
            pa[s][2] = pack_h2(sacc[2*s + 1][0], sacc[2*s + 1][1]);
            pa[s][3] = pack_h2(sacc[2*s + 1][2], sacc[2*s + 1][3]);
        }
        #pragma unroll
        for (int nt2 = 0; nt2 < 8; nt2++) {
            #pragma unroll
            for (int sp = 0; sp < 2; sp++) {
                uint32_t vb[4];
                ldsm_x4(vb, VhS + (((nt2 * 8 + rr) * ASTW) + sp * 16 + q4 * 4) * 4);
                mma16816(oacc[nt2], pa[2 * sp],     &vb[0]);
                mma16816(oacc[nt2], pa[2 * sp + 1], &vb[2]);
            }
        }
    }

    // ---- finalize: write O as half hi/lo (feeds O-proj GEMM) ----
    float il0 = 1.0f / l0, il1 = 1.0f / l1;
    size_t row0 = (size_t)(b * T_ + q0 + wbase + g);
    uint32_t* ohw = (uint32_t*)g_oh;
    uint32_t* olw = (uint32_t*)g_ol;
    const int colw0 = (h * DH) >> 1;
    #pragma unroll
    for (int nt2 = 0; nt2 < 8; nt2++) {
        int w = colw0 + nt2 * 4 + t;
        uint32_t hw, lw;
        split_h2(oacc[nt2][0] * il0, oacc[nt2][1] * il0, hw, lw);
        ohw[row0 * 1024 + w] = hw;
        olw[row0 * 1024 + w] = lw;
        split_h2(oacc[nt2][2] * il1, oacc[nt2][3] * il1, hw, lw);
        ohw[(row0 + 8) * 1024 + w] = hw;
        olw[(row0 + 8) * 1024 + w] = lw;
    }
}

// ---------------------------------------------------------------------------
// Launch: hidden_states, shared_k, shared_v, Wq, Wo -> out (float32 [B,T,Dm])
// ---------------------------------------------------------------------------
extern "C" void kernel_launch(void* const* d_in, const int* in_sizes, int n_in,
                              void* d_out, int out_size) {
    const float* hidden = (const float*)d_in[0];
    const float* Kin    = (const float*)d_in[1];
    const float* Vin    = (const float*)d_in[2];
    const float* Wq     = (const float*)d_in[3];
    const float* Wo     = (const float*)d_in[4];
    float* out          = (float*)d_out;

    cudaFuncSetAttribute(gemm_h_kernel<0>,
                         cudaFuncAttributeMaxDynamicSharedMemorySize, SMEM_G_BYTES);
    cudaFuncSetAttribute(gemm_h_kernel<1>,
                         cudaFuncAttributeMaxDynamicSharedMemorySize, SMEM_G_BYTES);
    cudaFuncSetAttribute(attn_mma_kernel,
                         cudaFuncAttributeMaxDynamicSharedMemorySize, SMEM_A_BYTES);

    rope_table_kernel<<<(T_ * (DH/2) + 255) / 256, 256>>>();
    split_f32_kernel<0><<<M_ * DM / 512, 256>>>(hidden);
    split_f32_kernel<1><<<DM * DM / 512, 256>>>(Wq);
    split_f32_kernel<2><<<DM * DM / 512, 256>>>(Wo);
    prep_k_kernel<<<B_ * H_ * T_ * 32 / 256, 256>>>(Kin);
    prep_v_kernel<<<dim3(T_ / 64, H_, B_), 256>>>(Vin);

    dim3 gGemm(DM / 128, M_ / 128);   // (16, 32)
    gemm_h_kernel<0><<<gGemm, 256, SMEM_G_BYTES>>>(nullptr);

    dim3 gAttn(T_ / 128, H_, B_);     // (16, 32, 2)
    attn_mma_kernel<<<gAttn, 256, SMEM_A_BYTES>>>();

    gemm_h_kernel<1><<<gGemm, 256, SMEM_G_BYTES>>>(out);
}

// round 11
// speedup vs baseline: 4.8283x; 1.3473x over previous
#include <cuda_runtime.h>
#include <cuda_fp16.h>
#include <math.h>
#include <stdint.h>

// Problem constants
#define B_  2
#define T_  2048
#define DM  2048
#define H_  32
#define DH  64
#define M_  (B_*T_)   // 4096

// ---------------------------------------------------------------------------
// Half scratch (device globals: allocation-free per harness rules)
// ---------------------------------------------------------------------------
__device__ __half g_ah[(size_t)M_*DM];                           // hidden hi
__device__ __half g_wqh[(size_t)DM*DM], g_wql[(size_t)DM*DM];    // split Wq
__device__ __half g_woh[(size_t)DM*DM], g_wol[(size_t)DM*DM];    // split Wo
__device__ __half g_qh[(size_t)B_*H_*T_*DH], g_ql[(size_t)B_*H_*T_*DH];   // rope'd+scaled Q
__device__ __half g_kh[(size_t)B_*H_*T_*DH];                     // K hi [B,H,T,Dh]
__device__ __half g_vth[(size_t)B_*H_*T_*DH];                    // V^T hi [B,H,Dh,T]
__device__ __half g_oh[(size_t)M_*DM];                           // attention out hi
__device__ float g_cos[T_*(DH/2)];
__device__ float g_sin[T_*(DH/2)];

// ---------------------------------------------------------------------------
// helpers
// ---------------------------------------------------------------------------
__device__ __forceinline__ uint32_t pack_h2(float a, float b) {
    __half2 h = __floats2half2_rn(a, b);
    return *(uint32_t*)&h;
}
__device__ __forceinline__ void split_h2(float x, float y, uint32_t& h, uint32_t& l) {
    __half2 hh = __floats2half2_rn(x, y);
    float2 f = __half22float2(hh);
    __half2 ll = __floats2half2_rn(x - f.x, y - f.y);
    h = *(uint32_t*)&hh;
    l = *(uint32_t*)&ll;
}
__device__ __forceinline__ void mma16816(float* d, const uint32_t* a, const uint32_t* b) {
    asm volatile(
        "mma.sync.aligned.m16n8k16.row.col.f32.f16.f16.f32 "
        "{%0,%1,%2,%3}, {%4,%5,%6,%7}, {%8,%9}, {%0,%1,%2,%3};"
        : "+f"(d[0]), "+f"(d[1]), "+f"(d[2]), "+f"(d[3])
        : "r"(a[0]), "r"(a[1]), "r"(a[2]), "r"(a[3]), "r"(b[0]), "r"(b[1]));
}
__device__ __forceinline__ void ldsm_x4(uint32_t* r, uint32_t addr) {
    asm volatile(
        "ldmatrix.sync.aligned.m8n8.x4.shared.b16 {%0,%1,%2,%3}, [%4];"
        : "=r"(r[0]), "=r"(r[1]), "=r"(r[2]), "=r"(r[3]) : "r"(addr));
}
__device__ __forceinline__ void cp_async16(uint32_t saddr, const void* gptr) {
    asm volatile("cp.async.cg.shared.global [%0], [%1], 16;"
                 :: "r"(saddr), "l"(gptr));
}
#define CP_COMMIT() asm volatile("cp.async.commit_group;" ::: "memory")
#define CP_WAIT0()  asm volatile("cp.async.wait_group 0;" ::: "memory")

// ---------------------------------------------------------------------------
// RoPE table
// ---------------------------------------------------------------------------
__global__ void rope_table_kernel() {
    int idx = blockIdx.x * blockDim.x + threadIdx.x;
    if (idx >= T_ * (DH/2)) return;
    int t = idx >> 5;
    int i = idx & 31;
    double inv = pow(10000.0, -((double)(2 * i)) / 64.0);
    double ang = (double)t * inv;
    g_cos[idx] = (float)cos(ang);
    g_sin[idx] = (float)sin(ang);
}

// ---------------------------------------------------------------------------
// fp32 -> half prep.  WHICH: 0=hidden (hi only), 1=Wq (hi/lo), 2=Wo (hi/lo)
// ---------------------------------------------------------------------------
template<int WHICH>
__global__ void split_f32_kernel(const float* __restrict__ in) {
    size_t i = (size_t)blockIdx.x * 256 + threadIdx.x;
    float2 v = ((const float2*)in)[i];
    if (WHICH == 0) {
        ((uint32_t*)g_ah)[i] = pack_h2(v.x, v.y);
    } else {
        uint32_t h, l;
        split_h2(v.x, v.y, h, l);
        uint32_t* hw = (uint32_t*)(WHICH == 1 ? g_wqh : g_woh);
        uint32_t* lw = (uint32_t*)(WHICH == 1 ? g_wql : g_wol);
        hw[i] = h;
        lw[i] = l;
    }
}

// ---------------------------------------------------------------------------
// K prep: [B,T,H,Dh] fp32 -> [B,H,T,Dh] half (hi only).
// ---------------------------------------------------------------------------
__global__ void prep_k_kernel(const float* __restrict__ Kg) {
    uint32_t w = blockIdx.x * 256 + threadIdx.x;     // < B*H*T*32
    int dh2 = w & 31;
    int tok = (w >> 5) & (T_ - 1);
    int h   = (w >> 16) & (H_ - 1);
    int b   = (int)(w >> 21);
    float2 v = ((const float2*)Kg)[(((size_t)(b * T_ + tok)) * H_ + h) * 32 + dh2];
    ((uint32_t*)g_kh)[w] = pack_h2(v.x, v.y);
}

// ---------------------------------------------------------------------------
// V prep: [B,T,H,Dh] fp32 -> transposed [B,H,Dh,T] half (hi only).
// ---------------------------------------------------------------------------
__global__ void prep_v_kernel(const float* __restrict__ Vg) {
    __shared__ float stg[64 * 65];
    const int tid = threadIdx.x;
    const int kt  = blockIdx.x, h = blockIdx.y, b = blockIdx.z;
    const float* src = Vg + ((size_t)(b * T_ + kt * 64) * H_ + h) * DH;

    #pragma unroll
    for (int i = 0; i < 4; i++) {
        int chunk = i * 256 + tid;            // 64 rows x 16 float4
        int r = chunk >> 4, c4 = chunk & 15;
        float4 v = *(const float4*)(src + (size_t)r * (H_ * DH) + c4 * 4);
        float* d = stg + r * 65 + c4 * 4;
        d[0] = v.x; d[1] = v.y; d[2] = v.z; d[3] = v.w;
    }
    __syncthreads();

    const int kp = tid & 31, dhg = tid >> 5;
    #pragma unroll
    for (int i = 0; i < 8; i++) {
        int dh = dhg * 8 + i;
        float v0 = stg[(2 * kp)     * 65 + dh];
        float v1 = stg[(2 * kp + 1) * 65 + dh];
        size_t idx = ((size_t)(b * H_ + h) * DH + dh) * (T_ / 2) + kt * 32 + kp;
        ((uint32_t*)g_vth)[idx] = pack_h2(v0, v1);
    }
}

// ---------------------------------------------------------------------------
// 2-pass FP16 GEMM with cp.async double buffering: C = A @ W^T.
// A in fp16 hi only; W in hi/lo (Ahi*Whi + Ahi*Wlo).
// CTA 128x128, BK=32, 256 threads, 2 stages x (Ah,Bh,Bl).
// ---------------------------------------------------------------------------
#define GSTW 28
#define GT_W (128*GSTW)                 // 3584 words
#define G_STAGE_W (3*GT_W)              // 10752 words
#define SMEM_G_BYTES (2*G_STAGE_W*4)    // 86016 B

template<int MODE>
__global__ __launch_bounds__(256)
void gemm_h_kernel(float* __restrict__ C) {
    extern __shared__ uint32_t smw[];

    const uint4* Agh = (const uint4*)(MODE == 0 ? g_ah  : g_oh);
    const uint4* Bgh = (const uint4*)(MODE == 0 ? g_wqh : g_woh);
    const uint4* Bgl = (const uint4*)(MODE == 0 ? g_wql : g_wol);

    const int tid   = threadIdx.x;
    const int wid   = tid >> 5;
    const int lane  = tid & 31;
    const int g     = lane >> 2;
    const int t     = lane & 3;
    const int warpR = wid >> 2;
    const int warpC = wid & 3;
    const int rowBase = blockIdx.y * 128;
    const int colBase = blockIdx.x * 128;

    const int q4 = lane >> 3;
    const int rr = lane & 7;
    const int arow = (q4 & 1) * 8 + rr;
    const int aoff = (q4 >> 1) * 4;
    const int brow = (q4 >> 1) * 8 + rr;
    const int boff = (q4 & 1) * 4;

    const uint32_t smemS = (uint32_t)__cvta_generic_to_shared(smw);

    const int lr2 = tid >> 2;   // 0..63
    const int lc2 = tid & 3;    // 0..3

    // cp.async issue of one BK=32 tile into stage st
    auto issue = [&](int st, int kt) {
        uint32_t base = smemS + (uint32_t)st * G_STAGE_W * 4;
        #pragma unroll
        for (int i = 0; i < 2; i++) {
            int r = lr2 + i * 64;
            uint32_t so = (uint32_t)(r * GSTW + lc2 * 4) * 4;
            size_t ai = ((size_t)(rowBase + r)) * 256 + kt * 4 + lc2;
            size_t bi = ((size_t)(colBase + r)) * 256 + kt * 4 + lc2;
            cp_async16(base + so,                 Agh + ai);
            cp_async16(base + GT_W * 4 + so,      Bgh + bi);
            cp_async16(base + 2 * GT_W * 4 + so,  Bgl + bi);
        }
    };

    float acc[4][4][4];
    #pragma unroll
    for (int mt = 0; mt < 4; mt++)
        #pragma unroll
        for (int nt = 0; nt < 4; nt++)
            #pragma unroll
            for (int i = 0; i < 4; i++) acc[mt][nt][i] = 0.f;

    issue(0, 0);
    CP_COMMIT();

    for (int kt = 0; kt < 64; kt++) {
        CP_WAIT0();
        __syncthreads();    // stage kt visible to all; prior reads complete
        if (kt + 1 < 64) { issue((kt + 1) & 1, kt + 1); CP_COMMIT(); }

        const uint32_t AhS = smemS + (uint32_t)(kt & 1) * G_STAGE_W * 4;
        const uint32_t BhS = AhS + GT_W * 4;
        const uint32_t BlS = AhS + 2 * GT_W * 4;

        #pragma unroll
        for (int ks = 0; ks < 2; ks++) {
            uint32_t ah[4][4], bh[2][4], bl4[2][4];
            #pragma unroll
            for (int mt = 0; mt < 4; mt++) {
                uint32_t ao = ((warpR * 64 + mt * 16 + arow) * GSTW + ks * 8 + aoff) * 4;
                ldsm_x4(ah[mt], AhS + ao);
            }
            #pragma unroll
            for (int p = 0; p < 2; p++) {
                uint32_t bo = ((warpC * 32 + p * 16 + brow) * GSTW + ks * 8 + boff) * 4;
                ldsm_x4(bh[p],  BhS + bo);
                ldsm_x4(bl4[p], BlS + bo);
            }
            #pragma unroll
            for (int mt = 0; mt < 4; mt++)
                #pragma unroll
                for (int nt = 0; nt < 4; nt++) {
                    const uint32_t* bhp = &bh[nt >> 1][(nt & 1) * 2];
                    const uint32_t* blp = &bl4[nt >> 1][(nt & 1) * 2];
                    mma16816(acc[mt][nt], ah[mt], bhp);
                    mma16816(acc[mt][nt], ah[mt], blp);
                }
        }
    }

    #pragma unroll
    for (int mt = 0; mt < 4; mt++) {
        #pragma unroll
        for (int nt = 0; nt < 4; nt++) {
            int m0 = rowBase + warpR * 64 + mt * 16 + g;
            int n  = colBase + warpC * 32 + nt * 8 + 2 * t;
            if (MODE == 0) {
                int hh = n >> 6;
                int d  = n & 63;   // even
                #pragma unroll
                for (int half = 0; half < 2; half++) {
                    int m = m0 + half * 8;
                    float x1 = acc[mt][nt][half * 2];
                    float x2 = acc[mt][nt][half * 2 + 1];
                    int bb = m >> 11;
                    int tt = m & (T_ - 1);
                    float c = g_cos[tt * 32 + (d >> 1)];
                    float s = g_sin[tt * 32 + (d >> 1)];
                    float xr1 = (x1 * c - x2 * s) * 0.125f;
                    float xr2 = (x1 * s + x2 * c) * 0.125f;
                    uint32_t hw, lw;
                    split_h2(xr1, xr2, hw, lw);
                    size_t idx = ((size_t)(bb * H_ + hh) * T_ + tt) * 32 + (d >> 1);
                    ((uint32_t*)g_qh)[idx] = hw;
                    ((uint32_t*)g_ql)[idx] = lw;
                }
            } else {
                float2 v0 = make_float2(acc[mt][nt][0], acc[mt][nt][1]);
                float2 v1 = make_float2(acc[mt][nt][2], acc[mt][nt][3]);
                *(float2*)(C + (size_t)m0 * DM + n)       = v0;
                *(float2*)(C + (size_t)(m0 + 8) * DM + n) = v1;
            }
        }
    }
}

// ---------------------------------------------------------------------------
// FP16 flash attention with ldmatrix: 2-pass S, 1-pass PV (unchanged core).
// ---------------------------------------------------------------------------
#define ASTW 44
#define AT_W (64*ASTW)                  // 2816 words / buffer
#define SMEM_A_BYTES (2*AT_W*4)         // 22528 B

__global__ __launch_bounds__(256)
void attn_mma_kernel() {
    extern __shared__ uint32_t smw[];
    uint32_t* Khw = smw;
    uint32_t* Vhw = smw + AT_W;

    const int tid  = threadIdx.x;
    const int wid  = tid >> 5;
    const int lane = tid & 31;
    const int g    = lane >> 2;
    const int t    = lane & 3;
    const int bx   = (int)gridDim.x - 1 - (int)blockIdx.x;   // heavy blocks first
    const int h    = blockIdx.y;
    const int b    = blockIdx.z;
    const int q0   = bx * 128;
    const int wbase = wid * 16;

    const int q4 = lane >> 3;
    const int rr = lane & 7;

    const uint32_t KhS = (uint32_t)__cvta_generic_to_shared(Khw);
    const uint32_t VhS = (uint32_t)__cvta_generic_to_shared(Vhw);

    // ---- Q A-frags direct from gmem ----
    uint32_t qh[4][4], ql[4][4];
    {
        const uint32_t* qhw = (const uint32_t*)g_qh
            + (((size_t)(b * H_ + h)) * T_ + q0 + wbase + g) * 32;
        const uint32_t* qlw = (const uint32_t*)g_ql
            + (((size_t)(b * H_ + h)) * T_ + q0 + wbase + g) * 32;
        #pragma unroll
        for (int s = 0; s < 4; s++) {
            int o = s * 8 + t;
            qh[s][0] = qhw[o];           qh[s][1] = qhw[8 * 32 + o];
            qh[s][2] = qhw[o + 4];       qh[s][3] = qhw[8 * 32 + o + 4];
            ql[s][0] = qlw[o];           ql[s][1] = qlw[8 * 32 + o];
            ql[s][2] = qlw[o + 4];       ql[s][3] = qlw[8 * 32 + o + 4];
        }
    }

    float m0 = -1e30f, m1 = -1e30f, l0 = 0.f, l1 = 0.f;
    float oacc[8][4];
    #pragma unroll
    for (int nt = 0; nt < 8; nt++)
        #pragma unroll
        for (int i = 0; i < 4; i++) oacc[nt][i] = 0.f;

    const int nkt = 2 * bx + 2;

    const uint4* kh4 = (const uint4*)g_kh  + ((size_t)(b * H_ + h) * T_) * 8;
    const uint4* vh4 = (const uint4*)g_vth + ((size_t)(b * H_ + h) * DH) * (T_ / 8);

    const int ldr = tid >> 3;   // 0..31 (row, +32)
    const int ldc = tid & 7;

    uint4 pkh[2], pvh[2];
    #pragma unroll
    for (int i = 0; i < 2; i++) {
        int r = ldr + i * 32;
        pkh[i] = kh4[(size_t)r * 8 + ldc];
        pvh[i] = vh4[(size_t)r * 256 + ldc];
    }

    const int qw_min = q0 + wbase;
    const int qw_max = q0 + wbase + 15;

    for (int kt = 0; kt < nkt; kt++) {
        const int ktb = kt * 64;

        __syncthreads();
        #pragma unroll
        for (int i = 0; i < 2; i++) {
            int wo = (ldr + i * 32) * ASTW + ldc * 4;
            *(uint4*)(Khw + wo) = pkh[i];
            *(uint4*)(Vhw + wo) = pvh[i];
        }
        __syncthreads();

        if (kt + 1 < nkt) {
            int kb = ktb + 64;
            #pragma unroll
            for (int i = 0; i < 2; i++) {
                int r = ldr + i * 32;
                pkh[i] = kh4[(size_t)(kb + r) * 8 + ldc];
                pvh[i] = vh4[(size_t)r * 256 + (kb >> 3) + ldc];
            }
        }

        if (ktb > qw_max) continue;   // fully masked for this warp

        // ---- S = Q K^T (2-pass: qh*kh + ql*kh) ----
        float sacc[8][4];
        #pragma unroll
        for (int nt = 0; nt < 8; nt++)
            #pragma unroll
            for (int i = 0; i < 4; i++) sacc[nt][i] = 0.f;

        #pragma unroll
        for (int nt = 0; nt < 8; nt++) {
            #pragma unroll
            for (int sp = 0; sp < 2; sp++) {
                uint32_t kb2[4];
                ldsm_x4(kb2, KhS + (((nt * 8 + rr) * ASTW) + sp * 16 + q4 * 4) * 4);
                mma16816(sacc[nt], qh[2 * sp],     &kb2[0]);
                mma16816(sacc[nt], ql[2 * sp],     &kb2[0]);
                mma16816(sacc[nt], qh[2 * sp + 1], &kb2[2]);
                mma16816(sacc[nt], ql[2 * sp + 1], &kb2[2]);
            }
        }

        // ---- causal mask (diagonal tiles only) ----
        if (ktb + 63 > qw_min) {
            int qr0 = qw_min + g, qr1 = qr0 + 8;
            #pragma unroll
            for (int nt = 0; nt < 8; nt++) {
                int kc0 = ktb + nt * 8 + 2 * t;
                if (kc0     > qr0) sacc[nt][0] = -1e30f;
                if (kc0 + 1 > qr0) sacc[nt][1] = -1e30f;
                if (kc0     > qr1) sacc[nt][2] = -1e30f;
                if (kc0 + 1 > qr1) sacc[nt][3] = -1e30f;
            }
        }

        // ---- online softmax ----
        float mx0 = -1e30f, mx1 = -1e30f;
        #pragma unroll
        for (int nt = 0; nt < 8; nt++) {
            mx0 = fmaxf(mx0, fmaxf(sacc[nt][0], sacc[nt][1]));
            mx1 = fmaxf(mx1, fmaxf(sacc[nt][2], sacc[nt][3]));
        }
        mx0 = fmaxf(mx0, __shfl_xor_sync(0xffffffffu, mx0, 1));
        mx0 = fmaxf(mx0, __shfl_xor_sync(0xffffffffu, mx0, 2));
        mx1 = fmaxf(mx1, __shfl_xor_sync(0xffffffffu, mx1, 1));
        mx1 = fmaxf(mx1, __shfl_xor_sync(0xffffffffu, mx1, 2));

        float mn0 = fmaxf(m0, mx0), mn1 = fmaxf(m1, mx1);
        float c0 = __expf(m0 - mn0), c1 = __expf(m1 - mn1);
        m0 = mn0; m1 = mn1;

        float s0 = 0.f, s1 = 0.f;
        #pragma unroll
        for (int nt = 0; nt < 8; nt++) {
            sacc[nt][0] = __expf(sacc[nt][0] - mn0);
            sacc[nt][1] = __expf(sacc[nt][1] - mn0);
            sacc[nt][2] = __expf(sacc[nt][2] - mn1);
            sacc[nt][3] = __expf(sacc[nt][3] - mn1);
            s0 += sacc[nt][0] + sacc[nt][1];
            s1 += sacc[nt][2] + sacc[nt][3];
        }
        s0 += __shfl_xor_sync(0xffffffffu, s0, 1);
        s0 += __shfl_xor_sync(0xffffffffu, s0, 2);
        s1 += __shfl_xor_sync(0xffffffffu, s1, 1);
        s1 += __shfl_xor_sync(0xffffffffu, s1, 2);
        l0 = l0 * c0 + s0;
        l1 = l1 * c1 + s1;

        #pragma unroll
        for (int nt = 0; nt < 8; nt++) {
            oacc[nt][0] *= c0; oacc[nt][1] *= c0;
            oacc[nt][2] *= c1; oacc[nt][3] *= c1;
        }

        // ---- O += P V ----
        uint32_t pa[4][4];
        #pragma unroll
        for (int s = 0; s < 4; s++) {
            pa[s][0] = pack_h2(sacc[2*s][0],     sacc[2*s][1]);
            pa[s][1] = pack_h2(sacc[2*s][2],     sacc[2*s][3]);
            pa[s][2] = pack_h2(sacc[2*s + 1][0], sacc[2*s + 1][1]);
            pa[s][3] = pack_h2(sacc[2*s + 1][2], sacc[2*s + 1][3]);
        }
        #pragma unroll
        for (int nt2 = 0; nt2 < 8; nt2++) {
            #pragma unroll
            for (int sp = 0; sp < 2; sp++) {
                uint32_t vb[4];
                ldsm_x4(vb, VhS + (((nt2 * 8 + rr) * ASTW) + sp * 16 + q4 * 4) * 4);
                mma16816(oacc[nt2], pa[2 * sp],     &vb[0]);
                mma16816(oacc[nt2], pa[2 * sp + 1], &vb[2]);
            }
        }
    }

    // ---- finalize: write O as half hi only (feeds 2-pass O-proj GEMM) ----
    float il0 = 1.0f / l0, il1 = 1.0f / l1;
    size_t row0 = (size_t)(b * T_ + q0 + wbase + g);
    uint32_t* ohw = (uint32_t*)g_oh;
    const int colw0 = (h * DH) >> 1;
    #pragma unroll
    for (int nt2 = 0; nt2 < 8; nt2++) {
        int w = colw0 + nt2 * 4 + t;
        ohw[row0 * 1024 + w]       = pack_h2(oacc[nt2][0] * il0, oacc[nt2][1] * il0);
        ohw[(row0 + 8) * 1024 + w] = pack_h2(oacc[nt2][2] * il1, oacc[nt2][3] * il1);
    }
}

// ---------------------------------------------------------------------------
// Launch: hidden_states, shared_k, shared_v, Wq, Wo -> out (float32 [B,T,Dm])
// ---------------------------------------------------------------------------
extern "C" void kernel_launch(void* const* d_in, const int* in_sizes, int n_in,
                              void* d_out, int out_size) {
    const float* hidden = (const float*)d_in[0];
    const float* Kin    = (const float*)d_in[1];
    const float* Vin    = (const float*)d_in[2];
    const float* Wq     = (const float*)d_in[3];
    const float* Wo     = (const float*)d_in[4];
    float* out          = (float*)d_out;

    cudaFuncSetAttribute(gemm_h_kernel<0>,
                         cudaFuncAttributeMaxDynamicSharedMemorySize, SMEM_G_BYTES);
    cudaFuncSetAttribute(gemm_h_kernel<1>,
                         cudaFuncAttributeMaxDynamicSharedMemorySize, SMEM_G_BYTES);
    cudaFuncSetAttribute(attn_mma_kernel,
                         cudaFuncAttributeMaxDynamicSharedMemorySize, SMEM_A_BYTES);

    rope_table_kernel<<<(T_ * (DH/2) + 255) / 256, 256>>>();
    split_f32_kernel<0><<<M_ * DM / 512, 256>>>(hidden);
    split_f32_kernel<1><<<DM * DM / 512, 256>>>(Wq);
    split_f32_kernel<2><<<DM * DM / 512, 256>>>(Wo);
    prep_k_kernel<<<B_ * H_ * T_ * 32 / 256, 256>>>(Kin);
    prep_v_kernel<<<dim3(T_ / 64, H_, B_), 256>>>(Vin);

    dim3 gGemm(DM / 128, M_ / 128);   // (16, 32)
    gemm_h_kernel<0><<<gGemm, 256, SMEM_G_BYTES>>>(nullptr);

    dim3 gAttn(T_ / 128, H_, B_);     // (16, 32, 2)
    attn_mma_kernel<<<gAttn, 256, SMEM_A_BYTES>>>();

    gemm_h_kernel<1><<<gGemm, 256, SMEM_G_BYTES>>>(out);
}

// round 12
// speedup vs baseline: 6.5158x; 1.3495x over previous
#include <cuda_runtime.h>
#include <cuda_fp16.h>
#include <math.h>
#include <stdint.h>

// Problem constants
#define B_  2
#define T_  2048
#define DM  2048
#define H_  32
#define DH  64
#define M_  (B_*T_)   // 4096

// ---------------------------------------------------------------------------
// Half scratch (device globals: allocation-free per harness rules)
// ---------------------------------------------------------------------------
__device__ __half g_ah[(size_t)M_*DM];                           // hidden hi
__device__ __half g_wqh[(size_t)DM*DM];                          // Wq hi
__device__ __half g_woh[(size_t)DM*DM];                          // Wo hi
__device__ __half g_qh[(size_t)B_*H_*T_*DH], g_ql[(size_t)B_*H_*T_*DH];   // rope'd+scaled Q
__device__ __half g_kh[(size_t)B_*H_*T_*DH];                     // K hi [B,H,T,Dh]
__device__ __half g_vth[(size_t)B_*H_*T_*DH];                    // V^T hi [B,H,Dh,T]
__device__ __half g_oh[(size_t)M_*DM];                           // attention out hi
__device__ float g_cos[T_*(DH/2)];
__device__ float g_sin[T_*(DH/2)];

// ---------------------------------------------------------------------------
// helpers
// ---------------------------------------------------------------------------
__device__ __forceinline__ uint32_t pack_h2(float a, float b) {
    __half2 h = __floats2half2_rn(a, b);
    return *(uint32_t*)&h;
}
__device__ __forceinline__ void split_h2(float x, float y, uint32_t& h, uint32_t& l) {
    __half2 hh = __floats2half2_rn(x, y);
    float2 f = __half22float2(hh);
    __half2 ll = __floats2half2_rn(x - f.x, y - f.y);
    h = *(uint32_t*)&hh;
    l = *(uint32_t*)&ll;
}
__device__ __forceinline__ void mma16816(float* d, const uint32_t* a, const uint32_t* b) {
    asm volatile(
        "mma.sync.aligned.m16n8k16.row.col.f32.f16.f16.f32 "
        "{%0,%1,%2,%3}, {%4,%5,%6,%7}, {%8,%9}, {%0,%1,%2,%3};"
        : "+f"(d[0]), "+f"(d[1]), "+f"(d[2]), "+f"(d[3])
        : "r"(a[0]), "r"(a[1]), "r"(a[2]), "r"(a[3]), "r"(b[0]), "r"(b[1]));
}
__device__ __forceinline__ void ldsm_x4(uint32_t* r, uint32_t addr) {
    asm volatile(
        "ldmatrix.sync.aligned.m8n8.x4.shared.b16 {%0,%1,%2,%3}, [%4];"
        : "=r"(r[0]), "=r"(r[1]), "=r"(r[2]), "=r"(r[3]) : "r"(addr));
}
__device__ __forceinline__ void cp_async16(uint32_t saddr, const void* gptr) {
    asm volatile("cp.async.cg.shared.global [%0], [%1], 16;"
                 :: "r"(saddr), "l"(gptr));
}
#define CP_COMMIT() asm volatile("cp.async.commit_group;" ::: "memory")
#define CP_WAIT0()  asm volatile("cp.async.wait_group 0;" ::: "memory")

// ---------------------------------------------------------------------------
// RoPE table
// ---------------------------------------------------------------------------
__global__ void rope_table_kernel() {
    int idx = blockIdx.x * blockDim.x + threadIdx.x;
    if (idx >= T_ * (DH/2)) return;
    int t = idx >> 5;
    int i = idx & 31;
    double inv = pow(10000.0, -((double)(2 * i)) / 64.0);
    double ang = (double)t * inv;
    g_cos[idx] = (float)cos(ang);
    g_sin[idx] = (float)sin(ang);
}

// ---------------------------------------------------------------------------
// fp32 -> half hi prep.  WHICH: 0=hidden, 1=Wq, 2=Wo
// ---------------------------------------------------------------------------
template<int WHICH>
__global__ void split_f32_kernel(const float* __restrict__ in) {
    size_t i = (size_t)blockIdx.x * 256 + threadIdx.x;
    float2 v = ((const float2*)in)[i];
    uint32_t* hw = (uint32_t*)(WHICH == 0 ? g_ah : WHICH == 1 ? g_wqh : g_woh);
    hw[i] = pack_h2(v.x, v.y);
}

// ---------------------------------------------------------------------------
// K prep: [B,T,H,Dh] fp32 -> [B,H,T,Dh] half (hi only).
// ---------------------------------------------------------------------------
__global__ void prep_k_kernel(const float* __restrict__ Kg) {
    uint32_t w = blockIdx.x * 256 + threadIdx.x;     // < B*H*T*32
    int dh2 = w & 31;
    int tok = (w >> 5) & (T_ - 1);
    int h   = (w >> 16) & (H_ - 1);
    int b   = (int)(w >> 21);
    float2 v = ((const float2*)Kg)[(((size_t)(b * T_ + tok)) * H_ + h) * 32 + dh2];
    ((uint32_t*)g_kh)[w] = pack_h2(v.x, v.y);
}

// ---------------------------------------------------------------------------
// V prep: [B,T,H,Dh] fp32 -> transposed [B,H,Dh,T] half (hi only).
// ---------------------------------------------------------------------------
__global__ void prep_v_kernel(const float* __restrict__ Vg) {
    __shared__ float stg[64 * 65];
    const int tid = threadIdx.x;
    const int kt  = blockIdx.x, h = blockIdx.y, b = blockIdx.z;
    const float* src = Vg + ((size_t)(b * T_ + kt * 64) * H_ + h) * DH;

    #pragma unroll
    for (int i = 0; i < 4; i++) {
        int chunk = i * 256 + tid;            // 64 rows x 16 float4
        int r = chunk >> 4, c4 = chunk & 15;
        float4 v = *(const float4*)(src + (size_t)r * (H_ * DH) + c4 * 4);
        float* d = stg + r * 65 + c4 * 4;
        d[0] = v.x; d[1] = v.y; d[2] = v.z; d[3] = v.w;
    }
    __syncthreads();

    const int kp = tid & 31, dhg = tid >> 5;
    #pragma unroll
    for (int i = 0; i < 8; i++) {
        int dh = dhg * 8 + i;
        float v0 = stg[(2 * kp)     * 65 + dh];
        float v1 = stg[(2 * kp + 1) * 65 + dh];
        size_t idx = ((size_t)(b * H_ + h) * DH + dh) * (T_ / 2) + kt * 32 + kp;
        ((uint32_t*)g_vth)[idx] = pack_h2(v0, v1);
    }
}

// ---------------------------------------------------------------------------
// Pure-FP16 GEMM with cp.async double buffering: C = A @ W^T (hi x hi).
// CTA 128x128, BK=32, 256 threads, 2 stages x (Ah,Bh).
// ---------------------------------------------------------------------------
#define GSTW 28
#define GT_W (128*GSTW)                 // 3584 words
#define G_STAGE_W (2*GT_W)              // 7168 words
#define SMEM_G_BYTES (2*G_STAGE_W*4)    // 57344 B

template<int MODE>
__global__ __launch_bounds__(256)
void gemm_h_kernel(float* __restrict__ C) {
    extern __shared__ uint32_t smw[];

    const uint4* Agh = (const uint4*)(MODE == 0 ? g_ah  : g_oh);
    const uint4* Bgh = (const uint4*)(MODE == 0 ? g_wqh : g_woh);

    const int tid   = threadIdx.x;
    const int wid   = tid >> 5;
    const int lane  = tid & 31;
    const int g     = lane >> 2;
    const int t     = lane & 3;
    const int warpR = wid >> 2;
    const int warpC = wid & 3;
    const int rowBase = blockIdx.y * 128;
    const int colBase = blockIdx.x * 128;

    const int q4 = lane >> 3;
    const int rr = lane & 7;
    const int arow = (q4 & 1) * 8 + rr;
    const int aoff = (q4 >> 1) * 4;
    const int brow = (q4 >> 1) * 8 + rr;
    const int boff = (q4 & 1) * 4;

    const uint32_t smemS = (uint32_t)__cvta_generic_to_shared(smw);

    const int lr2 = tid >> 2;   // 0..63
    const int lc2 = tid & 3;    // 0..3

    auto issue = [&](int st, int kt) {
        uint32_t base = smemS + (uint32_t)st * G_STAGE_W * 4;
        #pragma unroll
        for (int i = 0; i < 2; i++) {
            int r = lr2 + i * 64;
            uint32_t so = (uint32_t)(r * GSTW + lc2 * 4) * 4;
            size_t ai = ((size_t)(rowBase + r)) * 256 + kt * 4 + lc2;
            size_t bi = ((size_t)(colBase + r)) * 256 + kt * 4 + lc2;
            cp_async16(base + so,            Agh + ai);
            cp_async16(base + GT_W * 4 + so, Bgh + bi);
        }
    };

    float acc[4][4][4];
    #pragma unroll
    for (int mt = 0; mt < 4; mt++)
        #pragma unroll
        for (int nt = 0; nt < 4; nt++)
            #pragma unroll
            for (int i = 0; i < 4; i++) acc[mt][nt][i] = 0.f;

    issue(0, 0);
    CP_COMMIT();

    for (int kt = 0; kt < 64; kt++) {
        CP_WAIT0();
        __syncthreads();
        if (kt + 1 < 64) { issue((kt + 1) & 1, kt + 1); CP_COMMIT(); }

        const uint32_t AhS = smemS + (uint32_t)(kt & 1) * G_STAGE_W * 4;
        const uint32_t BhS = AhS + GT_W * 4;

        #pragma unroll
        for (int ks = 0; ks < 2; ks++) {
            uint32_t ah[4][4], bh[2][4];
            #pragma unroll
            for (int mt = 0; mt < 4; mt++) {
                uint32_t ao = ((warpR * 64 + mt * 16 + arow) * GSTW + ks * 8 + aoff) * 4;
                ldsm_x4(ah[mt], AhS + ao);
            }
            #pragma unroll
            for (int p = 0; p < 2; p++) {
                uint32_t bo = ((warpC * 32 + p * 16 + brow) * GSTW + ks * 8 + boff) * 4;
                ldsm_x4(bh[p], BhS + bo);
            }
            #pragma unroll
            for (int mt = 0; mt < 4; mt++)
                #pragma unroll
                for (int nt = 0; nt < 4; nt++)
                    mma16816(acc[mt][nt], ah[mt], &bh[nt >> 1][(nt & 1) * 2]);
        }
    }

    #pragma unroll
    for (int mt = 0; mt < 4; mt++) {
        #pragma unroll
        for (int nt = 0; nt < 4; nt++) {
            int m0 = rowBase + warpR * 64 + mt * 16 + g;
            int n  = colBase + warpC * 32 + nt * 8 + 2 * t;
            if (MODE == 0) {
                int hh = n >> 6;
                int d  = n & 63;   // even
                #pragma unroll
                for (int half = 0; half < 2; half++) {
                    int m = m0 + half * 8;
                    float x1 = acc[mt][nt][half * 2];
                    float x2 = acc[mt][nt][half * 2 + 1];
                    int bb = m >> 11;
                    int tt = m & (T_ - 1);
                    float c = g_cos[tt * 32 + (d >> 1)];
                    float s = g_sin[tt * 32 + (d >> 1)];
                    float xr1 = (x1 * c - x2 * s) * 0.125f;
                    float xr2 = (x1 * s + x2 * c) * 0.125f;
                    uint32_t hw, lw;
                    split_h2(xr1, xr2, hw, lw);
                    size_t idx = ((size_t)(bb * H_ + hh) * T_ + tt) * 32 + (d >> 1);
                    ((uint32_t*)g_qh)[idx] = hw;
                    ((uint32_t*)g_ql)[idx] = lw;
                }
            } else {
                float2 v0 = make_float2(acc[mt][nt][0], acc[mt][nt][1]);
                float2 v1 = make_float2(acc[mt][nt][2], acc[mt][nt][3]);
                *(float2*)(C + (size_t)m0 * DM + n)       = v0;
                *(float2*)(C + (size_t)(m0 + 8) * DM + n) = v1;
            }
        }
    }
}

// ---------------------------------------------------------------------------
// FP16 flash attention with ldmatrix: 2-pass S, 1-pass PV (unchanged).
// ---------------------------------------------------------------------------
#define ASTW 44
#define AT_W (64*ASTW)                  // 2816 words / buffer
#define SMEM_A_BYTES (2*AT_W*4)         // 22528 B

__global__ __launch_bounds__(256)
void attn_mma_kernel() {
    extern __shared__ uint32_t smw[];
    uint32_t* Khw = smw;
    uint32_t* Vhw = smw + AT_W;

    const int tid  = threadIdx.x;
    const int wid  = tid >> 5;
    const int lane = tid & 31;
    const int g    = lane >> 2;
    const int t    = lane & 3;
    const int bx   = (int)gridDim.x - 1 - (int)blockIdx.x;   // heavy blocks first
    const int h    = blockIdx.y;
    const int b    = blockIdx.z;
    const int q0   = bx * 128;
    const int wbase = wid * 16;

    const int q4 = lane >> 3;
    const int rr = lane & 7;

    const uint32_t KhS = (uint32_t)__cvta_generic_to_shared(Khw);
    const uint32_t VhS = (uint32_t)__cvta_generic_to_shared(Vhw);

    // ---- Q A-frags direct from gmem ----
    uint32_t qh[4][4], ql[4][4];
    {
        const uint32_t* qhw = (const uint32_t*)g_qh
            + (((size_t)(b * H_ + h)) * T_ + q0 + wbase + g) * 32;
        const uint32_t* qlw = (const uint32_t*)g_ql
            + (((size_t)(b * H_ + h)) * T_ + q0 + wbase + g) * 32;
        #pragma unroll
        for (int s = 0; s < 4; s++) {
            int o = s * 8 + t;
            qh[s][0] = qhw[o];           qh[s][1] = qhw[8 * 32 + o];
            qh[s][2] = qhw[o + 4];       qh[s][3] = qhw[8 * 32 + o + 4];
            ql[s][0] = qlw[o];           ql[s][1] = qlw[8 * 32 + o];
            ql[s][2] = qlw[o + 4];       ql[s][3] = qlw[8 * 32 + o + 4];
        }
    }

    float m0 = -1e30f, m1 = -1e30f, l0 = 0.f, l1 = 0.f;
    float oacc[8][4];
    #pragma unroll
    for (int nt = 0; nt < 8; nt++)
        #pragma unroll
        for (int i = 0; i < 4; i++) oacc[nt][i] = 0.f;

    const int nkt = 2 * bx + 2;

    const uint4* kh4 = (const uint4*)g_kh  + ((size_t)(b * H_ + h) * T_) * 8;
    const uint4* vh4 = (const uint4*)g_vth + ((size_t)(b * H_ + h) * DH) * (T_ / 8);

    const int ldr = tid >> 3;   // 0..31 (row, +32)
    const int ldc = tid & 7;

    uint4 pkh[2], pvh[2];
    #pragma unroll
    for (int i = 0; i < 2; i++) {
        int r = ldr + i * 32;
        pkh[i] = kh4[(size_t)r * 8 + ldc];
        pvh[i] = vh4[(size_t)r * 256 + ldc];
    }

    const int qw_min = q0 + wbase;
    const int qw_max = q0 + wbase + 15;

    for (int kt = 0; kt < nkt; kt++) {
        const int ktb = kt * 64;

        __syncthreads();
        #pragma unroll
        for (int i = 0; i < 2; i++) {
            int wo = (ldr + i * 32) * ASTW + ldc * 4;
            *(uint4*)(Khw + wo) = pkh[i];
            *(uint4*)(Vhw + wo) = pvh[i];
        }
        __syncthreads();

        if (kt + 1 < nkt) {
            int kb = ktb + 64;
            #pragma unroll
            for (int i = 0; i < 2; i++) {
                int r = ldr + i * 32;
                pkh[i] = kh4[(size_t)(kb + r) * 8 + ldc];
                pvh[i] = vh4[(size_t)r * 256 + (kb >> 3) + ldc];
            }
        }

        if (ktb > qw_max) continue;   // fully masked for this warp

        // ---- S = Q K^T (2-pass: qh*kh + ql*kh) ----
        float sacc[8][4];
        #pragma unroll
        for (int nt = 0; nt < 8; nt++)
            #pragma unroll
            for (int i = 0; i < 4; i++) sacc[nt][i] = 0.f;

        #pragma unroll
        for (int nt = 0; nt < 8; nt++) {
            #pragma unroll
            for (int sp = 0; sp < 2; sp++) {
                uint32_t kb2[4];
                ldsm_x4(kb2, KhS + (((nt * 8 + rr) * ASTW) + sp * 16 + q4 * 4) * 4);
                mma16816(sacc[nt], qh[2 * sp],     &kb2[0]);
                mma16816(sacc[nt], ql[2 * sp],     &kb2[0]);
                mma16816(sacc[nt], qh[2 * sp + 1], &kb2[2]);
                mma16816(sacc[nt], ql[2 * sp + 1], &kb2[2]);
            }
        }

        // ---- causal mask (diagonal tiles only) ----
        if (ktb + 63 > qw_min) {
            int qr0 = qw_min + g, qr1 = qr0 + 8;
            #pragma unroll
            for (int nt = 0; nt < 8; nt++) {
                int kc0 = ktb + nt * 8 + 2 * t;
                if (kc0     > qr0) sacc[nt][0] = -1e30f;
                if (kc0 + 1 > qr0) sacc[nt][1] = -1e30f;
                if (kc0     > qr1) sacc[nt][2] = -1e30f;
                if (kc0 + 1 > qr1) sacc[nt][3] = -1e30f;
            }
        }

        // ---- online softmax ----
        float mx0 = -1e30f, mx1 = -1e30f;
        #pragma unroll
        for (int nt = 0; nt < 8; nt++) {
            mx0 = fmaxf(mx0, fmaxf(sacc[nt][0], sacc[nt][1]));
            mx1 = fmaxf(mx1, fmaxf(sacc[nt][2], sacc[nt][3]));
        }
        mx0 = fmaxf(mx0, __shfl_xor_sync(0xffffffffu, mx0, 1));
        mx0 = fmaxf(mx0, __shfl_xor_sync(0xffffffffu, mx0, 2));
        mx1 = fmaxf(mx1, __shfl_xor_sync(0xffffffffu, mx1, 1));
        mx1 = fmaxf(mx1, __shfl_xor_sync(0xffffffffu, mx1, 2));

        float mn0 = fmaxf(m0, mx0), mn1 = fmaxf(m1, mx1);
        float c0 = __expf(m0 - mn0), c1 = __expf(m1 - mn1);
        m0 = mn0; m1 = mn1;

        float s0 = 0.f, s1 = 0.f;
        #pragma unroll
        for (int nt = 0; nt < 8; nt++) {
            sacc[nt][0] = __expf(sacc[nt][0] - mn0);
            sacc[nt][1] = __expf(sacc[nt][1] - mn0);
            sacc[nt][2] = __expf(sacc[nt][2] - mn1);
            sacc[nt][3] = __expf(sacc[nt][3] - mn1);
            s0 += sacc[nt][0] + sacc[nt][1];
            s1 += sacc[nt][2] + sacc[nt][3];
        }
        s0 += __shfl_xor_sync(0xffffffffu, s0, 1);
        s0 += __shfl_xor_sync(0xffffffffu, s0, 2);
        s1 += __shfl_xor_sync(0xffffffffu, s1, 1);
        s1 += __shfl_xor_sync(0xffffffffu, s1, 2);
        l0 = l0 * c0 + s0;
        l1 = l1 * c1 + s1;

        #pragma unroll
        for (int nt = 0; nt < 8; nt++) {
            oacc[nt][0] *= c0; oacc[nt][1] *= c0;
            oacc[nt][2] *= c1; oacc[nt][3] *= c1;
        }

        // ---- O += P V ----
        uint32_t pa[4][4];
        #pragma unroll
        for (int s = 0; s < 4; s++) {
            pa[s][0] = pack_h2(sacc[2*s][0],     sacc[2*s][1]);
            pa[s][1] = pack_h2(sacc[2*s][2],     sacc[2*s][3]);
            pa[s][2] = pack_h2(sacc[2*s + 1][0], sacc[2*s + 1][1]);
            pa[s][3] = pack_h2(sacc[2*s + 1][2], sacc[2*s + 1][3]);
        }
        #pragma unroll
        for (int nt2 = 0; nt2 < 8; nt2++) {
            #pragma unroll
            for (int sp = 0; sp < 2; sp++) {
                uint32_t vb[4];
                ldsm_x4(vb, VhS + (((nt2 * 8 + rr) * ASTW) + sp * 16 + q4 * 4) * 4);
                mma16816(oacc[nt2], pa[2 * sp],     &vb[0]);
                mma16816(oacc[nt2], pa[2 * sp + 1], &vb[2]);
            }
        }
    }

    // ---- finalize: write O as half hi (feeds 1-pass O-proj GEMM) ----
    float il0 = 1.0f / l0, il1 = 1.0f / l1;
    size_t row0 = (size_t)(b * T_ + q0 + wbase + g);
    uint32_t* ohw = (uint32_t*)g_oh;
    const int colw0 = (h * DH) >> 1;
    #pragma unroll
    for (int nt2 = 0; nt2 < 8; nt2++) {
        int w = colw0 + nt2 * 4 + t;
        ohw[row0 * 1024 + w]       = pack_h2(oacc[nt2][0] * il0, oacc[nt2][1] * il0);
        ohw[(row0 + 8) * 1024 + w] = pack_h2(oacc[nt2][2] * il1, oacc[nt2][3] * il1);
    }
}

// ---------------------------------------------------------------------------
// Launch: hidden_states, shared_k, shared_v, Wq, Wo -> out (float32 [B,T,Dm])
// ---------------------------------------------------------------------------
extern "C" void kernel_launch(void* const* d_in, const int* in_sizes, int n_in,
                              void* d_out, int out_size) {
    const float* hidden = (const float*)d_in[0];
    const float* Kin    = (const float*)d_in[1];
    const float* Vin    = (const float*)d_in[2];
    const float* Wq     = (const float*)d_in[3];
    const float* Wo     = (const float*)d_in[4];
    float* out          = (float*)d_out;

    cudaFuncSetAttribute(gemm_h_kernel<0>,
                         cudaFuncAttributeMaxDynamicSharedMemorySize, SMEM_G_BYTES);
    cudaFuncSetAttribute(gemm_h_kernel<1>,
                         cudaFuncAttributeMaxDynamicSharedMemorySize, SMEM_G_BYTES);
    cudaFuncSetAttribute(attn_mma_kernel,
                         cudaFuncAttributeMaxDynamicSharedMemorySize, SMEM_A_BYTES);

    rope_table_kernel<<<(T_ * (DH/2) + 255) / 256, 256>>>();
    split_f32_kernel<0><<<M_ * DM / 512, 256>>>(hidden);
    split_f32_kernel<1><<<DM * DM / 512, 256>>>(Wq);
    split_f32_kernel<2><<<DM * DM / 512, 256>>>(Wo);
    prep_k_kernel<<<B_ * H_ * T_ * 32 / 256, 256>>>(Kin);
    prep_v_kernel<<<dim3(T_ / 64, H_, B_), 256>>>(Vin);

    dim3 gGemm(DM / 128, M_ / 128);   // (16, 32)
    gemm_h_kernel<0><<<gGemm, 256, SMEM_G_BYTES>>>(nullptr);

    dim3 gAttn(T_ / 128, H_, B_);     // (16, 32, 2)
    attn_mma_kernel<<<gAttn, 256, SMEM_A_BYTES>>>();

    gemm_h_kernel<1><<<gGemm, 256, SMEM_G_BYTES>>>(out);
}

// round 13
// speedup vs baseline: 6.9620x; 1.0685x over previous
#include <cuda_runtime.h>
#include <cuda_fp16.h>
#include <math.h>
#include <stdint.h>

// Problem constants
#define B_  2
#define T_  2048
#define DM  2048
#define H_  32
#define DH  64
#define M_  (B_*T_)   // 4096

// ---------------------------------------------------------------------------
// Half scratch (device globals: allocation-free per harness rules)
// ---------------------------------------------------------------------------
__device__ __half g_ah[(size_t)M_*DM];                           // hidden hi
__device__ __half g_wqh[(size_t)DM*DM];                          // Wq hi
__device__ __half g_woh[(size_t)DM*DM];                          // Wo hi
__device__ __half g_qh[(size_t)B_*H_*T_*DH];                     // rope'd+scaled Q hi
__device__ __half g_kh[(size_t)B_*H_*T_*DH];                     // K hi [B,H,T,Dh]
__device__ __half g_vth[(size_t)B_*H_*T_*DH];                    // V^T hi [B,H,Dh,T]
__device__ __half g_oh[(size_t)M_*DM];                           // attention out hi
__device__ float g_cos[T_*(DH/2)];
__device__ float g_sin[T_*(DH/2)];

// ---------------------------------------------------------------------------
// helpers
// ---------------------------------------------------------------------------
__device__ __forceinline__ uint32_t pack_h2(float a, float b) {
    __half2 h = __floats2half2_rn(a, b);
    return *(uint32_t*)&h;
}
__device__ __forceinline__ void mma16816(float* d, const uint32_t* a, const uint32_t* b) {
    asm volatile(
        "mma.sync.aligned.m16n8k16.row.col.f32.f16.f16.f32 "
        "{%0,%1,%2,%3}, {%4,%5,%6,%7}, {%8,%9}, {%0,%1,%2,%3};"
        : "+f"(d[0]), "+f"(d[1]), "+f"(d[2]), "+f"(d[3])
        : "r"(a[0]), "r"(a[1]), "r"(a[2]), "r"(a[3]), "r"(b[0]), "r"(b[1]));
}
__device__ __forceinline__ void ldsm_x4(uint32_t* r, uint32_t addr) {
    asm volatile(
        "ldmatrix.sync.aligned.m8n8.x4.shared.b16 {%0,%1,%2,%3}, [%4];"
        : "=r"(r[0]), "=r"(r[1]), "=r"(r[2]), "=r"(r[3]) : "r"(addr));
}
__device__ __forceinline__ void cp_async16(uint32_t saddr, const void* gptr) {
    asm volatile("cp.async.cg.shared.global [%0], [%1], 16;"
                 :: "r"(saddr), "l"(gptr));
}
#define CP_COMMIT() asm volatile("cp.async.commit_group;" ::: "memory")
#define CP_WAIT0()  asm volatile("cp.async.wait_group 0;" ::: "memory")

// ---------------------------------------------------------------------------
// RoPE table
// ---------------------------------------------------------------------------
__global__ void rope_table_kernel() {
    int idx = blockIdx.x * blockDim.x + threadIdx.x;
    if (idx >= T_ * (DH/2)) return;
    int t = idx >> 5;
    int i = idx & 31;
    double inv = pow(10000.0, -((double)(2 * i)) / 64.0);
    double ang = (double)t * inv;
    g_cos[idx] = (float)cos(ang);
    g_sin[idx] = (float)sin(ang);
}

// ---------------------------------------------------------------------------
// fp32 -> half hi prep.  WHICH: 0=hidden, 1=Wq, 2=Wo
// ---------------------------------------------------------------------------
template<int WHICH>
__global__ void split_f32_kernel(const float* __restrict__ in) {
    size_t i = (size_t)blockIdx.x * 256 + threadIdx.x;
    float2 v = ((const float2*)in)[i];
    uint32_t* hw = (uint32_t*)(WHICH == 0 ? g_ah : WHICH == 1 ? g_wqh : g_woh);
    hw[i] = pack_h2(v.x, v.y);
}

// ---------------------------------------------------------------------------
// K prep: [B,T,H,Dh] fp32 -> [B,H,T,Dh] half (hi only).
// ---------------------------------------------------------------------------
__global__ void prep_k_kernel(const float* __restrict__ Kg) {
    uint32_t w = blockIdx.x * 256 + threadIdx.x;     // < B*H*T*32
    int dh2 = w & 31;
    int tok = (w >> 5) & (T_ - 1);
    int h   = (w >> 16) & (H_ - 1);
    int b   = (int)(w >> 21);
    float2 v = ((const float2*)Kg)[(((size_t)(b * T_ + tok)) * H_ + h) * 32 + dh2];
    ((uint32_t*)g_kh)[w] = pack_h2(v.x, v.y);
}

// ---------------------------------------------------------------------------
// V prep: [B,T,H,Dh] fp32 -> transposed [B,H,Dh,T] half (hi only).
// ---------------------------------------------------------------------------
__global__ void prep_v_kernel(const float* __restrict__ Vg) {
    __shared__ float stg[64 * 65];
    const int tid = threadIdx.x;
    const int kt  = blockIdx.x, h = blockIdx.y, b = blockIdx.z;
    const float* src = Vg + ((size_t)(b * T_ + kt * 64) * H_ + h) * DH;

    #pragma unroll
    for (int i = 0; i < 4; i++) {
        int chunk = i * 256 + tid;            // 64 rows x 16 float4
        int r = chunk >> 4, c4 = chunk & 15;
        float4 v = *(const float4*)(src + (size_t)r * (H_ * DH) + c4 * 4);
        float* d = stg + r * 65 + c4 * 4;
        d[0] = v.x; d[1] = v.y; d[2] = v.z; d[3] = v.w;
    }
    __syncthreads();

    const int kp = tid & 31, dhg = tid >> 5;
    #pragma unroll
    for (int i = 0; i < 8; i++) {
        int dh = dhg * 8 + i;
        float v0 = stg[(2 * kp)     * 65 + dh];
        float v1 = stg[(2 * kp + 1) * 65 + dh];
        size_t idx = ((size_t)(b * H_ + h) * DH + dh) * (T_ / 2) + kt * 32 + kp;
        ((uint32_t*)g_vth)[idx] = pack_h2(v0, v1);
    }
}

// ---------------------------------------------------------------------------
// Pure-FP16 GEMM with cp.async double buffering: C = A @ W^T (hi x hi).
// ---------------------------------------------------------------------------
#define GSTW 28
#define GT_W (128*GSTW)                 // 3584 words
#define G_STAGE_W (2*GT_W)              // 7168 words
#define SMEM_G_BYTES (2*G_STAGE_W*4)    // 57344 B

template<int MODE>
__global__ __launch_bounds__(256)
void gemm_h_kernel(float* __restrict__ C) {
    extern __shared__ uint32_t smw[];

    const uint4* Agh = (const uint4*)(MODE == 0 ? g_ah  : g_oh);
    const uint4* Bgh = (const uint4*)(MODE == 0 ? g_wqh : g_woh);

    const int tid   = threadIdx.x;
    const int wid   = tid >> 5;
    const int lane  = tid & 31;
    const int g     = lane >> 2;
    const int t     = lane & 3;
    const int warpR = wid >> 2;
    const int warpC = wid & 3;
    const int rowBase = blockIdx.y * 128;
    const int colBase = blockIdx.x * 128;

    const int q4 = lane >> 3;
    const int rr = lane & 7;
    const int arow = (q4 & 1) * 8 + rr;
    const int aoff = (q4 >> 1) * 4;
    const int brow = (q4 >> 1) * 8 + rr;
    const int boff = (q4 & 1) * 4;

    const uint32_t smemS = (uint32_t)__cvta_generic_to_shared(smw);

    const int lr2 = tid >> 2;   // 0..63
    const int lc2 = tid & 3;    // 0..3

    auto issue = [&](int st, int kt) {
        uint32_t base = smemS + (uint32_t)st * G_STAGE_W * 4;
        #pragma unroll
        for (int i = 0; i < 2; i++) {
            int r = lr2 + i * 64;
            uint32_t so = (uint32_t)(r * GSTW + lc2 * 4) * 4;
            size_t ai = ((size_t)(rowBase + r)) * 256 + kt * 4 + lc2;
            size_t bi = ((size_t)(colBase + r)) * 256 + kt * 4 + lc2;
            cp_async16(base + so,            Agh + ai);
            cp_async16(base + GT_W * 4 + so, Bgh + bi);
        }
    };

    float acc[4][4][4];
    #pragma unroll
    for (int mt = 0; mt < 4; mt++)
        #pragma unroll
        for (int nt = 0; nt < 4; nt++)
            #pragma unroll
            for (int i = 0; i < 4; i++) acc[mt][nt][i] = 0.f;

    issue(0, 0);
    CP_COMMIT();

    for (int kt = 0; kt < 64; kt++) {
        CP_WAIT0();
        __syncthreads();
        if (kt + 1 < 64) { issue((kt + 1) & 1, kt + 1); CP_COMMIT(); }

        const uint32_t AhS = smemS + (uint32_t)(kt & 1) * G_STAGE_W * 4;
        const uint32_t BhS = AhS + GT_W * 4;

        #pragma unroll
        for (int ks = 0; ks < 2; ks++) {
            uint32_t ah[4][4], bh[2][4];
            #pragma unroll
            for (int mt = 0; mt < 4; mt++) {
                uint32_t ao = ((warpR * 64 + mt * 16 + arow) * GSTW + ks * 8 + aoff) * 4;
                ldsm_x4(ah[mt], AhS + ao);
            }
            #pragma unroll
            for (int p = 0; p < 2; p++) {
                uint32_t bo = ((warpC * 32 + p * 16 + brow) * GSTW + ks * 8 + boff) * 4;
                ldsm_x4(bh[p], BhS + bo);
            }
            #pragma unroll
            for (int mt = 0; mt < 4; mt++)
                #pragma unroll
                for (int nt = 0; nt < 4; nt++)
                    mma16816(acc[mt][nt], ah[mt], &bh[nt >> 1][(nt & 1) * 2]);
        }
    }

    #pragma unroll
    for (int mt = 0; mt < 4; mt++) {
        #pragma unroll
        for (int nt = 0; nt < 4; nt++) {
            int m0 = rowBase + warpR * 64 + mt * 16 + g;
            int n  = colBase + warpC * 32 + nt * 8 + 2 * t;
            if (MODE == 0) {
                int hh = n >> 6;
                int d  = n & 63;   // even
                #pragma unroll
                for (int half = 0; half < 2; half++) {
                    int m = m0 + half * 8;
                    float x1 = acc[mt][nt][half * 2];
                    float x2 = acc[mt][nt][half * 2 + 1];
                    int bb = m >> 11;
                    int tt = m & (T_ - 1);
                    float c = g_cos[tt * 32 + (d >> 1)];
                    float s = g_sin[tt * 32 + (d >> 1)];
                    float xr1 = (x1 * c - x2 * s) * 0.125f;
                    float xr2 = (x1 * s + x2 * c) * 0.125f;
                    size_t idx = ((size_t)(bb * H_ + hh) * T_ + tt) * 32 + (d >> 1);
                    ((uint32_t*)g_qh)[idx] = pack_h2(xr1, xr2);
                }
            } else {
                float2 v0 = make_float2(acc[mt][nt][0], acc[mt][nt][1]);
                float2 v1 = make_float2(acc[mt][nt][2], acc[mt][nt][3]);
                *(float2*)(C + (size_t)m0 * DM + n)       = v0;
                *(float2*)(C + (size_t)(m0 + 8) * DM + n) = v1;
            }
        }
    }
}

// ---------------------------------------------------------------------------
// FP16 flash attention: 1-pass S, 1-pass PV, cp.async 2-stage K/V pipeline.
// Block = (b, h, 128-row Q tile). 256 threads, 8 warps x 16 rows.
// ---------------------------------------------------------------------------
#define ASTW 44
#define AT_W (64*ASTW)                  // 2816 words / buffer
#define A_STAGE_W (2*AT_W)              // K + V per stage
#define SMEM_A_BYTES (2*A_STAGE_W*4)    // 45056 B

__global__ __launch_bounds__(256)
void attn_mma_kernel() {
    extern __shared__ uint32_t smw[];

    const int tid  = threadIdx.x;
    const int wid  = tid >> 5;
    const int lane = tid & 31;
    const int g    = lane >> 2;
    const int t    = lane & 3;
    const int bx   = (int)gridDim.x - 1 - (int)blockIdx.x;   // heavy blocks first
    const int h    = blockIdx.y;
    const int b    = blockIdx.z;
    const int q0   = bx * 128;
    const int wbase = wid * 16;

    const int q4 = lane >> 3;
    const int rr = lane & 7;

    const uint32_t smemS = (uint32_t)__cvta_generic_to_shared(smw);

    // ---- Q A-frags direct from gmem (hi only) ----
    uint32_t qh[4][4];
    {
        const uint32_t* qhw = (const uint32_t*)g_qh
            + (((size_t)(b * H_ + h)) * T_ + q0 + wbase + g) * 32;
        #pragma unroll
        for (int s = 0; s < 4; s++) {
            int o = s * 8 + t;
            qh[s][0] = qhw[o];           qh[s][1] = qhw[8 * 32 + o];
            qh[s][2] = qhw[o + 4];       qh[s][3] = qhw[8 * 32 + o + 4];
        }
    }

    float m0 = -1e30f, m1 = -1e30f, l0 = 0.f, l1 = 0.f;
    float oacc[8][4];
    #pragma unroll
    for (int nt = 0; nt < 8; nt++)
        #pragma unroll
        for (int i = 0; i < 4; i++) oacc[nt][i] = 0.f;

    const int nkt = 2 * bx + 2;

    const uint4* kh4 = (const uint4*)g_kh  + ((size_t)(b * H_ + h) * T_) * 8;
    const uint4* vh4 = (const uint4*)g_vth + ((size_t)(b * H_ + h) * DH) * (T_ / 8);

    const int ldr = tid >> 3;   // 0..31 (row, +32)
    const int ldc = tid & 7;    // uint4 chunk

    // cp.async one 64-key K/V tile pair into stage st
    auto issue = [&](int st, int kt) {
        uint32_t base = smemS + (uint32_t)st * A_STAGE_W * 4;
        #pragma unroll
        for (int i = 0; i < 2; i++) {
            int r = ldr + i * 32;
            uint32_t so = (uint32_t)(r * ASTW + ldc * 4) * 4;
            cp_async16(base + so,            kh4 + (size_t)(kt * 64 + r) * 8 + ldc);
            cp_async16(base + AT_W * 4 + so, vh4 + (size_t)r * 256 + kt * 8 + ldc);
        }
    };

    const int qw_min = q0 + wbase;
    const int qw_max = q0 + wbase + 15;

    issue(0, 0);
    CP_COMMIT();

    for (int kt = 0; kt < nkt; kt++) {
        const int ktb = kt * 64;

        CP_WAIT0();
        __syncthreads();
        if (kt + 1 < nkt) { issue((kt + 1) & 1, kt + 1); CP_COMMIT(); }

        if (ktb > qw_max) continue;   // fully masked for this warp

        const uint32_t KhS = smemS + (uint32_t)(kt & 1) * A_STAGE_W * 4;
        const uint32_t VhS = KhS + AT_W * 4;

        // ---- S = Q K^T (1-pass fp16) ----
        float sacc[8][4];
        #pragma unroll
        for (int nt = 0; nt < 8; nt++)
            #pragma unroll
            for (int i = 0; i < 4; i++) sacc[nt][i] = 0.f;

        #pragma unroll
        for (int nt = 0; nt < 8; nt++) {
            #pragma unroll
            for (int sp = 0; sp < 2; sp++) {
                uint32_t kb2[4];
                ldsm_x4(kb2, KhS + (((nt * 8 + rr) * ASTW) + sp * 16 + q4 * 4) * 4);
                mma16816(sacc[nt], qh[2 * sp],     &kb2[0]);
                mma16816(sacc[nt], qh[2 * sp + 1], &kb2[2]);
            }
        }

        // ---- causal mask (diagonal tiles only) ----
        if (ktb + 63 > qw_min) {
            int qr0 = qw_min + g, qr1 = qr0 + 8;
            #pragma unroll
            for (int nt = 0; nt < 8; nt++) {
                int kc0 = ktb + nt * 8 + 2 * t;
                if (kc0     > qr0) sacc[nt][0] = -1e30f;
                if (kc0 + 1 > qr0) sacc[nt][1] = -1e30f;
                if (kc0     > qr1) sacc[nt][2] = -1e30f;
                if (kc0 + 1 > qr1) sacc[nt][3] = -1e30f;
            }
        }

        // ---- online softmax ----
        float mx0 = -1e30f, mx1 = -1e30f;
        #pragma unroll
        for (int nt = 0; nt < 8; nt++) {
            mx0 = fmaxf(mx0, fmaxf(sacc[nt][0], sacc[nt][1]));
            mx1 = fmaxf(mx1, fmaxf(sacc[nt][2], sacc[nt][3]));
        }
        mx0 = fmaxf(mx0, __shfl_xor_sync(0xffffffffu, mx0, 1));
        mx0 = fmaxf(mx0, __shfl_xor_sync(0xffffffffu, mx0, 2));
        mx1 = fmaxf(mx1, __shfl_xor_sync(0xffffffffu, mx1, 1));
        mx1 = fmaxf(mx1, __shfl_xor_sync(0xffffffffu, mx1, 2));

        float mn0 = fmaxf(m0, mx0), mn1 = fmaxf(m1, mx1);
        float c0 = __expf(m0 - mn0), c1 = __expf(m1 - mn1);
        m0 = mn0; m1 = mn1;

        float s0 = 0.f, s1 = 0.f;
        #pragma unroll
        for (int nt = 0; nt < 8; nt++) {
            sacc[nt][0] = __expf(sacc[nt][0] - mn0);
            sacc[nt][1] = __expf(sacc[nt][1] - mn0);
            sacc[nt][2] = __expf(sacc[nt][2] - mn1);
            sacc[nt][3] = __expf(sacc[nt][3] - mn1);
            s0 += sacc[nt][0] + sacc[nt][1];
            s1 += sacc[nt][2] + sacc[nt][3];
        }
        s0 += __shfl_xor_sync(0xffffffffu, s0, 1);
        s0 += __shfl_xor_sync(0xffffffffu, s0, 2);
        s1 += __shfl_xor_sync(0xffffffffu, s1, 1);
        s1 += __shfl_xor_sync(0xffffffffu, s1, 2);
        l0 = l0 * c0 + s0;
        l1 = l1 * c1 + s1;

        #pragma unroll
        for (int nt = 0; nt < 8; nt++) {
            oacc[nt][0] *= c0; oacc[nt][1] *= c0;
            oacc[nt][2] *= c1; oacc[nt][3] *= c1;
        }

        // ---- O += P V ----
        uint32_t pa[4][4];
        #pragma unroll
        for (int s = 0; s < 4; s++) {
            pa[s][0] = pack_h2(sacc[2*s][0],     sacc[2*s][1]);
            pa[s][1] = pack_h2(sacc[2*s][2],     sacc[2*s][3]);
            pa[s][2] = pack_h2(sacc[2*s + 1][0], sacc[2*s + 1][1]);
            pa[s][3] = pack_h2(sacc[2*s + 1][2], sacc[2*s + 1][3]);
        }
        #pragma unroll
        for (int nt2 = 0; nt2 < 8; nt2++) {
            #pragma unroll
            for (int sp = 0; sp < 2; sp++) {
                uint32_t vb[4];
                ldsm_x4(vb, VhS + (((nt2 * 8 + rr) * ASTW) + sp * 16 + q4 * 4) * 4);
                mma16816(oacc[nt2], pa[2 * sp],     &vb[0]);
                mma16816(oacc[nt2], pa[2 * sp + 1], &vb[2]);
            }
        }
    }

    // ---- finalize: write O as half hi (feeds 1-pass O-proj GEMM) ----
    float il0 = 1.0f / l0, il1 = 1.0f / l1;
    size_t row0 = (size_t)(b * T_ + q0 + wbase + g);
    uint32_t* ohw = (uint32_t*)g_oh;
    const int colw0 = (h * DH) >> 1;
    #pragma unroll
    for (int nt2 = 0; nt2 < 8; nt2++) {
        int w = colw0 + nt2 * 4 + t;
        ohw[row0 * 1024 + w]       = pack_h2(oacc[nt2][0] * il0, oacc[nt2][1] * il0);
        ohw[(row0 + 8) * 1024 + w] = pack_h2(oacc[nt2][2] * il1, oacc[nt2][3] * il1);
    }
}

// ---------------------------------------------------------------------------
// Launch: hidden_states, shared_k, shared_v, Wq, Wo -> out (float32 [B,T,Dm])
// ---------------------------------------------------------------------------
extern "C" void kernel_launch(void* const* d_in, const int* in_sizes, int n_in,
                              void* d_out, int out_size) {
    const float* hidden = (const float*)d_in[0];
    const float* Kin    = (const float*)d_in[1];
    const float* Vin    = (const float*)d_in[2];
    const float* Wq     = (const float*)d_in[3];
    const float* Wo     = (const float*)d_in[4];
    float* out          = (float*)d_out;

    cudaFuncSetAttribute(gemm_h_kernel<0>,
                         cudaFuncAttributeMaxDynamicSharedMemorySize, SMEM_G_BYTES);
    cudaFuncSetAttribute(gemm_h_kernel<1>,
                         cudaFuncAttributeMaxDynamicSharedMemorySize, SMEM_G_BYTES);
    cudaFuncSetAttribute(attn_mma_kernel,
                         cudaFuncAttributeMaxDynamicSharedMemorySize, SMEM_A_BYTES);

    rope_table_kernel<<<(T_ * (DH/2) + 255) / 256, 256>>>();
    split_f32_kernel<0><<<M_ * DM / 512, 256>>>(hidden);
    split_f32_kernel<1><<<DM * DM / 512, 256>>>(Wq);
    split_f32_kernel<2><<<DM * DM / 512, 256>>>(Wo);
    prep_k_kernel<<<B_ * H_ * T_ * 32 / 256, 256>>>(Kin);
    prep_v_kernel<<<dim3(T_ / 64, H_, B_), 256>>>(Vin);

    dim3 gGemm(DM / 128, M_ / 128);   // (16, 32)
    gemm_h_kernel<0><<<gGemm, 256, SMEM_G_BYTES>>>(nullptr);

    dim3 gAttn(T_ / 128, H_, B_);     // (16, 32, 2)
    attn_mma_kernel<<<gAttn, 256, SMEM_A_BYTES>>>();

    gemm_h_kernel<1><<<gGemm, 256, SMEM_G_BYTES>>>(out);
}